// round 1
// baseline (speedup 1.0000x reference)
#include <cuda_runtime.h>
#include <cuda_bf16.h>
#include <math.h>

// ---------------- problem constants ----------------
#define S_TOK   16384          // B*N
#define DMODEL  1024
#define NEXP    8
#define HFFN    4096
#define CAP     2560           // int(S*1.25/E)
#define GATE_BLOCKS (S_TOK/8)  // gating: 8 tokens per 256-thread block

// ---------------- device scratch (allocation-free rule) ----------------
__device__ float g_buf[NEXP * CAP * DMODEL];   // 80 MB  dispatch buffers
__device__ float g_h  [NEXP * CAP * HFFN];     // 320 MB hidden activations
__device__ float g_eo [NEXP * CAP * DMODEL];   // 80 MB  expert outputs
__device__ float g_gate1[S_TOK];
__device__ float g_gate2[S_TOK];
__device__ int   g_idx1[S_TOK];
__device__ int   g_idx2[S_TOK];
__device__ int   g_pos1[S_TOK];
__device__ int   g_pos2[S_TOK];
__device__ float g_partial[GATE_BLOCKS * NEXP]; // per-block gate sums (for me)
__device__ int   g_cnt1[NEXP];                  // top-1 counts (for ce)

// ---------------- helpers ----------------
__device__ __forceinline__ float gelu_tanh(float x) {
    // jax.nn.gelu(approximate=True)
    float x3 = x * x * x;
    return 0.5f * x * (1.0f + tanhf(0.7978845608028654f * (x + 0.044715f * x3)));
}

// ---------------- 1) gating: logits, softmax, top-2, partial gate sums ----
__global__ void __launch_bounds__(256) gating_kernel(
    const float* __restrict__ x, const float* __restrict__ Wg)
{
    // Wg is [D, E] row-major; store transposed [E][D] in smem for
    // conflict-free per-e loads.
    __shared__ float sWgT[NEXP * DMODEL];   // 32 KB
    __shared__ float sP[8][NEXP];           // per-warp token gate probs
    for (int i = threadIdx.x; i < NEXP * DMODEL; i += blockDim.x) {
        int d = i & (DMODEL - 1);
        int e = i >> 10;
        sWgT[i] = Wg[d * NEXP + e];
    }
    __syncthreads();

    int warp = threadIdx.x >> 5;
    int lane = threadIdx.x & 31;
    int tok  = blockIdx.x * 8 + warp;

    const float* xr = x + (size_t)tok * DMODEL;
    float acc[NEXP];
    #pragma unroll
    for (int e = 0; e < NEXP; e++) acc[e] = 0.f;

    #pragma unroll 4
    for (int t = 0; t < 32; t++) {
        int d = t * 32 + lane;
        float xv = xr[d];
        #pragma unroll
        for (int e = 0; e < NEXP; e++)
            acc[e] += xv * sWgT[e * DMODEL + d];
    }
    // deterministic butterfly reduce
    #pragma unroll
    for (int e = 0; e < NEXP; e++) {
        #pragma unroll
        for (int off = 16; off; off >>= 1)
            acc[e] += __shfl_xor_sync(0xffffffffu, acc[e], off);
    }

    if (lane == 0) {
        float mx = acc[0];
        #pragma unroll
        for (int e = 1; e < NEXP; e++) mx = fmaxf(mx, acc[e]);
        float p[NEXP], sum = 0.f;
        #pragma unroll
        for (int e = 0; e < NEXP; e++) { p[e] = expf(acc[e] - mx); sum += p[e]; }
        float inv = 1.0f / sum;
        #pragma unroll
        for (int e = 0; e < NEXP; e++) p[e] *= inv;

        // top-1 (first max on ties, matching argmax)
        int i1 = 0; float v1 = p[0];
        #pragma unroll
        for (int e = 1; e < NEXP; e++) if (p[e] > v1) { v1 = p[e]; i1 = e; }
        // top-2 among remaining
        int i2 = (i1 == 0) ? 1 : 0; float v2 = p[i2];
        #pragma unroll
        for (int e = 0; e < NEXP; e++)
            if (e != i1 && p[e] > v2) { v2 = p[e]; i2 = e; }

        g_idx1[tok] = i1;  g_idx2[tok] = i2;
        g_gate1[tok] = v1; g_gate2[tok] = v2;
        #pragma unroll
        for (int e = 0; e < NEXP; e++) sP[warp][e] = p[e];
    }
    __syncthreads();
    if (threadIdx.x < NEXP) {
        float s = 0.f;
        #pragma unroll
        for (int w = 0; w < 8; w++) s += sP[w][threadIdx.x]; // fixed order
        g_partial[blockIdx.x * NEXP + threadIdx.x] = s;
    }
}

// ---------------- 2) capacity scan (single block; warp e owns expert e) ----
__global__ void __launch_bounds__(256) scan_loss_kernel(float* loss_out)
{
    int warp = threadIdx.x >> 5;     // expert id
    int lane = threadIdx.x & 31;
    int e = warp;

    // pass 1: top-1 running positions (token order preserved)
    int cnt = 0;
    for (int base = 0; base < S_TOK; base += 32) {
        int id = g_idx1[base + lane];
        unsigned m = __ballot_sync(0xffffffffu, id == e);
        if (id == e)
            g_pos1[base + lane] = cnt + __popc(m & ((1u << lane) - 1u));
        cnt += __popc(m);
    }
    if (lane == 0) g_cnt1[e] = cnt;
    int used1 = min(cnt, CAP);       // identical in every lane of the warp

    // pass 2: top-2 positions offset by used1
    int cnt2 = 0;
    for (int base = 0; base < S_TOK; base += 32) {
        int id = g_idx2[base + lane];
        unsigned m = __ballot_sync(0xffffffffu, id == e);
        if (id == e)
            g_pos2[base + lane] = used1 + cnt2 + __popc(m & ((1u << lane) - 1u));
        cnt2 += __popc(m);
    }
    __syncthreads();

    // aux loss: fixed-order reductions -> deterministic
    __shared__ float sms[NEXP];
    if (threadIdx.x < NEXP) {
        float s = 0.f;
        for (int b = 0; b < GATE_BLOCKS; b++)
            s += g_partial[b * NEXP + threadIdx.x];
        sms[threadIdx.x] = s;
    }
    __syncthreads();
    if (threadIdx.x == 0 && loss_out != nullptr) {
        const float invS = 1.0f / (float)S_TOK;
        float tot = 0.f;
        #pragma unroll
        for (int e2 = 0; e2 < NEXP; e2++)
            tot += (sms[e2] * invS) * ((float)g_cnt1[e2] * invS);
        // LOSS_COEF * mean(me*ce) * E*E
        *loss_out = 0.01f * (tot * 0.125f) * 64.0f;
    }
}

// ---------------- 3) zero dispatch buffers ----------------
__global__ void zero_buf_kernel()
{
    size_t i = (size_t)blockIdx.x * blockDim.x + threadIdx.x;
    float4 z = make_float4(0.f, 0.f, 0.f, 0.f);
    ((float4*)g_buf)[i] = z;   // grid sized exactly to cover
}

// ---------------- 4) dispatch scatter ----------------
__global__ void __launch_bounds__(256) dispatch_kernel(const float* __restrict__ x)
{
    int tok = blockIdx.x;
    int i1 = g_idx1[tok], i2 = g_idx2[tok];
    int p1 = g_pos1[tok], p2 = g_pos2[tok];
    bool k1 = p1 < CAP, k2 = p2 < CAP;

    const float4* xr = (const float4*)(x + (size_t)tok * DMODEL);
    float4* b1p = (float4*)(g_buf + ((size_t)i1 * CAP + p1) * DMODEL);
    float4* b2p = (float4*)(g_buf + ((size_t)i2 * CAP + p2) * DMODEL);

    int j = threadIdx.x;                    // 256 threads * float4 = 1024 floats
    float4 v = xr[j];
    if (k1) b1p[j] = v;
    if (k2) b2p[j] = v;
}

// ---------------- 5) grouped GEMM (fp32 SIMT, 128x128x8 double-buffered) ----
template<int DO_GELU>
__global__ void __launch_bounds__(256, 2) gemm_kernel(
    const float* __restrict__ A, const float* __restrict__ B,
    const float* __restrict__ bias, float* __restrict__ C,
    int M, int N, int K)
{
    const float* Ae = A + (size_t)blockIdx.z * M * K;
    const float* Be = B + (size_t)blockIdx.z * K * N;
    const float* be = bias + (size_t)blockIdx.z * N;
    float* Ce = C + (size_t)blockIdx.z * M * N;

    __shared__ float As[2][8][128];
    __shared__ float Bs[2][8][128];

    int tid = threadIdx.x;
    int tx = tid & 15, ty = tid >> 4;
    int m0 = ty * 8, n0 = tx * 8;
    int blockM = blockIdx.y * 128, blockN = blockIdx.x * 128;

    int arow = tid >> 1, acol = (tid & 1) * 4;   // A tile loader
    int brow = tid >> 5, bcol = (tid & 31) * 4;  // B tile loader

    float acc[8][8];
    #pragma unroll
    for (int i = 0; i < 8; i++)
        #pragma unroll
        for (int j = 0; j < 8; j++) acc[i][j] = 0.f;

    const int KT = K >> 3;
    {
        float4 a = *(const float4*)(Ae + (size_t)(blockM + arow) * K + acol);
        As[0][acol + 0][arow] = a.x; As[0][acol + 1][arow] = a.y;
        As[0][acol + 2][arow] = a.z; As[0][acol + 3][arow] = a.w;
        float4 b = *(const float4*)(Be + (size_t)brow * N + blockN + bcol);
        *(float4*)&Bs[0][brow][bcol] = b;
    }
    __syncthreads();

    for (int kt = 0; kt < KT; ++kt) {
        int s = kt & 1;
        float4 na, nb;
        bool more = (kt + 1 < KT);
        if (more) {
            int k0 = (kt + 1) * 8;
            na = *(const float4*)(Ae + (size_t)(blockM + arow) * K + k0 + acol);
            nb = *(const float4*)(Be + (size_t)(k0 + brow) * N + blockN + bcol);
        }
        #pragma unroll
        for (int kk = 0; kk < 8; ++kk) {
            float a[8], b[8];
            *(float4*)&a[0] = *(const float4*)&As[s][kk][m0];
            *(float4*)&a[4] = *(const float4*)&As[s][kk][m0 + 4];
            *(float4*)&b[0] = *(const float4*)&Bs[s][kk][n0];
            *(float4*)&b[4] = *(const float4*)&Bs[s][kk][n0 + 4];
            #pragma unroll
            for (int i = 0; i < 8; i++)
                #pragma unroll
                for (int j = 0; j < 8; j++)
                    acc[i][j] += a[i] * b[j];
        }
        if (more) {
            int s2 = s ^ 1;
            As[s2][acol + 0][arow] = na.x; As[s2][acol + 1][arow] = na.y;
            As[s2][acol + 2][arow] = na.z; As[s2][acol + 3][arow] = na.w;
            *(float4*)&Bs[s2][brow][bcol] = nb;
            __syncthreads();
        }
    }

    // epilogue: bias (+gelu) then vectorized store
    #pragma unroll
    for (int i = 0; i < 8; i++) {
        size_t row = (size_t)(blockM + m0 + i);
        float* crow = Ce + row * N + blockN + n0;
        float4 o0, o1;
        float v[8];
        #pragma unroll
        for (int j = 0; j < 8; j++) {
            float t = acc[i][j] + be[blockN + n0 + j];
            v[j] = DO_GELU ? gelu_tanh(t) : t;
        }
        o0 = make_float4(v[0], v[1], v[2], v[3]);
        o1 = make_float4(v[4], v[5], v[6], v[7]);
        *(float4*)&crow[0] = o0;
        *(float4*)&crow[4] = o1;
    }
}

// ---------------- 6) combine (gather + gate renorm) ----------------
__global__ void __launch_bounds__(256) combine_kernel(float* __restrict__ out)
{
    int tok = blockIdx.x;
    int i1 = g_idx1[tok], i2 = g_idx2[tok];
    int p1 = g_pos1[tok], p2 = g_pos2[tok];
    float ga = g_gate1[tok], gb = g_gate2[tok];
    bool k1 = p1 < CAP, k2 = p2 < CAP;
    float a1 = k1 ? ga : 0.f;
    float a2 = k2 ? gb : 0.f;
    float denom = a1 + a2 + 1e-9f;
    float w1 = a1 / denom, w2 = a2 / denom;
    int q1 = k1 ? p1 : 0, q2 = k2 ? p2 : 0;

    const float4* e1 = (const float4*)(g_eo + ((size_t)i1 * CAP + q1) * DMODEL);
    const float4* e2 = (const float4*)(g_eo + ((size_t)i2 * CAP + q2) * DMODEL);
    float4* o = (float4*)(out + (size_t)tok * DMODEL);

    int j = threadIdx.x;
    float4 v1 = e1[j], v2 = e2[j];
    float4 r;
    r.x = w1 * v1.x + w2 * v2.x;
    r.y = w1 * v1.y + w2 * v2.y;
    r.z = w1 * v1.z + w2 * v2.z;
    r.w = w1 * v1.w + w2 * v2.w;
    o[j] = r;
}

// ---------------- launch ----------------
extern "C" void kernel_launch(void* const* d_in, const int* in_sizes, int n_in,
                              void* d_out, int out_size)
{
    const float* x  = (const float*)d_in[0];  // [8,2048,1024]
    const float* Wg = (const float*)d_in[1];  // [1024,8]
    const float* W1 = (const float*)d_in[2];  // [8,1024,4096]
    const float* b1 = (const float*)d_in[3];  // [8,4096]
    const float* W2 = (const float*)d_in[4];  // [8,4096,1024]
    const float* b2 = (const float*)d_in[5];  // [8,1024]
    float* out = (float*)d_out;

    // device scratch addresses (pure queries; capture-safe, no allocation)
    void *pbuf, *ph, *peo;
    cudaGetSymbolAddress(&pbuf, g_buf);
    cudaGetSymbolAddress(&ph,   g_h);
    cudaGetSymbolAddress(&peo,  g_eo);

    float* loss_ptr = (out_size > S_TOK * DMODEL) ? (out + (size_t)S_TOK * DMODEL)
                                                  : nullptr;

    gating_kernel<<<GATE_BLOCKS, 256>>>(x, Wg);
    scan_loss_kernel<<<1, 256>>>(loss_ptr);

    // zero dispatch buffers: 8*2560*1024 floats = 5,242,880 float4
    zero_buf_kernel<<<(NEXP * CAP * DMODEL / 4) / 256, 256>>>();
    dispatch_kernel<<<S_TOK, 256>>>(x);

    // GEMM1: [C,D] x [D,H] + b1, gelu -> h
    dim3 grid1(HFFN / 128, CAP / 128, NEXP);
    gemm_kernel<1><<<grid1, 256>>>((const float*)pbuf, W1, b1, (float*)ph,
                                   CAP, HFFN, DMODEL);
    // GEMM2: [C,H] x [H,D] + b2 -> eo
    dim3 grid2(DMODEL / 128, CAP / 128, NEXP);
    gemm_kernel<0><<<grid2, 256>>>((const float*)ph, W2, b2, (float*)peo,
                                   CAP, DMODEL, HFFN);

    combine_kernel<<<S_TOK, 256>>>(out);
}

// round 3
// speedup vs baseline: 3.0651x; 3.0651x over previous
#include <cuda_runtime.h>
#include <cuda_bf16.h>
#include <math.h>
#include <stdint.h>

// ---------------- problem constants ----------------
#define S_TOK   16384          // B*N
#define DMODEL  1024
#define NEXP    8
#define HFFN    4096
#define CAP     2560           // int(S*1.25/E)
#define GATE_BLOCKS (S_TOK/8)

// ---------------- device scratch (allocation-free rule) ----------------
__device__ float g_buf[NEXP * CAP * DMODEL];          // 80 MB  dispatch (tf32)
__device__ float g_h  [(size_t)NEXP * CAP * HFFN];    // 320 MB hidden (tf32)
__device__ float g_eo [NEXP * CAP * DMODEL];          // 80 MB  expert outputs
__device__ float g_w1r[(size_t)NEXP * DMODEL * HFFN]; // 134 MB W1 tf32-rounded
__device__ float g_w2r[(size_t)NEXP * HFFN * DMODEL]; // 134 MB W2 tf32-rounded
__device__ float g_gate1[S_TOK];
__device__ float g_gate2[S_TOK];
__device__ int   g_idx1[S_TOK];
__device__ int   g_idx2[S_TOK];
__device__ int   g_pos1[S_TOK];
__device__ int   g_pos2[S_TOK];
__device__ float g_partial[GATE_BLOCKS * NEXP];
__device__ int   g_cnt1[NEXP];

// ---------------- helpers ----------------
__device__ __forceinline__ float gelu_tanh(float x) {
    float x3 = x * x * x;
    return 0.5f * x * (1.0f + tanhf(0.7978845608028654f * (x + 0.044715f * x3)));
}
__device__ __forceinline__ float to_tf32(float x) {
    uint32_t u;
    asm("cvt.rna.tf32.f32 %0, %1;" : "=r"(u) : "f"(x));
    return __uint_as_float(u);
}
__device__ __forceinline__ uint32_t smem_u32(const void* p) {
    uint32_t a;
    asm("{ .reg .u64 t; cvta.to.shared.u64 t, %1; cvt.u32.u64 %0, t; }" : "=r"(a) : "l"(p));
    return a;
}
__device__ __forceinline__ void cp_async16(uint32_t dst, const void* src) {
    asm volatile("cp.async.cg.shared.global [%0], [%1], 16;" :: "r"(dst), "l"(src));
}
__device__ __forceinline__ void cp_commit() {
    asm volatile("cp.async.commit_group;");
}
template<int N>
__device__ __forceinline__ void cp_wait() {
    asm volatile("cp.async.wait_group %0;" :: "n"(N));
}
__device__ __forceinline__ void mma_tf32(float& c0, float& c1, float& c2, float& c3,
                                         uint32_t a0, uint32_t a1, uint32_t a2, uint32_t a3,
                                         uint32_t b0, uint32_t b1) {
    asm volatile(
        "mma.sync.aligned.m16n8k8.row.col.f32.tf32.tf32.f32 "
        "{%0,%1,%2,%3}, {%4,%5,%6,%7}, {%8,%9}, {%0,%1,%2,%3};"
        : "+f"(c0), "+f"(c1), "+f"(c2), "+f"(c3)
        : "r"(a0), "r"(a1), "r"(a2), "r"(a3), "r"(b0), "r"(b1));
}

// ---------------- 1) gating ----------------
__global__ void __launch_bounds__(256) gating_kernel(
    const float* __restrict__ x, const float* __restrict__ Wg)
{
    __shared__ float sWgT[NEXP * DMODEL];
    __shared__ float sP[8][NEXP];
    for (int i = threadIdx.x; i < NEXP * DMODEL; i += blockDim.x) {
        int d = i & (DMODEL - 1);
        int e = i >> 10;
        sWgT[i] = Wg[d * NEXP + e];
    }
    __syncthreads();

    int warp = threadIdx.x >> 5;
    int lane = threadIdx.x & 31;
    int tok  = blockIdx.x * 8 + warp;

    const float* xr = x + (size_t)tok * DMODEL;
    float acc[NEXP];
    #pragma unroll
    for (int e = 0; e < NEXP; e++) acc[e] = 0.f;

    #pragma unroll 4
    for (int t = 0; t < 32; t++) {
        int d = t * 32 + lane;
        float xv = xr[d];
        #pragma unroll
        for (int e = 0; e < NEXP; e++)
            acc[e] += xv * sWgT[e * DMODEL + d];
    }
    #pragma unroll
    for (int e = 0; e < NEXP; e++) {
        #pragma unroll
        for (int off = 16; off; off >>= 1)
            acc[e] += __shfl_xor_sync(0xffffffffu, acc[e], off);
    }

    if (lane == 0) {
        float mx = acc[0];
        #pragma unroll
        for (int e = 1; e < NEXP; e++) mx = fmaxf(mx, acc[e]);
        float p[NEXP], sum = 0.f;
        #pragma unroll
        for (int e = 0; e < NEXP; e++) { p[e] = expf(acc[e] - mx); sum += p[e]; }
        float inv = 1.0f / sum;
        #pragma unroll
        for (int e = 0; e < NEXP; e++) p[e] *= inv;

        int i1 = 0; float v1 = p[0];
        #pragma unroll
        for (int e = 1; e < NEXP; e++) if (p[e] > v1) { v1 = p[e]; i1 = e; }
        int i2 = (i1 == 0) ? 1 : 0; float v2 = p[i2];
        #pragma unroll
        for (int e = 0; e < NEXP; e++)
            if (e != i1 && p[e] > v2) { v2 = p[e]; i2 = e; }

        g_idx1[tok] = i1;  g_idx2[tok] = i2;
        g_gate1[tok] = v1; g_gate2[tok] = v2;
        #pragma unroll
        for (int e = 0; e < NEXP; e++) sP[warp][e] = p[e];
    }
    __syncthreads();
    if (threadIdx.x < NEXP) {
        float s = 0.f;
        #pragma unroll
        for (int w = 0; w < 8; w++) s += sP[w][threadIdx.x];
        g_partial[blockIdx.x * NEXP + threadIdx.x] = s;
    }
}

// ---------------- 2) capacity scan + loss ----------------
__global__ void __launch_bounds__(256) scan_loss_kernel(float* loss_out)
{
    int warp = threadIdx.x >> 5;
    int lane = threadIdx.x & 31;
    int e = warp;

    int cnt = 0;
    for (int base = 0; base < S_TOK; base += 32) {
        int id = g_idx1[base + lane];
        unsigned m = __ballot_sync(0xffffffffu, id == e);
        if (id == e)
            g_pos1[base + lane] = cnt + __popc(m & ((1u << lane) - 1u));
        cnt += __popc(m);
    }
    if (lane == 0) g_cnt1[e] = cnt;
    int used1 = min(cnt, CAP);

    int cnt2 = 0;
    for (int base = 0; base < S_TOK; base += 32) {
        int id = g_idx2[base + lane];
        unsigned m = __ballot_sync(0xffffffffu, id == e);
        if (id == e)
            g_pos2[base + lane] = used1 + cnt2 + __popc(m & ((1u << lane) - 1u));
        cnt2 += __popc(m);
    }
    __syncthreads();

    __shared__ float sms[NEXP];
    if (threadIdx.x < NEXP) {
        float s = 0.f;
        for (int b = 0; b < GATE_BLOCKS; b++)
            s += g_partial[b * NEXP + threadIdx.x];
        sms[threadIdx.x] = s;
    }
    __syncthreads();
    if (threadIdx.x == 0 && loss_out != nullptr) {
        const float invS = 1.0f / (float)S_TOK;
        float tot = 0.f;
        #pragma unroll
        for (int e2 = 0; e2 < NEXP; e2++)
            tot += (sms[e2] * invS) * ((float)g_cnt1[e2] * invS);
        *loss_out = 0.01f * (tot * 0.125f) * 64.0f;
    }
}

// ---------------- 3) zero dispatch buffers ----------------
__global__ void zero_buf_kernel()
{
    size_t i = (size_t)blockIdx.x * blockDim.x + threadIdx.x;
    ((float4*)g_buf)[i] = make_float4(0.f, 0.f, 0.f, 0.f);
}

// ---------------- 4) dispatch scatter (+ tf32 RNA round) ----------------
__global__ void __launch_bounds__(256) dispatch_kernel(const float* __restrict__ x)
{
    int tok = blockIdx.x;
    int i1 = g_idx1[tok], i2 = g_idx2[tok];
    int p1 = g_pos1[tok], p2 = g_pos2[tok];
    bool k1 = p1 < CAP, k2 = p2 < CAP;

    const float4* xr = (const float4*)(x + (size_t)tok * DMODEL);
    float4* b1p = (float4*)(g_buf + ((size_t)i1 * CAP + p1) * DMODEL);
    float4* b2p = (float4*)(g_buf + ((size_t)i2 * CAP + p2) * DMODEL);

    int j = threadIdx.x;
    float4 v = xr[j];
    v.x = to_tf32(v.x); v.y = to_tf32(v.y); v.z = to_tf32(v.z); v.w = to_tf32(v.w);
    if (k1) b1p[j] = v;
    if (k2) b2p[j] = v;
}

// ---------------- 5) streaming tf32 round of weights ----------------
__global__ void __launch_bounds__(256) round_tf32_kernel(
    const float4* __restrict__ in, float4* __restrict__ out)
{
    size_t i = (size_t)blockIdx.x * blockDim.x + threadIdx.x;
    float4 v = in[i];
    v.x = to_tf32(v.x); v.y = to_tf32(v.y); v.z = to_tf32(v.z); v.w = to_tf32(v.w);
    out[i] = v;
}

// ---------------- 6) tf32 mma.sync grouped GEMM ----------------
// C[e] = A[e] (MxK, row-major) @ B[e] (KxN, row-major) + bias  (opt gelu+round)
// Block tile 128x256, BK=32, 8 warps (warp tile 64x64), 3-stage cp.async.
#define BM 128
#define BN 256
#define BK 32
#define AST 36                   // A smem row stride (floats): banks (4g+t) distinct
#define BST 264                  // B smem row stride (floats): banks (8t+g) distinct
#define STG_FLT (BM*AST + BK*BST)   // 4608 + 8448 = 13056 floats per stage
#define NSTG 3
#define GEMM_SMEM (NSTG * STG_FLT * 4)  // 156672 bytes

template<int DO_GELU>
__global__ void __launch_bounds__(256, 1) moe_mma_gemm(
    const float* __restrict__ A, const float* __restrict__ B,
    const float* __restrict__ bias, float* __restrict__ C,
    int M, int N, int K)
{
    extern __shared__ float smem[];
    const uint32_t sb = smem_u32(smem);

    const int tid = threadIdx.x;
    const int lane = tid & 31;
    const int wid = tid >> 5;
    const int wm = wid & 1;          // warp m half (0/1)
    const int wn = wid >> 1;         // warp n quarter (0..3)
    const int g = lane >> 2;         // fragment group row 0..7
    const int t4 = lane & 3;         // fragment k/col 0..3

    const int e = blockIdx.z;
    const int mbase = blockIdx.x * BM;
    const int nbase = blockIdx.y * BN;
    const float* Ae = A + (size_t)e * M * K;
    const float* Be = B + (size_t)e * K * N;

    // cp.async per-thread mapping
    const int a_c = tid & 7;                 // 16B chunk within 32-float row
    const int a_m0 = tid >> 3;               // + t*32
    const int b_c = tid & 63;                // 16B chunk within 256-float row
    const int b_k0 = tid >> 6;               // + t*4

    const int KT = K / BK;

    auto load_stage = [&](int s, int kt) {
        uint32_t abase = sb + (uint32_t)s * (STG_FLT * 4);
        uint32_t bbase = abase + BM * AST * 4;
        const float* Asrc = Ae + (size_t)(mbase) * K + kt * BK;
        const float* Bsrc = Be + (size_t)(kt * BK) * N + nbase;
        #pragma unroll
        for (int t = 0; t < 4; t++) {
            int m = a_m0 + t * 32;
            cp_async16(abase + (uint32_t)(m * AST + a_c * 4) * 4,
                       Asrc + (size_t)m * K + a_c * 4);
        }
        #pragma unroll
        for (int t = 0; t < 8; t++) {
            int k = b_k0 + t * 4;
            cp_async16(bbase + (uint32_t)(k * BST + b_c * 4) * 4,
                       Bsrc + (size_t)k * N + b_c * 4);
        }
    };

    float acc[4][8][4];
    #pragma unroll
    for (int i = 0; i < 4; i++)
        #pragma unroll
        for (int j = 0; j < 8; j++)
            #pragma unroll
            for (int r = 0; r < 4; r++) acc[i][j][r] = 0.f;

    load_stage(0, 0); cp_commit();
    load_stage(1, 1); cp_commit();

    for (int kt = 0; kt < KT; kt++) {
        cp_wait<1>();
        __syncthreads();
        if (kt + 2 < KT) load_stage((kt + 2) % NSTG, kt + 2);
        cp_commit();   // empty commit keeps group counting exact at the tail

        int s = kt % NSTG;
        const float* As = smem + (size_t)s * STG_FLT;
        const float* Bs = As + BM * AST;

        #pragma unroll
        for (int kc = 0; kc < 4; kc++) {
            uint32_t a[4][4], b[8][2];
            #pragma unroll
            for (int i = 0; i < 4; i++) {
                const float* ap = As + (wm * 64 + i * 16 + g) * AST + kc * 8 + t4;
                a[i][0] = __float_as_uint(ap[0]);
                a[i][1] = __float_as_uint(ap[8 * AST]);
                a[i][2] = __float_as_uint(ap[4]);
                a[i][3] = __float_as_uint(ap[8 * AST + 4]);
            }
            #pragma unroll
            for (int j = 0; j < 8; j++) {
                const float* bp = Bs + (kc * 8 + t4) * BST + wn * 64 + j * 8 + g;
                b[j][0] = __float_as_uint(bp[0]);
                b[j][1] = __float_as_uint(bp[4 * BST]);
            }
            #pragma unroll
            for (int i = 0; i < 4; i++)
                #pragma unroll
                for (int j = 0; j < 8; j++)
                    mma_tf32(acc[i][j][0], acc[i][j][1], acc[i][j][2], acc[i][j][3],
                             a[i][0], a[i][1], a[i][2], a[i][3],
                             b[j][0], b[j][1]);
        }
        __syncthreads();
    }

    // ---- epilogue ----
    const float* brow = bias + (size_t)e * N + nbase + wn * 64;
    float* Cr = C + ((size_t)e * M + mbase + wm * 64) * N + nbase + wn * 64;
    #pragma unroll
    for (int i = 0; i < 4; i++) {
        #pragma unroll
        for (int j = 0; j < 8; j++) {
            int col = j * 8 + 2 * t4;
            float b0 = brow[col], b1 = brow[col + 1];
            float v0 = acc[i][j][0] + b0;
            float v1 = acc[i][j][1] + b1;
            float v2 = acc[i][j][2] + b0;
            float v3 = acc[i][j][3] + b1;
            if (DO_GELU) {
                v0 = to_tf32(gelu_tanh(v0)); v1 = to_tf32(gelu_tanh(v1));
                v2 = to_tf32(gelu_tanh(v2)); v3 = to_tf32(gelu_tanh(v3));
            }
            float* r0 = Cr + (size_t)(i * 16 + g) * N + col;
            float* r1 = Cr + (size_t)(i * 16 + g + 8) * N + col;
            *(float2*)r0 = make_float2(v0, v1);
            *(float2*)r1 = make_float2(v2, v3);
        }
    }
}

// ---------------- 7) combine ----------------
__global__ void __launch_bounds__(256) combine_kernel(float* __restrict__ out)
{
    int tok = blockIdx.x;
    int i1 = g_idx1[tok], i2 = g_idx2[tok];
    int p1 = g_pos1[tok], p2 = g_pos2[tok];
    float ga = g_gate1[tok], gb = g_gate2[tok];
    bool k1 = p1 < CAP, k2 = p2 < CAP;
    float a1 = k1 ? ga : 0.f;
    float a2 = k2 ? gb : 0.f;
    float denom = a1 + a2 + 1e-9f;
    float w1 = a1 / denom, w2 = a2 / denom;
    int q1 = k1 ? p1 : 0, q2 = k2 ? p2 : 0;

    const float4* e1 = (const float4*)(g_eo + ((size_t)i1 * CAP + q1) * DMODEL);
    const float4* e2 = (const float4*)(g_eo + ((size_t)i2 * CAP + q2) * DMODEL);
    float4* o = (float4*)(out + (size_t)tok * DMODEL);

    int j = threadIdx.x;
    float4 v1 = e1[j], v2 = e2[j];
    float4 r;
    r.x = w1 * v1.x + w2 * v2.x;
    r.y = w1 * v1.y + w2 * v2.y;
    r.z = w1 * v1.z + w2 * v2.z;
    r.w = w1 * v1.w + w2 * v2.w;
    o[j] = r;
}

// ---------------- launch ----------------
extern "C" void kernel_launch(void* const* d_in, const int* in_sizes, int n_in,
                              void* d_out, int out_size)
{
    const float* x  = (const float*)d_in[0];
    const float* Wg = (const float*)d_in[1];
    const float* W1 = (const float*)d_in[2];
    const float* b1 = (const float*)d_in[3];
    const float* W2 = (const float*)d_in[4];
    const float* b2 = (const float*)d_in[5];
    float* out = (float*)d_out;

    void *pbuf, *ph, *peo, *pw1r, *pw2r;
    cudaGetSymbolAddress(&pbuf, g_buf);
    cudaGetSymbolAddress(&ph,   g_h);
    cudaGetSymbolAddress(&peo,  g_eo);
    cudaGetSymbolAddress(&pw1r, g_w1r);
    cudaGetSymbolAddress(&pw2r, g_w2r);

    cudaFuncSetAttribute(moe_mma_gemm<1>,
                         cudaFuncAttributeMaxDynamicSharedMemorySize, GEMM_SMEM);
    cudaFuncSetAttribute(moe_mma_gemm<0>,
                         cudaFuncAttributeMaxDynamicSharedMemorySize, GEMM_SMEM);

    float* loss_ptr = (out_size > S_TOK * DMODEL) ? (out + (size_t)S_TOK * DMODEL)
                                                  : nullptr;

    // round weights to tf32 (RNA) once per call
    const int WBLK = ((size_t)NEXP * DMODEL * HFFN / 4) / 256;  // 32768
    round_tf32_kernel<<<WBLK, 256>>>((const float4*)W1, (float4*)pw1r);
    round_tf32_kernel<<<WBLK, 256>>>((const float4*)W2, (float4*)pw2r);

    gating_kernel<<<GATE_BLOCKS, 256>>>(x, Wg);
    scan_loss_kernel<<<1, 256>>>(loss_ptr);

    zero_buf_kernel<<<(NEXP * CAP * DMODEL / 4) / 256, 256>>>();
    dispatch_kernel<<<S_TOK, 256>>>(x);

    // GEMM1: h = gelu(buf @ W1 + b1), tf32-rounded output
    moe_mma_gemm<1><<<dim3(CAP / BM, HFFN / BN, NEXP), 256, GEMM_SMEM>>>(
        (const float*)pbuf, (const float*)pw1r, b1, (float*)ph,
        CAP, HFFN, DMODEL);
    // GEMM2: eo = h @ W2 + b2
    moe_mma_gemm<0><<<dim3(CAP / BM, DMODEL / BN, NEXP), 256, GEMM_SMEM>>>(
        (const float*)ph, (const float*)pw2r, b2, (float*)peo,
        CAP, DMODEL, HFFN);

    combine_kernel<<<S_TOK, 256>>>(out);
}

// round 4
// speedup vs baseline: 3.4573x; 1.1279x over previous
#include <cuda_runtime.h>
#include <cuda_bf16.h>
#include <math.h>
#include <stdint.h>

// ---------------- problem constants ----------------
#define S_TOK   16384          // B*N
#define DMODEL  1024
#define NEXP    8
#define HFFN    4096
#define CAP     2560           // int(S*1.25/E)
#define GATE_BLOCKS (S_TOK/8)

// ---------------- device scratch (allocation-free rule) ----------------
__device__ float g_buf[NEXP * CAP * DMODEL];          // 80 MB  dispatch (tf32)
__device__ float g_h  [(size_t)NEXP * CAP * HFFN];    // 320 MB hidden (tf32)
__device__ float g_eo [NEXP * CAP * DMODEL];          // 80 MB  expert outputs
__device__ float g_gate1[S_TOK];
__device__ float g_gate2[S_TOK];
__device__ int   g_idx1[S_TOK];
__device__ int   g_idx2[S_TOK];
__device__ int   g_pos1[S_TOK];
__device__ int   g_pos2[S_TOK];
__device__ float g_partial[GATE_BLOCKS * NEXP];
__device__ int   g_cnt1[NEXP];

// ---------------- helpers ----------------
__device__ __forceinline__ float gelu_tanh(float x) {
    float x3 = x * x * x;
    return 0.5f * x * (1.0f + tanhf(0.7978845608028654f * (x + 0.044715f * x3)));
}
__device__ __forceinline__ float to_tf32(float x) {
    uint32_t u;
    asm("cvt.rna.tf32.f32 %0, %1;" : "=r"(u) : "f"(x));
    return __uint_as_float(u);
}
__device__ __forceinline__ uint32_t tf32_bits(float x) {
    uint32_t u;
    asm("cvt.rna.tf32.f32 %0, %1;" : "=r"(u) : "f"(x));
    return u;
}
__device__ __forceinline__ uint32_t smem_u32(const void* p) {
    uint32_t a;
    asm("{ .reg .u64 t; cvta.to.shared.u64 t, %1; cvt.u32.u64 %0, t; }" : "=r"(a) : "l"(p));
    return a;
}
__device__ __forceinline__ void cp_async16(uint32_t dst, const void* src) {
    asm volatile("cp.async.cg.shared.global [%0], [%1], 16;" :: "r"(dst), "l"(src));
}
__device__ __forceinline__ void cp_commit() {
    asm volatile("cp.async.commit_group;");
}
template<int N>
__device__ __forceinline__ void cp_wait() {
    asm volatile("cp.async.wait_group %0;" :: "n"(N));
}
__device__ __forceinline__ void mma_tf32(float& c0, float& c1, float& c2, float& c3,
                                         uint32_t a0, uint32_t a1, uint32_t a2, uint32_t a3,
                                         uint32_t b0, uint32_t b1) {
    asm volatile(
        "mma.sync.aligned.m16n8k8.row.col.f32.tf32.tf32.f32 "
        "{%0,%1,%2,%3}, {%4,%5,%6,%7}, {%8,%9}, {%0,%1,%2,%3};"
        : "+f"(c0), "+f"(c1), "+f"(c2), "+f"(c3)
        : "r"(a0), "r"(a1), "r"(a2), "r"(a3), "r"(b0), "r"(b1));
}

// ---------------- 1) gating ----------------
__global__ void __launch_bounds__(256) gating_kernel(
    const float* __restrict__ x, const float* __restrict__ Wg)
{
    __shared__ float sWgT[NEXP * DMODEL];
    __shared__ float sP[8][NEXP];
    for (int i = threadIdx.x; i < NEXP * DMODEL; i += blockDim.x) {
        int d = i & (DMODEL - 1);
        int e = i >> 10;
        sWgT[i] = Wg[d * NEXP + e];
    }
    __syncthreads();

    int warp = threadIdx.x >> 5;
    int lane = threadIdx.x & 31;
    int tok  = blockIdx.x * 8 + warp;

    const float* xr = x + (size_t)tok * DMODEL;
    float acc[NEXP];
    #pragma unroll
    for (int e = 0; e < NEXP; e++) acc[e] = 0.f;

    #pragma unroll 4
    for (int t = 0; t < 32; t++) {
        int d = t * 32 + lane;
        float xv = xr[d];
        #pragma unroll
        for (int e = 0; e < NEXP; e++)
            acc[e] += xv * sWgT[e * DMODEL + d];
    }
    #pragma unroll
    for (int e = 0; e < NEXP; e++) {
        #pragma unroll
        for (int off = 16; off; off >>= 1)
            acc[e] += __shfl_xor_sync(0xffffffffu, acc[e], off);
    }

    if (lane == 0) {
        float mx = acc[0];
        #pragma unroll
        for (int e = 1; e < NEXP; e++) mx = fmaxf(mx, acc[e]);
        float p[NEXP], sum = 0.f;
        #pragma unroll
        for (int e = 0; e < NEXP; e++) { p[e] = expf(acc[e] - mx); sum += p[e]; }
        float inv = 1.0f / sum;
        #pragma unroll
        for (int e = 0; e < NEXP; e++) p[e] *= inv;

        int i1 = 0; float v1 = p[0];
        #pragma unroll
        for (int e = 1; e < NEXP; e++) if (p[e] > v1) { v1 = p[e]; i1 = e; }
        int i2 = (i1 == 0) ? 1 : 0; float v2 = p[i2];
        #pragma unroll
        for (int e = 0; e < NEXP; e++)
            if (e != i1 && p[e] > v2) { v2 = p[e]; i2 = e; }

        g_idx1[tok] = i1;  g_idx2[tok] = i2;
        g_gate1[tok] = v1; g_gate2[tok] = v2;
        #pragma unroll
        for (int e = 0; e < NEXP; e++) sP[warp][e] = p[e];
    }
    __syncthreads();
    if (threadIdx.x < NEXP) {
        float s = 0.f;
        #pragma unroll
        for (int w = 0; w < 8; w++) s += sP[w][threadIdx.x];
        g_partial[blockIdx.x * NEXP + threadIdx.x] = s;
    }
}

// ---------------- 2) capacity scan + loss (smem-staged, warp-parallel) ----
#define SCAN_SMEM (2 * S_TOK * 4)   // 128 KB: idx1 then idx2

__global__ void __launch_bounds__(256) scan_loss_kernel(float* loss_out)
{
    extern __shared__ int sidx[];
    int* s1 = sidx;
    int* s2 = sidx + S_TOK;

    // cooperative vectorized staging of both index arrays (high MLP)
    {
        const int4* p1 = (const int4*)g_idx1;
        const int4* p2 = (const int4*)g_idx2;
        int4* q1 = (int4*)s1;
        int4* q2 = (int4*)s2;
        #pragma unroll
        for (int i = 0; i < S_TOK / 4 / 256; i++) {
            q1[threadIdx.x + i * 256] = p1[threadIdx.x + i * 256];
            q2[threadIdx.x + i * 256] = p2[threadIdx.x + i * 256];
        }
    }
    __syncthreads();

    int warp = threadIdx.x >> 5;
    int lane = threadIdx.x & 31;
    int e = warp;
    unsigned lmask = (1u << lane) - 1u;

    // pass 1: top-1 positions
    int cnt = 0;
    #pragma unroll 4
    for (int base = 0; base < S_TOK; base += 32) {
        int id = s1[base + lane];
        unsigned m = __ballot_sync(0xffffffffu, id == e);
        if (id == e)
            g_pos1[base + lane] = cnt + __popc(m & lmask);
        cnt += __popc(m);
    }
    if (lane == 0) g_cnt1[e] = cnt;
    int used1 = min(cnt, CAP);

    // pass 2: top-2 positions offset by used1
    int cnt2 = 0;
    #pragma unroll 4
    for (int base = 0; base < S_TOK; base += 32) {
        int id = s2[base + lane];
        unsigned m = __ballot_sync(0xffffffffu, id == e);
        if (id == e)
            g_pos2[base + lane] = used1 + cnt2 + __popc(m & lmask);
        cnt2 += __popc(m);
    }

    // loss: warp e reduces g_partial[:, e] (strided + butterfly, deterministic)
    float s = 0.f;
    #pragma unroll 4
    for (int b = lane; b < GATE_BLOCKS; b += 32)
        s += g_partial[b * NEXP + e];
    #pragma unroll
    for (int off = 16; off; off >>= 1)
        s += __shfl_xor_sync(0xffffffffu, s, off);

    __shared__ float sms[NEXP];
    if (lane == 0) sms[e] = s;
    __syncthreads();
    if (threadIdx.x == 0 && loss_out != nullptr) {
        const float invS = 1.0f / (float)S_TOK;
        float tot = 0.f;
        #pragma unroll
        for (int e2 = 0; e2 < NEXP; e2++)
            tot += (sms[e2] * invS) * ((float)g_cnt1[e2] * invS);
        *loss_out = 0.01f * (tot * 0.125f) * 64.0f;
    }
}

// ---------------- 3) zero dispatch buffers ----------------
__global__ void zero_buf_kernel()
{
    size_t i = (size_t)blockIdx.x * blockDim.x + threadIdx.x;
    ((float4*)g_buf)[i] = make_float4(0.f, 0.f, 0.f, 0.f);
}

// ---------------- 4) dispatch scatter (+ tf32 RNA round) ----------------
__global__ void __launch_bounds__(256) dispatch_kernel(const float* __restrict__ x)
{
    int tok = blockIdx.x;
    int i1 = g_idx1[tok], i2 = g_idx2[tok];
    int p1 = g_pos1[tok], p2 = g_pos2[tok];
    bool k1 = p1 < CAP, k2 = p2 < CAP;

    const float4* xr = (const float4*)(x + (size_t)tok * DMODEL);
    float4* b1p = (float4*)(g_buf + ((size_t)i1 * CAP + p1) * DMODEL);
    float4* b2p = (float4*)(g_buf + ((size_t)i2 * CAP + p2) * DMODEL);

    int j = threadIdx.x;
    float4 v = xr[j];
    v.x = to_tf32(v.x); v.y = to_tf32(v.y); v.z = to_tf32(v.z); v.w = to_tf32(v.w);
    if (k1) b1p[j] = v;
    if (k2) b2p[j] = v;
}

// ---------------- 5) tf32 mma.sync grouped GEMM (B rounded in-register) ----
// C[e] = A[e] (MxK, row-major, already tf32) @ B[e] (KxN, row-major, fp32)
// Block tile 128x256, BK=32, 8 warps (warp tile 64x64), 3-stage cp.async.
#define BM 128
#define BN 256
#define BK 32
#define AST 36                   // A smem row stride (floats)
#define BST 264                  // B smem row stride (floats)
#define STG_FLT (BM*AST + BK*BST)   // 13056 floats per stage
#define NSTG 3
#define GEMM_SMEM (NSTG * STG_FLT * 4)  // 156672 bytes

template<int DO_GELU>
__global__ void __launch_bounds__(256, 1) moe_mma_gemm(
    const float* __restrict__ A, const float* __restrict__ B,
    const float* __restrict__ bias, float* __restrict__ C,
    int M, int N, int K)
{
    extern __shared__ float smem[];
    const uint32_t sb = smem_u32(smem);

    const int tid = threadIdx.x;
    const int lane = tid & 31;
    const int wid = tid >> 5;
    const int wm = wid & 1;
    const int wn = wid >> 1;
    const int g = lane >> 2;
    const int t4 = lane & 3;

    const int e = blockIdx.z;
    const int mbase = blockIdx.x * BM;
    const int nbase = blockIdx.y * BN;
    const float* Ae = A + (size_t)e * M * K;
    const float* Be = B + (size_t)e * K * N;

    const int a_c = tid & 7;
    const int a_m0 = tid >> 3;
    const int b_c = tid & 63;
    const int b_k0 = tid >> 6;

    const int KT = K / BK;

    auto load_stage = [&](int s, int kt) {
        uint32_t abase = sb + (uint32_t)s * (STG_FLT * 4);
        uint32_t bbase = abase + BM * AST * 4;
        const float* Asrc = Ae + (size_t)(mbase) * K + kt * BK;
        const float* Bsrc = Be + (size_t)(kt * BK) * N + nbase;
        #pragma unroll
        for (int t = 0; t < 4; t++) {
            int m = a_m0 + t * 32;
            cp_async16(abase + (uint32_t)(m * AST + a_c * 4) * 4,
                       Asrc + (size_t)m * K + a_c * 4);
        }
        #pragma unroll
        for (int t = 0; t < 8; t++) {
            int k = b_k0 + t * 4;
            cp_async16(bbase + (uint32_t)(k * BST + b_c * 4) * 4,
                       Bsrc + (size_t)k * N + b_c * 4);
        }
    };

    float acc[4][8][4];
    #pragma unroll
    for (int i = 0; i < 4; i++)
        #pragma unroll
        for (int j = 0; j < 8; j++)
            #pragma unroll
            for (int r = 0; r < 4; r++) acc[i][j][r] = 0.f;

    load_stage(0, 0); cp_commit();
    load_stage(1, 1); cp_commit();

    for (int kt = 0; kt < KT; kt++) {
        cp_wait<1>();
        __syncthreads();
        if (kt + 2 < KT) load_stage((kt + 2) % NSTG, kt + 2);
        cp_commit();

        int s = kt % NSTG;
        const float* As = smem + (size_t)s * STG_FLT;
        const float* Bs = As + BM * AST;

        #pragma unroll
        for (int kc = 0; kc < 4; kc++) {
            uint32_t a[4][4], b[8][2];
            #pragma unroll
            for (int i = 0; i < 4; i++) {
                const float* ap = As + (wm * 64 + i * 16 + g) * AST + kc * 8 + t4;
                a[i][0] = __float_as_uint(ap[0]);
                a[i][1] = __float_as_uint(ap[8 * AST]);
                a[i][2] = __float_as_uint(ap[4]);
                a[i][3] = __float_as_uint(ap[8 * AST + 4]);
            }
            #pragma unroll
            for (int j = 0; j < 8; j++) {
                const float* bp = Bs + (kc * 8 + t4) * BST + wn * 64 + j * 8 + g;
                b[j][0] = tf32_bits(bp[0]);           // fused RNA round of weights
                b[j][1] = tf32_bits(bp[4 * BST]);
            }
            #pragma unroll
            for (int i = 0; i < 4; i++)
                #pragma unroll
                for (int j = 0; j < 8; j++)
                    mma_tf32(acc[i][j][0], acc[i][j][1], acc[i][j][2], acc[i][j][3],
                             a[i][0], a[i][1], a[i][2], a[i][3],
                             b[j][0], b[j][1]);
        }
        __syncthreads();
    }

    // ---- epilogue ----
    const float* brow = bias + (size_t)e * N + nbase + wn * 64;
    float* Cr = C + ((size_t)e * M + mbase + wm * 64) * N + nbase + wn * 64;
    #pragma unroll
    for (int i = 0; i < 4; i++) {
        #pragma unroll
        for (int j = 0; j < 8; j++) {
            int col = j * 8 + 2 * t4;
            float b0 = brow[col], b1 = brow[col + 1];
            float v0 = acc[i][j][0] + b0;
            float v1 = acc[i][j][1] + b1;
            float v2 = acc[i][j][2] + b0;
            float v3 = acc[i][j][3] + b1;
            if (DO_GELU) {
                v0 = to_tf32(gelu_tanh(v0)); v1 = to_tf32(gelu_tanh(v1));
                v2 = to_tf32(gelu_tanh(v2)); v3 = to_tf32(gelu_tanh(v3));
            }
            float* r0 = Cr + (size_t)(i * 16 + g) * N + col;
            float* r1 = Cr + (size_t)(i * 16 + g + 8) * N + col;
            *(float2*)r0 = make_float2(v0, v1);
            *(float2*)r1 = make_float2(v2, v3);
        }
    }
}

// ---------------- 6) combine ----------------
__global__ void __launch_bounds__(256) combine_kernel(float* __restrict__ out)
{
    int tok = blockIdx.x;
    int i1 = g_idx1[tok], i2 = g_idx2[tok];
    int p1 = g_pos1[tok], p2 = g_pos2[tok];
    float ga = g_gate1[tok], gb = g_gate2[tok];
    bool k1 = p1 < CAP, k2 = p2 < CAP;
    float a1 = k1 ? ga : 0.f;
    float a2 = k2 ? gb : 0.f;
    float denom = a1 + a2 + 1e-9f;
    float w1 = a1 / denom, w2 = a2 / denom;
    int q1 = k1 ? p1 : 0, q2 = k2 ? p2 : 0;

    const float4* e1 = (const float4*)(g_eo + ((size_t)i1 * CAP + q1) * DMODEL);
    const float4* e2 = (const float4*)(g_eo + ((size_t)i2 * CAP + q2) * DMODEL);
    float4* o = (float4*)(out + (size_t)tok * DMODEL);

    int j = threadIdx.x;
    float4 v1 = e1[j], v2 = e2[j];
    float4 r;
    r.x = w1 * v1.x + w2 * v2.x;
    r.y = w1 * v1.y + w2 * v2.y;
    r.z = w1 * v1.z + w2 * v2.z;
    r.w = w1 * v1.w + w2 * v2.w;
    o[j] = r;
}

// ---------------- launch ----------------
extern "C" void kernel_launch(void* const* d_in, const int* in_sizes, int n_in,
                              void* d_out, int out_size)
{
    const float* x  = (const float*)d_in[0];
    const float* Wg = (const float*)d_in[1];
    const float* W1 = (const float*)d_in[2];
    const float* b1 = (const float*)d_in[3];
    const float* W2 = (const float*)d_in[4];
    const float* b2 = (const float*)d_in[5];
    float* out = (float*)d_out;

    void *pbuf, *ph, *peo;
    cudaGetSymbolAddress(&pbuf, g_buf);
    cudaGetSymbolAddress(&ph,   g_h);
    cudaGetSymbolAddress(&peo,  g_eo);

    cudaFuncSetAttribute(moe_mma_gemm<1>,
                         cudaFuncAttributeMaxDynamicSharedMemorySize, GEMM_SMEM);
    cudaFuncSetAttribute(moe_mma_gemm<0>,
                         cudaFuncAttributeMaxDynamicSharedMemorySize, GEMM_SMEM);
    cudaFuncSetAttribute(scan_loss_kernel,
                         cudaFuncAttributeMaxDynamicSharedMemorySize, SCAN_SMEM);

    float* loss_ptr = (out_size > S_TOK * DMODEL) ? (out + (size_t)S_TOK * DMODEL)
                                                  : nullptr;

    gating_kernel<<<GATE_BLOCKS, 256>>>(x, Wg);
    scan_loss_kernel<<<1, 256, SCAN_SMEM>>>(loss_ptr);

    zero_buf_kernel<<<(NEXP * CAP * DMODEL / 4) / 256, 256>>>();
    dispatch_kernel<<<S_TOK, 256>>>(x);

    // GEMM1: h = gelu(buf @ W1 + b1), tf32-rounded output
    moe_mma_gemm<1><<<dim3(CAP / BM, HFFN / BN, NEXP), 256, GEMM_SMEM>>>(
        (const float*)pbuf, W1, b1, (float*)ph, CAP, HFFN, DMODEL);
    // GEMM2: eo = h @ W2 + b2
    moe_mma_gemm<0><<<dim3(CAP / BM, DMODEL / BN, NEXP), 256, GEMM_SMEM>>>(
        (const float*)ph, W2, b2, (float*)peo, CAP, DMODEL, HFFN);

    combine_kernel<<<S_TOK, 256>>>(out);
}

// round 5
// speedup vs baseline: 4.8864x; 1.4134x over previous
#include <cuda_runtime.h>
#include <cuda_fp16.h>
#include <math.h>
#include <stdint.h>

// ---------------- problem constants ----------------
#define S_TOK   16384          // B*N
#define DMODEL  1024
#define NEXP    8
#define HFFN    4096
#define CAP     2560           // int(S*1.25/E)
#define GATE_BLOCKS (S_TOK/8)

// ---------------- device scratch (allocation-free rule) ----------------
__device__ __half g_bufh[NEXP * CAP * DMODEL];            // 42 MB  dispatch fp16
__device__ __half g_hh  [(size_t)NEXP * CAP * HFFN];      // 168 MB hidden fp16
__device__ float  g_eo  [NEXP * CAP * DMODEL];            // 80 MB  expert out fp32
__device__ __half g_w1h [(size_t)NEXP * HFFN * DMODEL];   // 67 MB  W1^T [E][H][D]
__device__ __half g_w2h [(size_t)NEXP * DMODEL * HFFN];   // 67 MB  W2^T [E][D][H]
__device__ float g_gate1[S_TOK];
__device__ float g_gate2[S_TOK];
__device__ int   g_idx1[S_TOK];
__device__ int   g_idx2[S_TOK];
__device__ int   g_pos1[S_TOK];
__device__ int   g_pos2[S_TOK];
__device__ float g_partial[GATE_BLOCKS * NEXP];
__device__ int   g_cnt1[NEXP];

// ---------------- helpers ----------------
__device__ __forceinline__ float gelu_tanh(float x) {
    float x3 = x * x * x;
    return 0.5f * x * (1.0f + tanhf(0.7978845608028654f * (x + 0.044715f * x3)));
}
__device__ __forceinline__ uint32_t smem_u32(const void* p) {
    uint32_t a;
    asm("{ .reg .u64 t; cvta.to.shared.u64 t, %1; cvt.u32.u64 %0, t; }" : "=r"(a) : "l"(p));
    return a;
}
__device__ __forceinline__ void cp_async16(uint32_t dst, const void* src) {
    asm volatile("cp.async.cg.shared.global [%0], [%1], 16;" :: "r"(dst), "l"(src));
}
__device__ __forceinline__ void cp_commit() {
    asm volatile("cp.async.commit_group;");
}
template<int N>
__device__ __forceinline__ void cp_wait() {
    asm volatile("cp.async.wait_group %0;" :: "n"(N));
}
__device__ __forceinline__ void mma_f16(float& c0, float& c1, float& c2, float& c3,
                                        uint32_t a0, uint32_t a1, uint32_t a2, uint32_t a3,
                                        uint32_t b0, uint32_t b1) {
    asm volatile(
        "mma.sync.aligned.m16n8k16.row.col.f32.f16.f16.f32 "
        "{%0,%1,%2,%3}, {%4,%5,%6,%7}, {%8,%9}, {%0,%1,%2,%3};"
        : "+f"(c0), "+f"(c1), "+f"(c2), "+f"(c3)
        : "r"(a0), "r"(a1), "r"(a2), "r"(a3), "r"(b0), "r"(b1));
}

// ---------------- 1) gating ----------------
__global__ void __launch_bounds__(256) gating_kernel(
    const float* __restrict__ x, const float* __restrict__ Wg)
{
    __shared__ float sWgT[NEXP * DMODEL];
    __shared__ float sP[8][NEXP];
    for (int i = threadIdx.x; i < NEXP * DMODEL; i += blockDim.x) {
        int d = i & (DMODEL - 1);
        int e = i >> 10;
        sWgT[i] = Wg[d * NEXP + e];
    }
    __syncthreads();

    int warp = threadIdx.x >> 5;
    int lane = threadIdx.x & 31;
    int tok  = blockIdx.x * 8 + warp;

    const float* xr = x + (size_t)tok * DMODEL;
    float acc[NEXP];
    #pragma unroll
    for (int e = 0; e < NEXP; e++) acc[e] = 0.f;

    #pragma unroll 4
    for (int t = 0; t < 32; t++) {
        int d = t * 32 + lane;
        float xv = xr[d];
        #pragma unroll
        for (int e = 0; e < NEXP; e++)
            acc[e] += xv * sWgT[e * DMODEL + d];
    }
    #pragma unroll
    for (int e = 0; e < NEXP; e++) {
        #pragma unroll
        for (int off = 16; off; off >>= 1)
            acc[e] += __shfl_xor_sync(0xffffffffu, acc[e], off);
    }

    if (lane == 0) {
        float mx = acc[0];
        #pragma unroll
        for (int e = 1; e < NEXP; e++) mx = fmaxf(mx, acc[e]);
        float p[NEXP], sum = 0.f;
        #pragma unroll
        for (int e = 0; e < NEXP; e++) { p[e] = expf(acc[e] - mx); sum += p[e]; }
        float inv = 1.0f / sum;
        #pragma unroll
        for (int e = 0; e < NEXP; e++) p[e] *= inv;

        int i1 = 0; float v1 = p[0];
        #pragma unroll
        for (int e = 1; e < NEXP; e++) if (p[e] > v1) { v1 = p[e]; i1 = e; }
        int i2 = (i1 == 0) ? 1 : 0; float v2 = p[i2];
        #pragma unroll
        for (int e = 0; e < NEXP; e++)
            if (e != i1 && p[e] > v2) { v2 = p[e]; i2 = e; }

        g_idx1[tok] = i1;  g_idx2[tok] = i2;
        g_gate1[tok] = v1; g_gate2[tok] = v2;
        #pragma unroll
        for (int e = 0; e < NEXP; e++) sP[warp][e] = p[e];
    }
    __syncthreads();
    if (threadIdx.x < NEXP) {
        float s = 0.f;
        #pragma unroll
        for (int w = 0; w < 8; w++) s += sP[w][threadIdx.x];
        g_partial[blockIdx.x * NEXP + threadIdx.x] = s;
    }
}

// ---------------- 2) capacity scan + loss (smem-staged, warp-parallel) ----
#define SCAN_SMEM (2 * S_TOK * 4)   // 128 KB

__global__ void __launch_bounds__(256) scan_loss_kernel(float* loss_out)
{
    extern __shared__ int sidx[];
    int* s1 = sidx;
    int* s2 = sidx + S_TOK;

    {
        const int4* p1 = (const int4*)g_idx1;
        const int4* p2 = (const int4*)g_idx2;
        int4* q1 = (int4*)s1;
        int4* q2 = (int4*)s2;
        #pragma unroll
        for (int i = 0; i < S_TOK / 4 / 256; i++) {
            q1[threadIdx.x + i * 256] = p1[threadIdx.x + i * 256];
            q2[threadIdx.x + i * 256] = p2[threadIdx.x + i * 256];
        }
    }
    __syncthreads();

    int warp = threadIdx.x >> 5;
    int lane = threadIdx.x & 31;
    int e = warp;
    unsigned lmask = (1u << lane) - 1u;

    int cnt = 0;
    #pragma unroll 4
    for (int base = 0; base < S_TOK; base += 32) {
        int id = s1[base + lane];
        unsigned m = __ballot_sync(0xffffffffu, id == e);
        if (id == e)
            g_pos1[base + lane] = cnt + __popc(m & lmask);
        cnt += __popc(m);
    }
    if (lane == 0) g_cnt1[e] = cnt;
    int used1 = min(cnt, CAP);

    int cnt2 = 0;
    #pragma unroll 4
    for (int base = 0; base < S_TOK; base += 32) {
        int id = s2[base + lane];
        unsigned m = __ballot_sync(0xffffffffu, id == e);
        if (id == e)
            g_pos2[base + lane] = used1 + cnt2 + __popc(m & lmask);
        cnt2 += __popc(m);
    }

    float s = 0.f;
    #pragma unroll 4
    for (int b = lane; b < GATE_BLOCKS; b += 32)
        s += g_partial[b * NEXP + e];
    #pragma unroll
    for (int off = 16; off; off >>= 1)
        s += __shfl_xor_sync(0xffffffffu, s, off);

    __shared__ float sms[NEXP];
    if (lane == 0) sms[e] = s;
    __syncthreads();
    if (threadIdx.x == 0 && loss_out != nullptr) {
        const float invS = 1.0f / (float)S_TOK;
        float tot = 0.f;
        #pragma unroll
        for (int e2 = 0; e2 < NEXP; e2++)
            tot += (sms[e2] * invS) * ((float)g_cnt1[e2] * invS);
        *loss_out = 0.01f * (tot * 0.125f) * 64.0f;
    }
}

// ---------------- 3) zero dispatch buffers (fp16) ----------------
__global__ void zero_buf_kernel()
{
    size_t i = (size_t)blockIdx.x * blockDim.x + threadIdx.x;
    ((float4*)g_bufh)[i] = make_float4(0.f, 0.f, 0.f, 0.f);
}

// ---------------- 4) dispatch scatter (fp32 -> fp16 RN) ----------------
__global__ void __launch_bounds__(256) dispatch_kernel(const float* __restrict__ x)
{
    int tok = blockIdx.x;
    int i1 = g_idx1[tok], i2 = g_idx2[tok];
    int p1 = g_pos1[tok], p2 = g_pos2[tok];
    bool k1 = p1 < CAP, k2 = p2 < CAP;

    const float4* xr = (const float4*)(x + (size_t)tok * DMODEL);
    uint2* b1p = (uint2*)(g_bufh + ((size_t)i1 * CAP + p1) * DMODEL);
    uint2* b2p = (uint2*)(g_bufh + ((size_t)i2 * CAP + p2) * DMODEL);

    int j = threadIdx.x;
    float4 v = xr[j];
    __half2 h0 = __floats2half2_rn(v.x, v.y);
    __half2 h1 = __floats2half2_rn(v.z, v.w);
    uint2 pk = make_uint2(*(uint32_t*)&h0, *(uint32_t*)&h1);
    if (k1) b1p[j] = pk;
    if (k2) b2p[j] = pk;
}

// ---------------- 5) weight transpose fp32 -> fp16 ----------------
// in [E][R][C] fp32 -> out [E][C][R] fp16
__global__ void __launch_bounds__(256) transpose_h_kernel(
    const float* __restrict__ in, __half* __restrict__ out, int R, int C)
{
    __shared__ float tile[32][33];
    int e = blockIdx.z;
    const float* ine = in + (size_t)e * R * C;
    __half* oute = out + (size_t)e * R * C;
    int c0 = blockIdx.x * 32, r0 = blockIdx.y * 32;
    int tx = threadIdx.x, ty = threadIdx.y;
    #pragma unroll
    for (int i = 0; i < 32; i += 8)
        tile[ty + i][tx] = ine[(size_t)(r0 + ty + i) * C + c0 + tx];
    __syncthreads();
    #pragma unroll
    for (int i = 0; i < 32; i += 8)
        oute[(size_t)(c0 + ty + i) * R + r0 + tx] = __float2half_rn(tile[tx][ty + i]);
}

// ---------------- 6) fp16 mma.sync grouped GEMM ----------------
// C[e][m][n] = sum_k A[e][m][k] * Bt[e][n][k]  (+bias, opt gelu)
// A [M][K] fp16 row-major, Bt [N][K] fp16 (pre-transposed weights).
// Block 128x256, BK=32 halfs, 8 warps (64x64 each), 4-stage cp.async.
#define BM 128
#define BN 256
#define BK 32
#define ROWP 40                      // padded row length in halfs (80B = 20 banks)
#define A_STG (BM * ROWP)            // 5120 halfs
#define B_STG (BN * ROWP)            // 10240 halfs
#define STG_H (A_STG + B_STG)        // 15360 halfs = 30720 B
#define NSTG 4
#define GEMM_SMEM (NSTG * STG_H * 2) // 122880 bytes

template<typename OutT, int DO_GELU>
__global__ void __launch_bounds__(256, 1) moe_mma_gemm(
    const __half* __restrict__ A, const __half* __restrict__ Bt,
    const float* __restrict__ bias, OutT* __restrict__ C,
    int M, int N, int K)
{
    extern __shared__ __half smemh[];
    const uint32_t sb = smem_u32(smemh);

    const int tid = threadIdx.x;
    const int lane = tid & 31;
    const int wid = tid >> 5;
    const int wm = wid & 1;          // warp m half
    const int wn = wid >> 1;         // warp n quarter
    const int g = lane >> 2;
    const int t4 = lane & 3;

    const int e = blockIdx.z;
    const int mbase = blockIdx.x * BM;
    const int nbase = blockIdx.y * BN;
    const __half* Ae = A + (size_t)e * M * K;
    const __half* Be = Bt + (size_t)e * N * K;

    // cp.async mapping: 16B chunks, 4 chunks per 32-half row
    const int ar0 = tid >> 1;            // A row (thread handles rows ar0, +128? no:)
    const int ac  = tid & 1;             // -> chunks (ar0, ac*2) and (ar0, ac*2+1)
    const int br0 = tid >> 1;            // B rows br0 and br0+128
    const int KT = K / BK;

    auto load_stage = [&](int s, int kt) {
        uint32_t abase = sb + (uint32_t)(s * STG_H) * 2;
        uint32_t bbase = abase + A_STG * 2;
        const __half* Asrc = Ae + (size_t)mbase * K + (size_t)kt * BK;
        const __half* Bsrc = Be + (size_t)nbase * K + (size_t)kt * BK;
        // A: 128 rows x 4 chunks = 512; 256 threads x 2
        cp_async16(abase + (uint32_t)(ar0 * ROWP + (ac * 2 + 0) * 8) * 2,
                   Asrc + (size_t)ar0 * K + (ac * 2 + 0) * 8);
        cp_async16(abase + (uint32_t)(ar0 * ROWP + (ac * 2 + 1) * 8) * 2,
                   Asrc + (size_t)ar0 * K + (ac * 2 + 1) * 8);
        // B: 256 rows x 4 chunks = 1024; 256 threads x 4
        #pragma unroll
        for (int h = 0; h < 2; h++) {
            int r = br0 + h * 128;
            cp_async16(bbase + (uint32_t)(r * ROWP + (ac * 2 + 0) * 8) * 2,
                       Bsrc + (size_t)r * K + (ac * 2 + 0) * 8);
            cp_async16(bbase + (uint32_t)(r * ROWP + (ac * 2 + 1) * 8) * 2,
                       Bsrc + (size_t)r * K + (ac * 2 + 1) * 8);
        }
    };

    float acc[4][8][4];
    #pragma unroll
    for (int i = 0; i < 4; i++)
        #pragma unroll
        for (int j = 0; j < 8; j++)
            #pragma unroll
            for (int r = 0; r < 4; r++) acc[i][j][r] = 0.f;

    load_stage(0, 0); cp_commit();
    load_stage(1, 1); cp_commit();
    load_stage(2, 2); cp_commit();

    for (int kt = 0; kt < KT; kt++) {
        cp_wait<2>();
        __syncthreads();
        if (kt + 3 < KT) load_stage((kt + 3) & 3, kt + 3);
        cp_commit();

        const __half* As = smemh + (size_t)(kt & 3) * STG_H;
        const __half* Bs = As + A_STG;

        #pragma unroll
        for (int kc = 0; kc < 2; kc++) {
            uint32_t a[4][4], b[8][2];
            #pragma unroll
            for (int i = 0; i < 4; i++) {
                const __half* ap = As + (wm * 64 + i * 16 + g) * ROWP + kc * 16 + 2 * t4;
                a[i][0] = *(const uint32_t*)(ap);
                a[i][1] = *(const uint32_t*)(ap + 8 * ROWP);
                a[i][2] = *(const uint32_t*)(ap + 8);
                a[i][3] = *(const uint32_t*)(ap + 8 * ROWP + 8);
            }
            #pragma unroll
            for (int j = 0; j < 8; j++) {
                const __half* bp = Bs + (wn * 64 + j * 8 + g) * ROWP + kc * 16 + 2 * t4;
                b[j][0] = *(const uint32_t*)(bp);
                b[j][1] = *(const uint32_t*)(bp + 8);
            }
            #pragma unroll
            for (int i = 0; i < 4; i++)
                #pragma unroll
                for (int j = 0; j < 8; j++)
                    mma_f16(acc[i][j][0], acc[i][j][1], acc[i][j][2], acc[i][j][3],
                            a[i][0], a[i][1], a[i][2], a[i][3],
                            b[j][0], b[j][1]);
        }
        __syncthreads();
    }

    // ---- epilogue ----
    const float* brow = bias + (size_t)e * N + nbase + wn * 64;
    OutT* Cr = C + ((size_t)e * M + mbase + wm * 64) * N + nbase + wn * 64;
    #pragma unroll
    for (int i = 0; i < 4; i++) {
        #pragma unroll
        for (int j = 0; j < 8; j++) {
            int col = j * 8 + 2 * t4;
            float b0 = brow[col], b1 = brow[col + 1];
            float v0 = acc[i][j][0] + b0;
            float v1 = acc[i][j][1] + b1;
            float v2 = acc[i][j][2] + b0;
            float v3 = acc[i][j][3] + b1;
            if (DO_GELU) {
                v0 = gelu_tanh(v0); v1 = gelu_tanh(v1);
                v2 = gelu_tanh(v2); v3 = gelu_tanh(v3);
            }
            OutT* r0 = Cr + (size_t)(i * 16 + g) * N + col;
            OutT* r1 = Cr + (size_t)(i * 16 + g + 8) * N + col;
            if (sizeof(OutT) == 2) {
                __half2 h0 = __floats2half2_rn(v0, v1);
                __half2 h1 = __floats2half2_rn(v2, v3);
                *(__half2*)r0 = h0;
                *(__half2*)r1 = h1;
            } else {
                *(float2*)r0 = make_float2(v0, v1);
                *(float2*)r1 = make_float2(v2, v3);
            }
        }
    }
}

// ---------------- 7) combine ----------------
__global__ void __launch_bounds__(256) combine_kernel(float* __restrict__ out)
{
    int tok = blockIdx.x;
    int i1 = g_idx1[tok], i2 = g_idx2[tok];
    int p1 = g_pos1[tok], p2 = g_pos2[tok];
    float ga = g_gate1[tok], gb = g_gate2[tok];
    bool k1 = p1 < CAP, k2 = p2 < CAP;
    float a1 = k1 ? ga : 0.f;
    float a2 = k2 ? gb : 0.f;
    float denom = a1 + a2 + 1e-9f;
    float w1 = a1 / denom, w2 = a2 / denom;
    int q1 = k1 ? p1 : 0, q2 = k2 ? p2 : 0;

    const float4* e1 = (const float4*)(g_eo + ((size_t)i1 * CAP + q1) * DMODEL);
    const float4* e2 = (const float4*)(g_eo + ((size_t)i2 * CAP + q2) * DMODEL);
    float4* o = (float4*)(out + (size_t)tok * DMODEL);

    int j = threadIdx.x;
    float4 v1 = e1[j], v2 = e2[j];
    float4 r;
    r.x = w1 * v1.x + w2 * v2.x;
    r.y = w1 * v1.y + w2 * v2.y;
    r.z = w1 * v1.z + w2 * v2.z;
    r.w = w1 * v1.w + w2 * v2.w;
    o[j] = r;
}

// ---------------- launch ----------------
extern "C" void kernel_launch(void* const* d_in, const int* in_sizes, int n_in,
                              void* d_out, int out_size)
{
    const float* x  = (const float*)d_in[0];
    const float* Wg = (const float*)d_in[1];
    const float* W1 = (const float*)d_in[2];
    const float* b1 = (const float*)d_in[3];
    const float* W2 = (const float*)d_in[4];
    const float* b2 = (const float*)d_in[5];
    float* out = (float*)d_out;

    void *pbuf, *ph, *peo, *pw1, *pw2;
    cudaGetSymbolAddress(&pbuf, g_bufh);
    cudaGetSymbolAddress(&ph,   g_hh);
    cudaGetSymbolAddress(&peo,  g_eo);
    cudaGetSymbolAddress(&pw1,  g_w1h);
    cudaGetSymbolAddress(&pw2,  g_w2h);

    cudaFuncSetAttribute((const void*)moe_mma_gemm<__half, 1>,
                         cudaFuncAttributeMaxDynamicSharedMemorySize, GEMM_SMEM);
    cudaFuncSetAttribute((const void*)moe_mma_gemm<float, 0>,
                         cudaFuncAttributeMaxDynamicSharedMemorySize, GEMM_SMEM);
    cudaFuncSetAttribute((const void*)scan_loss_kernel,
                         cudaFuncAttributeMaxDynamicSharedMemorySize, SCAN_SMEM);

    float* loss_ptr = (out_size > S_TOK * DMODEL) ? (out + (size_t)S_TOK * DMODEL)
                                                  : nullptr;

    // weight transposes fp32 -> fp16 (W^T layouts for row.col mma)
    transpose_h_kernel<<<dim3(HFFN / 32, DMODEL / 32, NEXP), dim3(32, 8)>>>(
        W1, (__half*)pw1, DMODEL, HFFN);
    transpose_h_kernel<<<dim3(DMODEL / 32, HFFN / 32, NEXP), dim3(32, 8)>>>(
        W2, (__half*)pw2, HFFN, DMODEL);

    gating_kernel<<<GATE_BLOCKS, 256>>>(x, Wg);
    scan_loss_kernel<<<1, 256, SCAN_SMEM>>>(loss_ptr);

    // zero fp16 dispatch buffer: 42MB / 16B / 256
    zero_buf_kernel<<<(int)(((size_t)NEXP * CAP * DMODEL * 2 / 16) / 256), 256>>>();
    dispatch_kernel<<<S_TOK, 256>>>(x);

    // GEMM1: h = gelu(buf @ W1 + b1) -> fp16
    moe_mma_gemm<__half, 1><<<dim3(CAP / BM, HFFN / BN, NEXP), 256, GEMM_SMEM>>>(
        (const __half*)pbuf, (const __half*)pw1, b1, (__half*)ph,
        CAP, HFFN, DMODEL);
    // GEMM2: eo = h @ W2 + b2 -> fp32
    moe_mma_gemm<float, 0><<<dim3(CAP / BM, DMODEL / BN, NEXP), 256, GEMM_SMEM>>>(
        (const __half*)ph, (const __half*)pw2, b2, (float*)peo,
        CAP, DMODEL, HFFN);

    combine_kernel<<<S_TOK, 256>>>(out);
}

// round 6
// speedup vs baseline: 5.4460x; 1.1145x over previous
#include <cuda_runtime.h>
#include <cuda_fp16.h>
#include <math.h>
#include <stdint.h>

// ---------------- problem constants ----------------
#define S_TOK   16384          // B*N
#define DMODEL  1024
#define NEXP    8
#define HFFN    4096
#define CAP     2560           // int(S*1.25/E)
#define GATE_BLOCKS (S_TOK/8)

// ---------------- device scratch (allocation-free rule) ----------------
__device__ __half g_bufh[NEXP * CAP * DMODEL];            // 42 MB  dispatch fp16
__device__ __half g_hh  [(size_t)NEXP * CAP * HFFN];      // 168 MB hidden fp16
__device__ float  g_eo  [NEXP * CAP * DMODEL];            // 80 MB  expert out fp32
__device__ __half g_w1h [(size_t)NEXP * HFFN * DMODEL];   // 67 MB  W1^T [E][H][D]
__device__ __half g_w2h [(size_t)NEXP * DMODEL * HFFN];   // 67 MB  W2^T [E][D][H]
__device__ float g_gate1[S_TOK];
__device__ float g_gate2[S_TOK];
__device__ int   g_idx1[S_TOK];
__device__ int   g_idx2[S_TOK];
__device__ int   g_pos1[S_TOK];
__device__ int   g_pos2[S_TOK];
__device__ float g_partial[GATE_BLOCKS * NEXP];
__device__ int   g_cnt1[NEXP];

// ---------------- helpers ----------------
__device__ __forceinline__ float gelu_tanh(float x) {
    float x3 = x * x * x;
    return 0.5f * x * (1.0f + tanhf(0.7978845608028654f * (x + 0.044715f * x3)));
}
__device__ __forceinline__ uint32_t smem_u32(const void* p) {
    uint32_t a;
    asm("{ .reg .u64 t; cvta.to.shared.u64 t, %1; cvt.u32.u64 %0, t; }" : "=r"(a) : "l"(p));
    return a;
}
__device__ __forceinline__ void cp_async16(uint32_t dst, const void* src) {
    asm volatile("cp.async.cg.shared.global [%0], [%1], 16;" :: "r"(dst), "l"(src));
}
__device__ __forceinline__ void cp_commit() {
    asm volatile("cp.async.commit_group;");
}
template<int N>
__device__ __forceinline__ void cp_wait() {
    asm volatile("cp.async.wait_group %0;" :: "n"(N));
}
__device__ __forceinline__ void mma_f16(float& c0, float& c1, float& c2, float& c3,
                                        uint32_t a0, uint32_t a1, uint32_t a2, uint32_t a3,
                                        uint32_t b0, uint32_t b1) {
    asm volatile(
        "mma.sync.aligned.m16n8k16.row.col.f32.f16.f16.f32 "
        "{%0,%1,%2,%3}, {%4,%5,%6,%7}, {%8,%9}, {%0,%1,%2,%3};"
        : "+f"(c0), "+f"(c1), "+f"(c2), "+f"(c3)
        : "r"(a0), "r"(a1), "r"(a2), "r"(a3), "r"(b0), "r"(b1));
}
__device__ __forceinline__ void ldsm_x4(uint32_t& r0, uint32_t& r1,
                                        uint32_t& r2, uint32_t& r3, uint32_t addr) {
    asm volatile("ldmatrix.sync.aligned.m8n8.x4.shared.b16 {%0,%1,%2,%3}, [%4];"
                 : "=r"(r0), "=r"(r1), "=r"(r2), "=r"(r3) : "r"(addr));
}

// ---------------- 1) gating ----------------
__global__ void __launch_bounds__(256) gating_kernel(
    const float* __restrict__ x, const float* __restrict__ Wg)
{
    __shared__ float sWgT[NEXP * DMODEL];
    __shared__ float sP[8][NEXP];
    for (int i = threadIdx.x; i < NEXP * DMODEL; i += blockDim.x) {
        int d = i & (DMODEL - 1);
        int e = i >> 10;
        sWgT[i] = Wg[d * NEXP + e];
    }
    __syncthreads();

    int warp = threadIdx.x >> 5;
    int lane = threadIdx.x & 31;
    int tok  = blockIdx.x * 8 + warp;

    const float* xr = x + (size_t)tok * DMODEL;
    float acc[NEXP];
    #pragma unroll
    for (int e = 0; e < NEXP; e++) acc[e] = 0.f;

    #pragma unroll 4
    for (int t = 0; t < 32; t++) {
        int d = t * 32 + lane;
        float xv = xr[d];
        #pragma unroll
        for (int e = 0; e < NEXP; e++)
            acc[e] += xv * sWgT[e * DMODEL + d];
    }
    #pragma unroll
    for (int e = 0; e < NEXP; e++) {
        #pragma unroll
        for (int off = 16; off; off >>= 1)
            acc[e] += __shfl_xor_sync(0xffffffffu, acc[e], off);
    }

    if (lane == 0) {
        float mx = acc[0];
        #pragma unroll
        for (int e = 1; e < NEXP; e++) mx = fmaxf(mx, acc[e]);
        float p[NEXP], sum = 0.f;
        #pragma unroll
        for (int e = 0; e < NEXP; e++) { p[e] = expf(acc[e] - mx); sum += p[e]; }
        float inv = 1.0f / sum;
        #pragma unroll
        for (int e = 0; e < NEXP; e++) p[e] *= inv;

        int i1 = 0; float v1 = p[0];
        #pragma unroll
        for (int e = 1; e < NEXP; e++) if (p[e] > v1) { v1 = p[e]; i1 = e; }
        int i2 = (i1 == 0) ? 1 : 0; float v2 = p[i2];
        #pragma unroll
        for (int e = 0; e < NEXP; e++)
            if (e != i1 && p[e] > v2) { v2 = p[e]; i2 = e; }

        g_idx1[tok] = i1;  g_idx2[tok] = i2;
        g_gate1[tok] = v1; g_gate2[tok] = v2;
        #pragma unroll
        for (int e = 0; e < NEXP; e++) sP[warp][e] = p[e];
    }
    __syncthreads();
    if (threadIdx.x < NEXP) {
        float s = 0.f;
        #pragma unroll
        for (int w = 0; w < 8; w++) s += sP[w][threadIdx.x];
        g_partial[blockIdx.x * NEXP + threadIdx.x] = s;
    }
}

// ---------------- 2) capacity scan + loss (smem-staged, warp-parallel) ----
#define SCAN_SMEM (2 * S_TOK * 4)   // 128 KB

__global__ void __launch_bounds__(256) scan_loss_kernel(float* loss_out)
{
    extern __shared__ int sidx[];
    int* s1 = sidx;
    int* s2 = sidx + S_TOK;

    {
        const int4* p1 = (const int4*)g_idx1;
        const int4* p2 = (const int4*)g_idx2;
        int4* q1 = (int4*)s1;
        int4* q2 = (int4*)s2;
        #pragma unroll
        for (int i = 0; i < S_TOK / 4 / 256; i++) {
            q1[threadIdx.x + i * 256] = p1[threadIdx.x + i * 256];
            q2[threadIdx.x + i * 256] = p2[threadIdx.x + i * 256];
        }
    }
    __syncthreads();

    int warp = threadIdx.x >> 5;
    int lane = threadIdx.x & 31;
    int e = warp;
    unsigned lmask = (1u << lane) - 1u;

    int cnt = 0;
    #pragma unroll 4
    for (int base = 0; base < S_TOK; base += 32) {
        int id = s1[base + lane];
        unsigned m = __ballot_sync(0xffffffffu, id == e);
        if (id == e)
            g_pos1[base + lane] = cnt + __popc(m & lmask);
        cnt += __popc(m);
    }
    if (lane == 0) g_cnt1[e] = cnt;
    int used1 = min(cnt, CAP);

    int cnt2 = 0;
    #pragma unroll 4
    for (int base = 0; base < S_TOK; base += 32) {
        int id = s2[base + lane];
        unsigned m = __ballot_sync(0xffffffffu, id == e);
        if (id == e)
            g_pos2[base + lane] = used1 + cnt2 + __popc(m & lmask);
        cnt2 += __popc(m);
    }

    float s = 0.f;
    #pragma unroll 4
    for (int b = lane; b < GATE_BLOCKS; b += 32)
        s += g_partial[b * NEXP + e];
    #pragma unroll
    for (int off = 16; off; off >>= 1)
        s += __shfl_xor_sync(0xffffffffu, s, off);

    __shared__ float sms[NEXP];
    if (lane == 0) sms[e] = s;
    __syncthreads();
    if (threadIdx.x == 0 && loss_out != nullptr) {
        const float invS = 1.0f / (float)S_TOK;
        float tot = 0.f;
        #pragma unroll
        for (int e2 = 0; e2 < NEXP; e2++)
            tot += (sms[e2] * invS) * ((float)g_cnt1[e2] * invS);
        *loss_out = 0.01f * (tot * 0.125f) * 64.0f;
    }
}

// ---------------- 3) zero dispatch buffers (fp16) ----------------
__global__ void zero_buf_kernel()
{
    size_t i = (size_t)blockIdx.x * blockDim.x + threadIdx.x;
    ((float4*)g_bufh)[i] = make_float4(0.f, 0.f, 0.f, 0.f);
}

// ---------------- 4) dispatch scatter (fp32 -> fp16 RN) ----------------
__global__ void __launch_bounds__(256) dispatch_kernel(const float* __restrict__ x)
{
    int tok = blockIdx.x;
    int i1 = g_idx1[tok], i2 = g_idx2[tok];
    int p1 = g_pos1[tok], p2 = g_pos2[tok];
    bool k1 = p1 < CAP, k2 = p2 < CAP;

    const float4* xr = (const float4*)(x + (size_t)tok * DMODEL);
    uint2* b1p = (uint2*)(g_bufh + ((size_t)i1 * CAP + p1) * DMODEL);
    uint2* b2p = (uint2*)(g_bufh + ((size_t)i2 * CAP + p2) * DMODEL);

    int j = threadIdx.x;
    float4 v = xr[j];
    __half2 h0 = __floats2half2_rn(v.x, v.y);
    __half2 h1 = __floats2half2_rn(v.z, v.w);
    uint2 pk = make_uint2(*(uint32_t*)&h0, *(uint32_t*)&h1);
    if (k1) b1p[j] = pk;
    if (k2) b2p[j] = pk;
}

// ---------------- 5) weight transpose fp32 -> fp16 ----------------
// in [E][R][C] fp32 -> out [E][C][R] fp16
__global__ void __launch_bounds__(256) transpose_h_kernel(
    const float* __restrict__ in, __half* __restrict__ out, int R, int C)
{
    __shared__ float tile[32][33];
    int e = blockIdx.z;
    const float* ine = in + (size_t)e * R * C;
    __half* oute = out + (size_t)e * R * C;
    int c0 = blockIdx.x * 32, r0 = blockIdx.y * 32;
    int tx = threadIdx.x, ty = threadIdx.y;
    #pragma unroll
    for (int i = 0; i < 32; i += 8)
        tile[ty + i][tx] = ine[(size_t)(r0 + ty + i) * C + c0 + tx];
    __syncthreads();
    #pragma unroll
    for (int i = 0; i < 32; i += 8)
        oute[(size_t)(c0 + ty + i) * R + r0 + tx] = __float2half_rn(tile[tx][ty + i]);
}

// ---------------- 6) fp16 mma.sync grouped GEMM (ldmatrix fragments) ------
// C[e][m][n] = sum_k A[e][m][k] * Bt[e][n][k]  (+bias, opt gelu)
// Block 128x256, BK=32 halfs, 8 warps (64x64 each), 4-stage cp.async.
#define BM 128
#define BN 256
#define BK 32
#define ROWP 40                      // padded row (halfs); 80B stride -> LDSM conflict-free
#define A_STG (BM * ROWP)            // 5120 halfs
#define B_STG (BN * ROWP)            // 10240 halfs
#define STG_H (A_STG + B_STG)        // 15360 halfs = 30720 B
#define NSTG 4
#define GEMM_SMEM (NSTG * STG_H * 2) // 122880 bytes

template<typename OutT, int DO_GELU>
__global__ void __launch_bounds__(256, 1) moe_mma_gemm(
    const __half* __restrict__ A, const __half* __restrict__ Bt,
    const float* __restrict__ bias, OutT* __restrict__ C,
    int M, int N, int K)
{
    extern __shared__ __half smemh[];
    const uint32_t sb = smem_u32(smemh);

    const int tid = threadIdx.x;
    const int lane = tid & 31;
    const int wid = tid >> 5;
    const int wm = wid & 1;          // warp m half
    const int wn = wid >> 1;         // warp n quarter
    const int g = lane >> 2;
    const int t4 = lane & 3;

    const int e = blockIdx.z;
    const int mbase = blockIdx.x * BM;
    const int nbase = blockIdx.y * BN;
    const __half* Ae = A + (size_t)e * M * K;
    const __half* Be = Bt + (size_t)e * N * K;

    // cp.async mapping
    const int ar0 = tid >> 1;
    const int ac  = tid & 1;
    const int br0 = tid >> 1;
    const int KT = K / BK;

    // ldmatrix per-lane smem byte offsets (within a stage)
    // A: row = wm*64 + (lane&7) + ((lane&8)?8:0) [+ i*16], col = ((lane&16)?8:0) [+ kc*16]
    const uint32_t a_off =
        (uint32_t)((wm * 64 + (lane & 7) + ((lane >> 3) & 1) * 8) * ROWP
                   + ((lane >> 4) & 1) * 8) * 2;
    // B: row = wn*64 + (lane&7) + ((lane&16)?8:0) [+ jp*16], col = ((lane&8)?8:0) [+ kc*16]
    const uint32_t b_off = (uint32_t)(A_STG
                   + (wn * 64 + (lane & 7) + ((lane >> 4) & 1) * 8) * ROWP
                   + ((lane >> 3) & 1) * 8) * 2;

    auto load_stage = [&](int s, int kt) {
        uint32_t abase = sb + (uint32_t)(s * STG_H) * 2;
        uint32_t bbase = abase + A_STG * 2;
        const __half* Asrc = Ae + (size_t)mbase * K + (size_t)kt * BK;
        const __half* Bsrc = Be + (size_t)nbase * K + (size_t)kt * BK;
        cp_async16(abase + (uint32_t)(ar0 * ROWP + (ac * 2 + 0) * 8) * 2,
                   Asrc + (size_t)ar0 * K + (ac * 2 + 0) * 8);
        cp_async16(abase + (uint32_t)(ar0 * ROWP + (ac * 2 + 1) * 8) * 2,
                   Asrc + (size_t)ar0 * K + (ac * 2 + 1) * 8);
        #pragma unroll
        for (int h = 0; h < 2; h++) {
            int r = br0 + h * 128;
            cp_async16(bbase + (uint32_t)(r * ROWP + (ac * 2 + 0) * 8) * 2,
                       Bsrc + (size_t)r * K + (ac * 2 + 0) * 8);
            cp_async16(bbase + (uint32_t)(r * ROWP + (ac * 2 + 1) * 8) * 2,
                       Bsrc + (size_t)r * K + (ac * 2 + 1) * 8);
        }
    };

    float acc[4][8][4];
    #pragma unroll
    for (int i = 0; i < 4; i++)
        #pragma unroll
        for (int j = 0; j < 8; j++)
            #pragma unroll
            for (int r = 0; r < 4; r++) acc[i][j][r] = 0.f;

    load_stage(0, 0); cp_commit();
    load_stage(1, 1); cp_commit();
    load_stage(2, 2); cp_commit();

    for (int kt = 0; kt < KT; kt++) {
        cp_wait<2>();
        __syncthreads();
        if (kt + 3 < KT) load_stage((kt + 3) & 3, kt + 3);
        cp_commit();

        uint32_t stg = sb + (uint32_t)((kt & 3) * STG_H) * 2;
        uint32_t a_base = stg + a_off;
        uint32_t b_base = stg + b_off;

        #pragma unroll
        for (int kc = 0; kc < 2; kc++) {
            uint32_t a[4][4], b[8][2];
            #pragma unroll
            for (int i = 0; i < 4; i++)
                ldsm_x4(a[i][0], a[i][1], a[i][2], a[i][3],
                        a_base + (uint32_t)(i * 16 * ROWP + kc * 16) * 2);
            #pragma unroll
            for (int jp = 0; jp < 4; jp++)
                ldsm_x4(b[2 * jp][0], b[2 * jp][1], b[2 * jp + 1][0], b[2 * jp + 1][1],
                        b_base + (uint32_t)(jp * 16 * ROWP + kc * 16) * 2);
            #pragma unroll
            for (int i = 0; i < 4; i++)
                #pragma unroll
                for (int j = 0; j < 8; j++)
                    mma_f16(acc[i][j][0], acc[i][j][1], acc[i][j][2], acc[i][j][3],
                            a[i][0], a[i][1], a[i][2], a[i][3],
                            b[j][0], b[j][1]);
        }
        __syncthreads();
    }

    // ---- epilogue ----
    const float* brow = bias + (size_t)e * N + nbase + wn * 64;
    OutT* Cr = C + ((size_t)e * M + mbase + wm * 64) * N + nbase + wn * 64;
    #pragma unroll
    for (int i = 0; i < 4; i++) {
        #pragma unroll
        for (int j = 0; j < 8; j++) {
            int col = j * 8 + 2 * t4;
            float b0 = brow[col], b1 = brow[col + 1];
            float v0 = acc[i][j][0] + b0;
            float v1 = acc[i][j][1] + b1;
            float v2 = acc[i][j][2] + b0;
            float v3 = acc[i][j][3] + b1;
            if (DO_GELU) {
                v0 = gelu_tanh(v0); v1 = gelu_tanh(v1);
                v2 = gelu_tanh(v2); v3 = gelu_tanh(v3);
            }
            OutT* r0 = Cr + (size_t)(i * 16 + g) * N + col;
            OutT* r1 = Cr + (size_t)(i * 16 + g + 8) * N + col;
            if (sizeof(OutT) == 2) {
                __half2 h0 = __floats2half2_rn(v0, v1);
                __half2 h1 = __floats2half2_rn(v2, v3);
                *(__half2*)r0 = h0;
                *(__half2*)r1 = h1;
            } else {
                *(float2*)r0 = make_float2(v0, v1);
                *(float2*)r1 = make_float2(v2, v3);
            }
        }
    }
}

// ---------------- 7) combine ----------------
__global__ void __launch_bounds__(256) combine_kernel(float* __restrict__ out)
{
    int tok = blockIdx.x;
    int i1 = g_idx1[tok], i2 = g_idx2[tok];
    int p1 = g_pos1[tok], p2 = g_pos2[tok];
    float ga = g_gate1[tok], gb = g_gate2[tok];
    bool k1 = p1 < CAP, k2 = p2 < CAP;
    float a1 = k1 ? ga : 0.f;
    float a2 = k2 ? gb : 0.f;
    float denom = a1 + a2 + 1e-9f;
    float w1 = a1 / denom, w2 = a2 / denom;
    int q1 = k1 ? p1 : 0, q2 = k2 ? p2 : 0;

    const float4* e1 = (const float4*)(g_eo + ((size_t)i1 * CAP + q1) * DMODEL);
    const float4* e2 = (const float4*)(g_eo + ((size_t)i2 * CAP + q2) * DMODEL);
    float4* o = (float4*)(out + (size_t)tok * DMODEL);

    int j = threadIdx.x;
    float4 v1 = e1[j], v2 = e2[j];
    float4 r;
    r.x = w1 * v1.x + w2 * v2.x;
    r.y = w1 * v1.y + w2 * v2.y;
    r.z = w1 * v1.z + w2 * v2.z;
    r.w = w1 * v1.w + w2 * v2.w;
    o[j] = r;
}

// ---------------- launch ----------------
extern "C" void kernel_launch(void* const* d_in, const int* in_sizes, int n_in,
                              void* d_out, int out_size)
{
    const float* x  = (const float*)d_in[0];
    const float* Wg = (const float*)d_in[1];
    const float* W1 = (const float*)d_in[2];
    const float* b1 = (const float*)d_in[3];
    const float* W2 = (const float*)d_in[4];
    const float* b2 = (const float*)d_in[5];
    float* out = (float*)d_out;

    void *pbuf, *ph, *peo, *pw1, *pw2;
    cudaGetSymbolAddress(&pbuf, g_bufh);
    cudaGetSymbolAddress(&ph,   g_hh);
    cudaGetSymbolAddress(&peo,  g_eo);
    cudaGetSymbolAddress(&pw1,  g_w1h);
    cudaGetSymbolAddress(&pw2,  g_w2h);

    cudaFuncSetAttribute((const void*)moe_mma_gemm<__half, 1>,
                         cudaFuncAttributeMaxDynamicSharedMemorySize, GEMM_SMEM);
    cudaFuncSetAttribute((const void*)moe_mma_gemm<float, 0>,
                         cudaFuncAttributeMaxDynamicSharedMemorySize, GEMM_SMEM);
    cudaFuncSetAttribute((const void*)scan_loss_kernel,
                         cudaFuncAttributeMaxDynamicSharedMemorySize, SCAN_SMEM);

    float* loss_ptr = (out_size > S_TOK * DMODEL) ? (out + (size_t)S_TOK * DMODEL)
                                                  : nullptr;

    // weight transposes fp32 -> fp16 (W^T layouts for row.col mma)
    transpose_h_kernel<<<dim3(HFFN / 32, DMODEL / 32, NEXP), dim3(32, 8)>>>(
        W1, (__half*)pw1, DMODEL, HFFN);
    transpose_h_kernel<<<dim3(DMODEL / 32, HFFN / 32, NEXP), dim3(32, 8)>>>(
        W2, (__half*)pw2, HFFN, DMODEL);

    gating_kernel<<<GATE_BLOCKS, 256>>>(x, Wg);
    scan_loss_kernel<<<1, 256, SCAN_SMEM>>>(loss_ptr);

    zero_buf_kernel<<<(int)(((size_t)NEXP * CAP * DMODEL * 2 / 16) / 256), 256>>>();
    dispatch_kernel<<<S_TOK, 256>>>(x);

    // GEMM1: h = gelu(buf @ W1 + b1) -> fp16
    moe_mma_gemm<__half, 1><<<dim3(CAP / BM, HFFN / BN, NEXP), 256, GEMM_SMEM>>>(
        (const __half*)pbuf, (const __half*)pw1, b1, (__half*)ph,
        CAP, HFFN, DMODEL);
    // GEMM2: eo = h @ W2 + b2 -> fp32
    moe_mma_gemm<float, 0><<<dim3(CAP / BM, DMODEL / BN, NEXP), 256, GEMM_SMEM>>>(
        (const __half*)ph, (const __half*)pw2, b2, (float*)peo,
        CAP, DMODEL, HFFN);

    combine_kernel<<<S_TOK, 256>>>(out);
}

// round 7
// speedup vs baseline: 5.9535x; 1.0932x over previous
#include <cuda_runtime.h>
#include <cuda_fp16.h>
#include <math.h>
#include <stdint.h>

// ---------------- problem constants ----------------
#define S_TOK   16384          // B*N
#define DMODEL  1024
#define NEXP    8
#define HFFN    4096
#define CAP     2560           // int(S*1.25/E)
#define GATE_BLOCKS (S_TOK/8)

// ---------------- device scratch (allocation-free rule) ----------------
__device__ __half g_bufh[NEXP * CAP * DMODEL];            // 42 MB  dispatch fp16
__device__ __half g_hh  [(size_t)NEXP * CAP * HFFN];      // 168 MB hidden fp16
__device__ float  g_eo  [NEXP * CAP * DMODEL];            // 80 MB  expert out fp32
__device__ __half g_w1h [(size_t)NEXP * HFFN * DMODEL];   // 67 MB  W1^T [E][H][D]
__device__ __half g_w2h [(size_t)NEXP * DMODEL * HFFN];   // 67 MB  W2^T [E][D][H]
__device__ float g_gate1[S_TOK];
__device__ float g_gate2[S_TOK];
__device__ int   g_idx1[S_TOK];
__device__ int   g_idx2[S_TOK];
__device__ int   g_pos1[S_TOK];
__device__ int   g_pos2[S_TOK];
__device__ float g_partial[GATE_BLOCKS * NEXP];
__device__ int   g_cnt1[NEXP];

// ---------------- helpers ----------------
__device__ __forceinline__ float gelu_tanh(float x) {
    float x3 = x * x * x;
    return 0.5f * x * (1.0f + tanhf(0.7978845608028654f * (x + 0.044715f * x3)));
}
__device__ __forceinline__ uint32_t smem_u32(const void* p) {
    uint32_t a;
    asm("{ .reg .u64 t; cvta.to.shared.u64 t, %1; cvt.u32.u64 %0, t; }" : "=r"(a) : "l"(p));
    return a;
}
__device__ __forceinline__ void cp_async16(uint32_t dst, const void* src) {
    asm volatile("cp.async.cg.shared.global [%0], [%1], 16;" :: "r"(dst), "l"(src));
}
__device__ __forceinline__ void cp_commit() {
    asm volatile("cp.async.commit_group;");
}
template<int N>
__device__ __forceinline__ void cp_wait() {
    asm volatile("cp.async.wait_group %0;" :: "n"(N));
}
__device__ __forceinline__ void mma_f16(float& c0, float& c1, float& c2, float& c3,
                                        uint32_t a0, uint32_t a1, uint32_t a2, uint32_t a3,
                                        uint32_t b0, uint32_t b1) {
    asm volatile(
        "mma.sync.aligned.m16n8k16.row.col.f32.f16.f16.f32 "
        "{%0,%1,%2,%3}, {%4,%5,%6,%7}, {%8,%9}, {%0,%1,%2,%3};"
        : "+f"(c0), "+f"(c1), "+f"(c2), "+f"(c3)
        : "r"(a0), "r"(a1), "r"(a2), "r"(a3), "r"(b0), "r"(b1));
}
__device__ __forceinline__ void ldsm_x4(uint32_t& r0, uint32_t& r1,
                                        uint32_t& r2, uint32_t& r3, uint32_t addr) {
    asm volatile("ldmatrix.sync.aligned.m8n8.x4.shared.b16 {%0,%1,%2,%3}, [%4];"
                 : "=r"(r0), "=r"(r1), "=r"(r2), "=r"(r3) : "r"(addr));
}

// ---------------- 1) gating ----------------
__global__ void __launch_bounds__(256) gating_kernel(
    const float* __restrict__ x, const float* __restrict__ Wg)
{
    __shared__ float sWgT[NEXP * DMODEL];
    __shared__ float sP[8][NEXP];
    for (int i = threadIdx.x; i < NEXP * DMODEL; i += blockDim.x) {
        int d = i & (DMODEL - 1);
        int e = i >> 10;
        sWgT[i] = Wg[d * NEXP + e];
    }
    __syncthreads();

    int warp = threadIdx.x >> 5;
    int lane = threadIdx.x & 31;
    int tok  = blockIdx.x * 8 + warp;

    const float* xr = x + (size_t)tok * DMODEL;
    float acc[NEXP];
    #pragma unroll
    for (int e = 0; e < NEXP; e++) acc[e] = 0.f;

    #pragma unroll 4
    for (int t = 0; t < 32; t++) {
        int d = t * 32 + lane;
        float xv = xr[d];
        #pragma unroll
        for (int e = 0; e < NEXP; e++)
            acc[e] += xv * sWgT[e * DMODEL + d];
    }
    #pragma unroll
    for (int e = 0; e < NEXP; e++) {
        #pragma unroll
        for (int off = 16; off; off >>= 1)
            acc[e] += __shfl_xor_sync(0xffffffffu, acc[e], off);
    }

    if (lane == 0) {
        float mx = acc[0];
        #pragma unroll
        for (int e = 1; e < NEXP; e++) mx = fmaxf(mx, acc[e]);
        float p[NEXP], sum = 0.f;
        #pragma unroll
        for (int e = 0; e < NEXP; e++) { p[e] = expf(acc[e] - mx); sum += p[e]; }
        float inv = 1.0f / sum;
        #pragma unroll
        for (int e = 0; e < NEXP; e++) p[e] *= inv;

        int i1 = 0; float v1 = p[0];
        #pragma unroll
        for (int e = 1; e < NEXP; e++) if (p[e] > v1) { v1 = p[e]; i1 = e; }
        int i2 = (i1 == 0) ? 1 : 0; float v2 = p[i2];
        #pragma unroll
        for (int e = 0; e < NEXP; e++)
            if (e != i1 && p[e] > v2) { v2 = p[e]; i2 = e; }

        g_idx1[tok] = i1;  g_idx2[tok] = i2;
        g_gate1[tok] = v1; g_gate2[tok] = v2;
        #pragma unroll
        for (int e = 0; e < NEXP; e++) sP[warp][e] = p[e];
    }
    __syncthreads();
    if (threadIdx.x < NEXP) {
        float s = 0.f;
        #pragma unroll
        for (int w = 0; w < 8; w++) s += sP[w][threadIdx.x];
        g_partial[blockIdx.x * NEXP + threadIdx.x] = s;
    }
}

// ---------------- 2) capacity scan + loss (smem-staged, warp-parallel) ----
#define SCAN_SMEM (2 * S_TOK * 4)   // 128 KB

__global__ void __launch_bounds__(256) scan_loss_kernel(float* loss_out)
{
    extern __shared__ int sidx[];
    int* s1 = sidx;
    int* s2 = sidx + S_TOK;

    {
        const int4* p1 = (const int4*)g_idx1;
        const int4* p2 = (const int4*)g_idx2;
        int4* q1 = (int4*)s1;
        int4* q2 = (int4*)s2;
        #pragma unroll
        for (int i = 0; i < S_TOK / 4 / 256; i++) {
            q1[threadIdx.x + i * 256] = p1[threadIdx.x + i * 256];
            q2[threadIdx.x + i * 256] = p2[threadIdx.x + i * 256];
        }
    }
    __syncthreads();

    int warp = threadIdx.x >> 5;
    int lane = threadIdx.x & 31;
    int e = warp;
    unsigned lmask = (1u << lane) - 1u;

    int cnt = 0;
    #pragma unroll 4
    for (int base = 0; base < S_TOK; base += 32) {
        int id = s1[base + lane];
        unsigned m = __ballot_sync(0xffffffffu, id == e);
        if (id == e)
            g_pos1[base + lane] = cnt + __popc(m & lmask);
        cnt += __popc(m);
    }
    if (lane == 0) g_cnt1[e] = cnt;
    int used1 = min(cnt, CAP);

    int cnt2 = 0;
    #pragma unroll 4
    for (int base = 0; base < S_TOK; base += 32) {
        int id = s2[base + lane];
        unsigned m = __ballot_sync(0xffffffffu, id == e);
        if (id == e)
            g_pos2[base + lane] = used1 + cnt2 + __popc(m & lmask);
        cnt2 += __popc(m);
    }

    float s = 0.f;
    #pragma unroll 4
    for (int b = lane; b < GATE_BLOCKS; b += 32)
        s += g_partial[b * NEXP + e];
    #pragma unroll
    for (int off = 16; off; off >>= 1)
        s += __shfl_xor_sync(0xffffffffu, s, off);

    __shared__ float sms[NEXP];
    if (lane == 0) sms[e] = s;
    __syncthreads();
    if (threadIdx.x == 0 && loss_out != nullptr) {
        const float invS = 1.0f / (float)S_TOK;
        float tot = 0.f;
        #pragma unroll
        for (int e2 = 0; e2 < NEXP; e2++)
            tot += (sms[e2] * invS) * ((float)g_cnt1[e2] * invS);
        *loss_out = 0.01f * (tot * 0.125f) * 64.0f;
    }
}

// ---------------- 3) zero dispatch buffers (fp16) ----------------
__global__ void zero_buf_kernel()
{
    size_t i = (size_t)blockIdx.x * blockDim.x + threadIdx.x;
    ((float4*)g_bufh)[i] = make_float4(0.f, 0.f, 0.f, 0.f);
}

// ---------------- 4) dispatch scatter (fp32 -> fp16 RN) ----------------
__global__ void __launch_bounds__(256) dispatch_kernel(const float* __restrict__ x)
{
    int tok = blockIdx.x;
    int i1 = g_idx1[tok], i2 = g_idx2[tok];
    int p1 = g_pos1[tok], p2 = g_pos2[tok];
    bool k1 = p1 < CAP, k2 = p2 < CAP;

    const float4* xr = (const float4*)(x + (size_t)tok * DMODEL);
    uint2* b1p = (uint2*)(g_bufh + ((size_t)i1 * CAP + p1) * DMODEL);
    uint2* b2p = (uint2*)(g_bufh + ((size_t)i2 * CAP + p2) * DMODEL);

    int j = threadIdx.x;
    float4 v = xr[j];
    __half2 h0 = __floats2half2_rn(v.x, v.y);
    __half2 h1 = __floats2half2_rn(v.z, v.w);
    uint2 pk = make_uint2(*(uint32_t*)&h0, *(uint32_t*)&h1);
    if (k1) b1p[j] = pk;
    if (k2) b2p[j] = pk;
}

// ---------------- 5) weight transpose fp32 -> fp16 ----------------
// in [E][R][C] fp32 -> out [E][C][R] fp16
__global__ void __launch_bounds__(256) transpose_h_kernel(
    const float* __restrict__ in, __half* __restrict__ out, int R, int C)
{
    __shared__ float tile[32][33];
    int e = blockIdx.z;
    const float* ine = in + (size_t)e * R * C;
    __half* oute = out + (size_t)e * R * C;
    int c0 = blockIdx.x * 32, r0 = blockIdx.y * 32;
    int tx = threadIdx.x, ty = threadIdx.y;
    #pragma unroll
    for (int i = 0; i < 32; i += 8)
        tile[ty + i][tx] = ine[(size_t)(r0 + ty + i) * C + c0 + tx];
    __syncthreads();
    #pragma unroll
    for (int i = 0; i < 32; i += 8)
        oute[(size_t)(c0 + ty + i) * R + r0 + tx] = __float2half_rn(tile[tx][ty + i]);
}

// ---------------- 6) fp16 mma.sync grouped GEMM (128x128, 2 CTA/SM) ------
// C[e][m][n] = sum_k A[e][m][k] * Bt[e][n][k]  (+bias, opt gelu)
// Block 128x128, BK=32 halfs, 8 warps (64x32 each), 4-stage cp.async.
#define BM 128
#define BN 128
#define BK 32
#define ROWP 40                      // padded row (halfs); 80B -> LDSM conflict-free
#define A_STG (BM * ROWP)            // 5120 halfs
#define B_STG (BN * ROWP)            // 5120 halfs
#define STG_H (A_STG + B_STG)        // 10240 halfs = 20480 B
#define NSTG 4
#define GEMM_SMEM (NSTG * STG_H * 2) // 81920 bytes -> 2 CTAs/SM

template<typename OutT, int DO_GELU>
__global__ void __launch_bounds__(256, 2) moe_mma_gemm(
    const __half* __restrict__ A, const __half* __restrict__ Bt,
    const float* __restrict__ bias, OutT* __restrict__ C,
    int M, int N, int K)
{
    extern __shared__ __half smemh[];
    const uint32_t sb = smem_u32(smemh);

    const int tid = threadIdx.x;
    const int lane = tid & 31;
    const int wid = tid >> 5;
    const int wm = wid & 1;          // warp m half (64)
    const int wn = wid >> 1;         // warp n quarter (32)
    const int g = lane >> 2;
    const int t4 = lane & 3;

    const int e = blockIdx.z;
    const int mbase = blockIdx.x * BM;
    const int nbase = blockIdx.y * BN;
    const __half* Ae = A + (size_t)e * M * K;
    const __half* Be = Bt + (size_t)e * N * K;

    // cp.async mapping: 128 rows x 4 chunks = 512 per tile; 256 thr x 2 each
    const int r0 = tid >> 1;
    const int c0 = (tid & 1) * 2;
    const int KT = K / BK;

    // ldmatrix per-lane smem byte offsets (within a stage)
    const uint32_t a_off =
        (uint32_t)((wm * 64 + (lane & 7) + ((lane >> 3) & 1) * 8) * ROWP
                   + ((lane >> 4) & 1) * 8) * 2;
    const uint32_t b_off = (uint32_t)(A_STG
                   + (wn * 32 + (lane & 7) + ((lane >> 4) & 1) * 8) * ROWP
                   + ((lane >> 3) & 1) * 8) * 2;

    auto load_stage = [&](int s, int kt) {
        uint32_t abase = sb + (uint32_t)(s * STG_H) * 2;
        uint32_t bbase = abase + A_STG * 2;
        const __half* Asrc = Ae + (size_t)mbase * K + (size_t)kt * BK;
        const __half* Bsrc = Be + (size_t)nbase * K + (size_t)kt * BK;
        cp_async16(abase + (uint32_t)(r0 * ROWP + (c0 + 0) * 8) * 2,
                   Asrc + (size_t)r0 * K + (c0 + 0) * 8);
        cp_async16(abase + (uint32_t)(r0 * ROWP + (c0 + 1) * 8) * 2,
                   Asrc + (size_t)r0 * K + (c0 + 1) * 8);
        cp_async16(bbase + (uint32_t)(r0 * ROWP + (c0 + 0) * 8) * 2,
                   Bsrc + (size_t)r0 * K + (c0 + 0) * 8);
        cp_async16(bbase + (uint32_t)(r0 * ROWP + (c0 + 1) * 8) * 2,
                   Bsrc + (size_t)r0 * K + (c0 + 1) * 8);
    };

    float acc[4][4][4];
    #pragma unroll
    for (int i = 0; i < 4; i++)
        #pragma unroll
        for (int j = 0; j < 4; j++)
            #pragma unroll
            for (int r = 0; r < 4; r++) acc[i][j][r] = 0.f;

    load_stage(0, 0); cp_commit();
    load_stage(1, 1); cp_commit();
    load_stage(2, 2); cp_commit();

    for (int kt = 0; kt < KT; kt++) {
        cp_wait<2>();
        __syncthreads();   // single barrier/kt: orders stage reuse + data ready
        if (kt + 3 < KT) load_stage((kt + 3) & 3, kt + 3);
        cp_commit();

        uint32_t stg = sb + (uint32_t)((kt & 3) * STG_H) * 2;
        uint32_t a_base = stg + a_off;
        uint32_t b_base = stg + b_off;

        #pragma unroll
        for (int kc = 0; kc < 2; kc++) {
            uint32_t a[4][4], b[4][2];
            #pragma unroll
            for (int i = 0; i < 4; i++)
                ldsm_x4(a[i][0], a[i][1], a[i][2], a[i][3],
                        a_base + (uint32_t)(i * 16 * ROWP + kc * 16) * 2);
            #pragma unroll
            for (int jp = 0; jp < 2; jp++)
                ldsm_x4(b[2 * jp][0], b[2 * jp][1], b[2 * jp + 1][0], b[2 * jp + 1][1],
                        b_base + (uint32_t)(jp * 16 * ROWP + kc * 16) * 2);
            #pragma unroll
            for (int i = 0; i < 4; i++)
                #pragma unroll
                for (int j = 0; j < 4; j++)
                    mma_f16(acc[i][j][0], acc[i][j][1], acc[i][j][2], acc[i][j][3],
                            a[i][0], a[i][1], a[i][2], a[i][3],
                            b[j][0], b[j][1]);
        }
        // no trailing barrier: next iteration's post-wait barrier orders reuse
    }

    // ---- epilogue (registers only; no barrier needed) ----
    const float* brow = bias + (size_t)e * N + nbase + wn * 32;
    OutT* Cr = C + ((size_t)e * M + mbase + wm * 64) * N + nbase + wn * 32;
    #pragma unroll
    for (int i = 0; i < 4; i++) {
        #pragma unroll
        for (int j = 0; j < 4; j++) {
            int col = j * 8 + 2 * t4;
            float b0 = brow[col], b1 = brow[col + 1];
            float v0 = acc[i][j][0] + b0;
            float v1 = acc[i][j][1] + b1;
            float v2 = acc[i][j][2] + b0;
            float v3 = acc[i][j][3] + b1;
            if (DO_GELU) {
                v0 = gelu_tanh(v0); v1 = gelu_tanh(v1);
                v2 = gelu_tanh(v2); v3 = gelu_tanh(v3);
            }
            OutT* p0 = Cr + (size_t)(i * 16 + g) * N + col;
            OutT* p1 = Cr + (size_t)(i * 16 + g + 8) * N + col;
            if (sizeof(OutT) == 2) {
                __half2 h0 = __floats2half2_rn(v0, v1);
                __half2 h1 = __floats2half2_rn(v2, v3);
                *(__half2*)p0 = h0;
                *(__half2*)p1 = h1;
            } else {
                *(float2*)p0 = make_float2(v0, v1);
                *(float2*)p1 = make_float2(v2, v3);
            }
        }
    }
}

// ---------------- 7) combine ----------------
__global__ void __launch_bounds__(256) combine_kernel(float* __restrict__ out)
{
    int tok = blockIdx.x;
    int i1 = g_idx1[tok], i2 = g_idx2[tok];
    int p1 = g_pos1[tok], p2 = g_pos2[tok];
    float ga = g_gate1[tok], gb = g_gate2[tok];
    bool k1 = p1 < CAP, k2 = p2 < CAP;
    float a1 = k1 ? ga : 0.f;
    float a2 = k2 ? gb : 0.f;
    float denom = a1 + a2 + 1e-9f;
    float w1 = a1 / denom, w2 = a2 / denom;
    int q1 = k1 ? p1 : 0, q2 = k2 ? p2 : 0;

    const float4* e1 = (const float4*)(g_eo + ((size_t)i1 * CAP + q1) * DMODEL);
    const float4* e2 = (const float4*)(g_eo + ((size_t)i2 * CAP + q2) * DMODEL);
    float4* o = (float4*)(out + (size_t)tok * DMODEL);

    int j = threadIdx.x;
    float4 v1 = e1[j], v2 = e2[j];
    float4 r;
    r.x = w1 * v1.x + w2 * v2.x;
    r.y = w1 * v1.y + w2 * v2.y;
    r.z = w1 * v1.z + w2 * v2.z;
    r.w = w1 * v1.w + w2 * v2.w;
    o[j] = r;
}

// ---------------- launch ----------------
extern "C" void kernel_launch(void* const* d_in, const int* in_sizes, int n_in,
                              void* d_out, int out_size)
{
    const float* x  = (const float*)d_in[0];
    const float* Wg = (const float*)d_in[1];
    const float* W1 = (const float*)d_in[2];
    const float* b1 = (const float*)d_in[3];
    const float* W2 = (const float*)d_in[4];
    const float* b2 = (const float*)d_in[5];
    float* out = (float*)d_out;

    void *pbuf, *ph, *peo, *pw1, *pw2;
    cudaGetSymbolAddress(&pbuf, g_bufh);
    cudaGetSymbolAddress(&ph,   g_hh);
    cudaGetSymbolAddress(&peo,  g_eo);
    cudaGetSymbolAddress(&pw1,  g_w1h);
    cudaGetSymbolAddress(&pw2,  g_w2h);

    cudaFuncSetAttribute((const void*)moe_mma_gemm<__half, 1>,
                         cudaFuncAttributeMaxDynamicSharedMemorySize, GEMM_SMEM);
    cudaFuncSetAttribute((const void*)moe_mma_gemm<float, 0>,
                         cudaFuncAttributeMaxDynamicSharedMemorySize, GEMM_SMEM);
    cudaFuncSetAttribute((const void*)scan_loss_kernel,
                         cudaFuncAttributeMaxDynamicSharedMemorySize, SCAN_SMEM);

    float* loss_ptr = (out_size > S_TOK * DMODEL) ? (out + (size_t)S_TOK * DMODEL)
                                                  : nullptr;

    // weight transposes fp32 -> fp16 (W^T layouts for row.col mma)
    transpose_h_kernel<<<dim3(HFFN / 32, DMODEL / 32, NEXP), dim3(32, 8)>>>(
        W1, (__half*)pw1, DMODEL, HFFN);
    transpose_h_kernel<<<dim3(DMODEL / 32, HFFN / 32, NEXP), dim3(32, 8)>>>(
        W2, (__half*)pw2, HFFN, DMODEL);

    gating_kernel<<<GATE_BLOCKS, 256>>>(x, Wg);
    scan_loss_kernel<<<1, 256, SCAN_SMEM>>>(loss_ptr);

    zero_buf_kernel<<<(int)(((size_t)NEXP * CAP * DMODEL * 2 / 16) / 256), 256>>>();
    dispatch_kernel<<<S_TOK, 256>>>(x);

    // GEMM1: h = gelu(buf @ W1 + b1) -> fp16
    moe_mma_gemm<__half, 1><<<dim3(CAP / BM, HFFN / BN, NEXP), 256, GEMM_SMEM>>>(
        (const __half*)pbuf, (const __half*)pw1, b1, (__half*)ph,
        CAP, HFFN, DMODEL);
    // GEMM2: eo = h @ W2 + b2 -> fp32
    moe_mma_gemm<float, 0><<<dim3(CAP / BM, DMODEL / BN, NEXP), 256, GEMM_SMEM>>>(
        (const __half*)ph, (const __half*)pw2, b2, (float*)peo,
        CAP, DMODEL, HFFN);

    combine_kernel<<<S_TOK, 256>>>(out);
}

// round 8
// speedup vs baseline: 6.3784x; 1.0714x over previous
#include <cuda_runtime.h>
#include <cuda_fp16.h>
#include <math.h>
#include <stdint.h>

// ---------------- problem constants ----------------
#define S_TOK   16384          // B*N
#define DMODEL  1024
#define NEXP    8
#define HFFN    4096
#define CAP     2560           // int(S*1.25/E)
#define GATE_BLOCKS (S_TOK/8)

// ---------------- device scratch (allocation-free rule) ----------------
__device__ __half g_bufh[NEXP * CAP * DMODEL];            // 42 MB  dispatch fp16
__device__ __half g_hh  [(size_t)NEXP * CAP * HFFN];      // 168 MB hidden fp16
__device__ float  g_eo  [NEXP * CAP * DMODEL];            // 80 MB  expert out fp32
__device__ __half g_w1h [(size_t)NEXP * HFFN * DMODEL];   // 67 MB  W1^T [E][H][D]
__device__ __half g_w2h [(size_t)NEXP * DMODEL * HFFN];   // 67 MB  W2^T [E][D][H]
__device__ float g_gate1[S_TOK];
__device__ float g_gate2[S_TOK];
__device__ int   g_idx1[S_TOK];
__device__ int   g_idx2[S_TOK];
__device__ int   g_pos1[S_TOK];
__device__ int   g_pos2[S_TOK];
__device__ float g_partial[GATE_BLOCKS * NEXP];
__device__ int   g_cnt1[NEXP];

// ---------------- helpers ----------------
__device__ __forceinline__ float gelu_tanh(float x) {
    float x3 = x * x * x;
    return 0.5f * x * (1.0f + tanhf(0.7978845608028654f * (x + 0.044715f * x3)));
}
__device__ __forceinline__ uint32_t smem_u32(const void* p) {
    uint32_t a;
    asm("{ .reg .u64 t; cvta.to.shared.u64 t, %1; cvt.u32.u64 %0, t; }" : "=r"(a) : "l"(p));
    return a;
}
__device__ __forceinline__ void cp_async16(uint32_t dst, const void* src) {
    asm volatile("cp.async.cg.shared.global [%0], [%1], 16;" :: "r"(dst), "l"(src));
}
__device__ __forceinline__ void cp_commit() {
    asm volatile("cp.async.commit_group;");
}
template<int N>
__device__ __forceinline__ void cp_wait() {
    asm volatile("cp.async.wait_group %0;" :: "n"(N));
}
__device__ __forceinline__ void mma_f16(float& c0, float& c1, float& c2, float& c3,
                                        uint32_t a0, uint32_t a1, uint32_t a2, uint32_t a3,
                                        uint32_t b0, uint32_t b1) {
    asm volatile(
        "mma.sync.aligned.m16n8k16.row.col.f32.f16.f16.f32 "
        "{%0,%1,%2,%3}, {%4,%5,%6,%7}, {%8,%9}, {%0,%1,%2,%3};"
        : "+f"(c0), "+f"(c1), "+f"(c2), "+f"(c3)
        : "r"(a0), "r"(a1), "r"(a2), "r"(a3), "r"(b0), "r"(b1));
}
__device__ __forceinline__ void ldsm_x4(uint32_t& r0, uint32_t& r1,
                                        uint32_t& r2, uint32_t& r3, uint32_t addr) {
    asm volatile("ldmatrix.sync.aligned.m8n8.x4.shared.b16 {%0,%1,%2,%3}, [%4];"
                 : "=r"(r0), "=r"(r1), "=r"(r2), "=r"(r3) : "r"(addr));
}

// ---------------- 1) gating ----------------
__global__ void __launch_bounds__(256) gating_kernel(
    const float* __restrict__ x, const float* __restrict__ Wg)
{
    __shared__ float sWgT[NEXP * DMODEL];
    __shared__ float sP[8][NEXP];
    for (int i = threadIdx.x; i < NEXP * DMODEL; i += blockDim.x) {
        int d = i & (DMODEL - 1);
        int e = i >> 10;
        sWgT[i] = Wg[d * NEXP + e];
    }
    __syncthreads();

    int warp = threadIdx.x >> 5;
    int lane = threadIdx.x & 31;
    int tok  = blockIdx.x * 8 + warp;

    const float* xr = x + (size_t)tok * DMODEL;
    float acc[NEXP];
    #pragma unroll
    for (int e = 0; e < NEXP; e++) acc[e] = 0.f;

    #pragma unroll 4
    for (int t = 0; t < 32; t++) {
        int d = t * 32 + lane;
        float xv = xr[d];
        #pragma unroll
        for (int e = 0; e < NEXP; e++)
            acc[e] += xv * sWgT[e * DMODEL + d];
    }
    #pragma unroll
    for (int e = 0; e < NEXP; e++) {
        #pragma unroll
        for (int off = 16; off; off >>= 1)
            acc[e] += __shfl_xor_sync(0xffffffffu, acc[e], off);
    }

    if (lane == 0) {
        float mx = acc[0];
        #pragma unroll
        for (int e = 1; e < NEXP; e++) mx = fmaxf(mx, acc[e]);
        float p[NEXP], sum = 0.f;
        #pragma unroll
        for (int e = 0; e < NEXP; e++) { p[e] = expf(acc[e] - mx); sum += p[e]; }
        float inv = 1.0f / sum;
        #pragma unroll
        for (int e = 0; e < NEXP; e++) p[e] *= inv;

        int i1 = 0; float v1 = p[0];
        #pragma unroll
        for (int e = 1; e < NEXP; e++) if (p[e] > v1) { v1 = p[e]; i1 = e; }
        int i2 = (i1 == 0) ? 1 : 0; float v2 = p[i2];
        #pragma unroll
        for (int e = 0; e < NEXP; e++)
            if (e != i1 && p[e] > v2) { v2 = p[e]; i2 = e; }

        g_idx1[tok] = i1;  g_idx2[tok] = i2;
        g_gate1[tok] = v1; g_gate2[tok] = v2;
        #pragma unroll
        for (int e = 0; e < NEXP; e++) sP[warp][e] = p[e];
    }
    __syncthreads();
    if (threadIdx.x < NEXP) {
        float s = 0.f;
        #pragma unroll
        for (int w = 0; w < 8; w++) s += sP[w][threadIdx.x];
        g_partial[blockIdx.x * NEXP + threadIdx.x] = s;
    }
}

// ---------------- 2) capacity scan + loss (smem-staged, warp-parallel) ----
#define SCAN_SMEM (2 * S_TOK * 4)   // 128 KB

__global__ void __launch_bounds__(256) scan_loss_kernel(float* loss_out)
{
    extern __shared__ int sidx[];
    int* s1 = sidx;
    int* s2 = sidx + S_TOK;

    {
        const int4* p1 = (const int4*)g_idx1;
        const int4* p2 = (const int4*)g_idx2;
        int4* q1 = (int4*)s1;
        int4* q2 = (int4*)s2;
        #pragma unroll
        for (int i = 0; i < S_TOK / 4 / 256; i++) {
            q1[threadIdx.x + i * 256] = p1[threadIdx.x + i * 256];
            q2[threadIdx.x + i * 256] = p2[threadIdx.x + i * 256];
        }
    }
    __syncthreads();

    int warp = threadIdx.x >> 5;
    int lane = threadIdx.x & 31;
    int e = warp;
    unsigned lmask = (1u << lane) - 1u;

    int cnt = 0;
    #pragma unroll 4
    for (int base = 0; base < S_TOK; base += 32) {
        int id = s1[base + lane];
        unsigned m = __ballot_sync(0xffffffffu, id == e);
        if (id == e)
            g_pos1[base + lane] = cnt + __popc(m & lmask);
        cnt += __popc(m);
    }
    if (lane == 0) g_cnt1[e] = cnt;
    int used1 = min(cnt, CAP);

    int cnt2 = 0;
    #pragma unroll 4
    for (int base = 0; base < S_TOK; base += 32) {
        int id = s2[base + lane];
        unsigned m = __ballot_sync(0xffffffffu, id == e);
        if (id == e)
            g_pos2[base + lane] = used1 + cnt2 + __popc(m & lmask);
        cnt2 += __popc(m);
    }

    float s = 0.f;
    #pragma unroll 4
    for (int b = lane; b < GATE_BLOCKS; b += 32)
        s += g_partial[b * NEXP + e];
    #pragma unroll
    for (int off = 16; off; off >>= 1)
        s += __shfl_xor_sync(0xffffffffu, s, off);

    __shared__ float sms[NEXP];
    if (lane == 0) sms[e] = s;
    __syncthreads();
    if (threadIdx.x == 0 && loss_out != nullptr) {
        const float invS = 1.0f / (float)S_TOK;
        float tot = 0.f;
        #pragma unroll
        for (int e2 = 0; e2 < NEXP; e2++)
            tot += (sms[e2] * invS) * ((float)g_cnt1[e2] * invS);
        *loss_out = 0.01f * (tot * 0.125f) * 64.0f;
    }
}

// ---------------- 3) zero dispatch buffers (fp16) ----------------
__global__ void zero_buf_kernel()
{
    size_t i = (size_t)blockIdx.x * blockDim.x + threadIdx.x;
    ((float4*)g_bufh)[i] = make_float4(0.f, 0.f, 0.f, 0.f);
}

// ---------------- 4) dispatch scatter (fp32 -> fp16 RN) ----------------
__global__ void __launch_bounds__(256) dispatch_kernel(const float* __restrict__ x)
{
    int tok = blockIdx.x;
    int i1 = g_idx1[tok], i2 = g_idx2[tok];
    int p1 = g_pos1[tok], p2 = g_pos2[tok];
    bool k1 = p1 < CAP, k2 = p2 < CAP;

    const float4* xr = (const float4*)(x + (size_t)tok * DMODEL);
    uint2* b1p = (uint2*)(g_bufh + ((size_t)i1 * CAP + p1) * DMODEL);
    uint2* b2p = (uint2*)(g_bufh + ((size_t)i2 * CAP + p2) * DMODEL);

    int j = threadIdx.x;
    float4 v = xr[j];
    __half2 h0 = __floats2half2_rn(v.x, v.y);
    __half2 h1 = __floats2half2_rn(v.z, v.w);
    uint2 pk = make_uint2(*(uint32_t*)&h0, *(uint32_t*)&h1);
    if (k1) b1p[j] = pk;
    if (k2) b2p[j] = pk;
}

// ---------------- 5) weight transpose fp32 -> fp16 ----------------
// in [E][R][C] fp32 -> out [E][C][R] fp16
__global__ void __launch_bounds__(256) transpose_h_kernel(
    const float* __restrict__ in, __half* __restrict__ out, int R, int C)
{
    __shared__ float tile[32][33];
    int e = blockIdx.z;
    const float* ine = in + (size_t)e * R * C;
    __half* oute = out + (size_t)e * R * C;
    int c0 = blockIdx.x * 32, r0 = blockIdx.y * 32;
    int tx = threadIdx.x, ty = threadIdx.y;
    #pragma unroll
    for (int i = 0; i < 32; i += 8)
        tile[ty + i][tx] = ine[(size_t)(r0 + ty + i) * C + c0 + tx];
    __syncthreads();
    #pragma unroll
    for (int i = 0; i < 32; i += 8)
        oute[(size_t)(c0 + ty + i) * R + r0 + tx] = __float2half_rn(tile[tx][ty + i]);
}

// ---------------- 6) fp16 mma.sync grouped GEMM (128x128, BK=64, 2 CTA/SM)
// C[e][m][n] = sum_k A[e][m][k] * Bt[e][n][k]  (+bias, opt gelu)
// Block 128x128, BK=64 halfs, 8 warps (64x32 each), 3-stage cp.async.
#define BM 128
#define BN 128
#define BK 64
#define ROWP 72                      // 64 + 8 pad halfs; 144B stride, LDSM conflict-free
#define A_STG (BM * ROWP)            // 9216 halfs
#define B_STG (BN * ROWP)            // 9216 halfs
#define STG_H (A_STG + B_STG)        // 18432 halfs = 36864 B
#define NSTG 3
#define GEMM_SMEM (NSTG * STG_H * 2) // 110592 bytes -> 2 CTAs/SM

template<typename OutT, int DO_GELU>
__global__ void __launch_bounds__(256, 2) moe_mma_gemm(
    const __half* __restrict__ A, const __half* __restrict__ Bt,
    const float* __restrict__ bias, OutT* __restrict__ C,
    int M, int N, int K)
{
    extern __shared__ __half smemh[];
    const uint32_t sb = smem_u32(smemh);

    const int tid = threadIdx.x;
    const int lane = tid & 31;
    const int wid = tid >> 5;
    const int wm = wid & 1;          // warp m half (64)
    const int wn = wid >> 1;         // warp n quarter (32)
    const int g = lane >> 2;
    const int t4 = lane & 3;

    const int e = blockIdx.z;
    const int mbase = blockIdx.x * BM;
    const int nbase = blockIdx.y * BN;
    const __half* Ae = A + (size_t)e * M * K;
    const __half* Be = Bt + (size_t)e * N * K;

    // cp.async mapping: 128 rows x 8 chunks (16B) per tile = 1024; 256 thr x 4
    const int r0 = tid >> 2;          // rows r0 and r0+64
    const int c0 = (tid & 3) * 2;     // chunks c0, c0+1
    const int KT = K / BK;

    // ldmatrix per-lane smem byte offsets (within a stage)
    const uint32_t a_off =
        (uint32_t)((wm * 64 + (lane & 7) + ((lane >> 3) & 1) * 8) * ROWP
                   + ((lane >> 4) & 1) * 8) * 2;
    const uint32_t b_off = (uint32_t)(A_STG
                   + (wn * 32 + (lane & 7) + ((lane >> 4) & 1) * 8) * ROWP
                   + ((lane >> 3) & 1) * 8) * 2;

    auto load_stage = [&](int s, int kt) {
        uint32_t abase = sb + (uint32_t)(s * STG_H) * 2;
        uint32_t bbase = abase + A_STG * 2;
        const __half* Asrc = Ae + (size_t)mbase * K + (size_t)kt * BK;
        const __half* Bsrc = Be + (size_t)nbase * K + (size_t)kt * BK;
        #pragma unroll
        for (int h = 0; h < 2; h++) {
            int r = r0 + h * 64;
            cp_async16(abase + (uint32_t)(r * ROWP + (c0 + 0) * 8) * 2,
                       Asrc + (size_t)r * K + (c0 + 0) * 8);
            cp_async16(abase + (uint32_t)(r * ROWP + (c0 + 1) * 8) * 2,
                       Asrc + (size_t)r * K + (c0 + 1) * 8);
            cp_async16(bbase + (uint32_t)(r * ROWP + (c0 + 0) * 8) * 2,
                       Bsrc + (size_t)r * K + (c0 + 0) * 8);
            cp_async16(bbase + (uint32_t)(r * ROWP + (c0 + 1) * 8) * 2,
                       Bsrc + (size_t)r * K + (c0 + 1) * 8);
        }
    };

    float acc[4][4][4];
    #pragma unroll
    for (int i = 0; i < 4; i++)
        #pragma unroll
        for (int j = 0; j < 4; j++)
            #pragma unroll
            for (int r = 0; r < 4; r++) acc[i][j][r] = 0.f;

    load_stage(0, 0); cp_commit();
    load_stage(1, 1); cp_commit();

    for (int kt = 0; kt < KT; kt++) {
        cp_wait<1>();
        __syncthreads();   // single barrier/kt: data ready + stage-reuse ordering
        if (kt + 2 < KT) load_stage((kt + 2) % NSTG, kt + 2);
        cp_commit();

        uint32_t stg = sb + (uint32_t)((kt % NSTG) * STG_H) * 2;
        uint32_t a_base = stg + a_off;
        uint32_t b_base = stg + b_off;

        #pragma unroll
        for (int kc = 0; kc < 4; kc++) {
            uint32_t a[4][4], b[4][2];
            #pragma unroll
            for (int i = 0; i < 4; i++)
                ldsm_x4(a[i][0], a[i][1], a[i][2], a[i][3],
                        a_base + (uint32_t)(i * 16 * ROWP + kc * 16) * 2);
            #pragma unroll
            for (int jp = 0; jp < 2; jp++)
                ldsm_x4(b[2 * jp][0], b[2 * jp][1], b[2 * jp + 1][0], b[2 * jp + 1][1],
                        b_base + (uint32_t)(jp * 16 * ROWP + kc * 16) * 2);
            #pragma unroll
            for (int i = 0; i < 4; i++)
                #pragma unroll
                for (int j = 0; j < 4; j++)
                    mma_f16(acc[i][j][0], acc[i][j][1], acc[i][j][2], acc[i][j][3],
                            a[i][0], a[i][1], a[i][2], a[i][3],
                            b[j][0], b[j][1]);
        }
        // no trailing barrier: next iteration's post-wait barrier orders reuse
    }

    // ---- epilogue (registers only) ----
    const float* brow = bias + (size_t)e * N + nbase + wn * 32;
    OutT* Cr = C + ((size_t)e * M + mbase + wm * 64) * N + nbase + wn * 32;
    #pragma unroll
    for (int i = 0; i < 4; i++) {
        #pragma unroll
        for (int j = 0; j < 4; j++) {
            int col = j * 8 + 2 * t4;
            float b0 = brow[col], b1 = brow[col + 1];
            float v0 = acc[i][j][0] + b0;
            float v1 = acc[i][j][1] + b1;
            float v2 = acc[i][j][2] + b0;
            float v3 = acc[i][j][3] + b1;
            if (DO_GELU) {
                v0 = gelu_tanh(v0); v1 = gelu_tanh(v1);
                v2 = gelu_tanh(v2); v3 = gelu_tanh(v3);
            }
            OutT* p0 = Cr + (size_t)(i * 16 + g) * N + col;
            OutT* p1 = Cr + (size_t)(i * 16 + g + 8) * N + col;
            if (sizeof(OutT) == 2) {
                __half2 h0 = __floats2half2_rn(v0, v1);
                __half2 h1 = __floats2half2_rn(v2, v3);
                *(__half2*)p0 = h0;
                *(__half2*)p1 = h1;
            } else {
                *(float2*)p0 = make_float2(v0, v1);
                *(float2*)p1 = make_float2(v2, v3);
            }
        }
    }
}

// ---------------- 7) combine ----------------
__global__ void __launch_bounds__(256) combine_kernel(float* __restrict__ out)
{
    int tok = blockIdx.x;
    int i1 = g_idx1[tok], i2 = g_idx2[tok];
    int p1 = g_pos1[tok], p2 = g_pos2[tok];
    float ga = g_gate1[tok], gb = g_gate2[tok];
    bool k1 = p1 < CAP, k2 = p2 < CAP;
    float a1 = k1 ? ga : 0.f;
    float a2 = k2 ? gb : 0.f;
    float denom = a1 + a2 + 1e-9f;
    float w1 = a1 / denom, w2 = a2 / denom;
    int q1 = k1 ? p1 : 0, q2 = k2 ? p2 : 0;

    const float4* e1 = (const float4*)(g_eo + ((size_t)i1 * CAP + q1) * DMODEL);
    const float4* e2 = (const float4*)(g_eo + ((size_t)i2 * CAP + q2) * DMODEL);
    float4* o = (float4*)(out + (size_t)tok * DMODEL);

    int j = threadIdx.x;
    float4 v1 = e1[j], v2 = e2[j];
    float4 r;
    r.x = w1 * v1.x + w2 * v2.x;
    r.y = w1 * v1.y + w2 * v2.y;
    r.z = w1 * v1.z + w2 * v2.z;
    r.w = w1 * v1.w + w2 * v2.w;
    o[j] = r;
}

// ---------------- launch ----------------
extern "C" void kernel_launch(void* const* d_in, const int* in_sizes, int n_in,
                              void* d_out, int out_size)
{
    const float* x  = (const float*)d_in[0];
    const float* Wg = (const float*)d_in[1];
    const float* W1 = (const float*)d_in[2];
    const float* b1 = (const float*)d_in[3];
    const float* W2 = (const float*)d_in[4];
    const float* b2 = (const float*)d_in[5];
    float* out = (float*)d_out;

    void *pbuf, *ph, *peo, *pw1, *pw2;
    cudaGetSymbolAddress(&pbuf, g_bufh);
    cudaGetSymbolAddress(&ph,   g_hh);
    cudaGetSymbolAddress(&peo,  g_eo);
    cudaGetSymbolAddress(&pw1,  g_w1h);
    cudaGetSymbolAddress(&pw2,  g_w2h);

    cudaFuncSetAttribute((const void*)moe_mma_gemm<__half, 1>,
                         cudaFuncAttributeMaxDynamicSharedMemorySize, GEMM_SMEM);
    cudaFuncSetAttribute((const void*)moe_mma_gemm<float, 0>,
                         cudaFuncAttributeMaxDynamicSharedMemorySize, GEMM_SMEM);
    cudaFuncSetAttribute((const void*)scan_loss_kernel,
                         cudaFuncAttributeMaxDynamicSharedMemorySize, SCAN_SMEM);

    float* loss_ptr = (out_size > S_TOK * DMODEL) ? (out + (size_t)S_TOK * DMODEL)
                                                  : nullptr;

    // weight transposes fp32 -> fp16 (W^T layouts for row.col mma)
    transpose_h_kernel<<<dim3(HFFN / 32, DMODEL / 32, NEXP), dim3(32, 8)>>>(
        W1, (__half*)pw1, DMODEL, HFFN);
    transpose_h_kernel<<<dim3(DMODEL / 32, HFFN / 32, NEXP), dim3(32, 8)>>>(
        W2, (__half*)pw2, HFFN, DMODEL);

    gating_kernel<<<GATE_BLOCKS, 256>>>(x, Wg);
    scan_loss_kernel<<<1, 256, SCAN_SMEM>>>(loss_ptr);

    zero_buf_kernel<<<(int)(((size_t)NEXP * CAP * DMODEL * 2 / 16) / 256), 256>>>();
    dispatch_kernel<<<S_TOK, 256>>>(x);

    // GEMM1: h = gelu(buf @ W1 + b1) -> fp16
    moe_mma_gemm<__half, 1><<<dim3(CAP / BM, HFFN / BN, NEXP), 256, GEMM_SMEM>>>(
        (const __half*)pbuf, (const __half*)pw1, b1, (__half*)ph,
        CAP, HFFN, DMODEL);
    // GEMM2: eo = h @ W2 + b2 -> fp32
    moe_mma_gemm<float, 0><<<dim3(CAP / BM, DMODEL / BN, NEXP), 256, GEMM_SMEM>>>(
        (const __half*)ph, (const __half*)pw2, b2, (float*)peo,
        CAP, DMODEL, HFFN);

    combine_kernel<<<S_TOK, 256>>>(out);
}

// round 9
// speedup vs baseline: 6.5711x; 1.0302x over previous
#include <cuda_runtime.h>
#include <cuda_fp16.h>
#include <math.h>
#include <stdint.h>

// ---------------- problem constants ----------------
#define S_TOK   16384          // B*N
#define DMODEL  1024
#define NEXP    8
#define HFFN    4096
#define CAP     2560           // int(S*1.25/E)
#define GATE_BLOCKS (S_TOK/8)

// ---------------- device scratch (allocation-free rule) ----------------
__device__ __half g_bufh[NEXP * CAP * DMODEL];            // 42 MB  dispatch fp16
__device__ __half g_hh  [(size_t)NEXP * CAP * HFFN];      // 168 MB hidden fp16
__device__ float  g_eo  [NEXP * CAP * DMODEL];            // 80 MB  expert out fp32
__device__ __half g_w1h [(size_t)NEXP * HFFN * DMODEL];   // 67 MB  W1^T [E][H][D]
__device__ __half g_w2h [(size_t)NEXP * DMODEL * HFFN];   // 67 MB  W2^T [E][D][H]
__device__ float g_gate1[S_TOK];
__device__ float g_gate2[S_TOK];
__device__ int   g_idx1[S_TOK];
__device__ int   g_idx2[S_TOK];
__device__ int   g_pos1[S_TOK];
__device__ int   g_pos2[S_TOK];
__device__ float g_partial[GATE_BLOCKS * NEXP];
__device__ int   g_cnt1[NEXP];

// ---------------- helpers ----------------
__device__ __forceinline__ float gelu_tanh(float x) {
    float x3 = x * x * x;
    return 0.5f * x * (1.0f + tanhf(0.7978845608028654f * (x + 0.044715f * x3)));
}
__device__ __forceinline__ uint32_t smem_u32(const void* p) {
    uint32_t a;
    asm("{ .reg .u64 t; cvta.to.shared.u64 t, %1; cvt.u32.u64 %0, t; }" : "=r"(a) : "l"(p));
    return a;
}
__device__ __forceinline__ void cp_async16(uint32_t dst, const void* src) {
    asm volatile("cp.async.cg.shared.global [%0], [%1], 16;" :: "r"(dst), "l"(src));
}
__device__ __forceinline__ void cp_commit() {
    asm volatile("cp.async.commit_group;");
}
template<int N>
__device__ __forceinline__ void cp_wait() {
    asm volatile("cp.async.wait_group %0;" :: "n"(N));
}
__device__ __forceinline__ void mma_f16(float& c0, float& c1, float& c2, float& c3,
                                        uint32_t a0, uint32_t a1, uint32_t a2, uint32_t a3,
                                        uint32_t b0, uint32_t b1) {
    asm volatile(
        "mma.sync.aligned.m16n8k16.row.col.f32.f16.f16.f32 "
        "{%0,%1,%2,%3}, {%4,%5,%6,%7}, {%8,%9}, {%0,%1,%2,%3};"
        : "+f"(c0), "+f"(c1), "+f"(c2), "+f"(c3)
        : "r"(a0), "r"(a1), "r"(a2), "r"(a3), "r"(b0), "r"(b1));
}
__device__ __forceinline__ void ldsm_x4(uint32_t& r0, uint32_t& r1,
                                        uint32_t& r2, uint32_t& r3, uint32_t addr) {
    asm volatile("ldmatrix.sync.aligned.m8n8.x4.shared.b16 {%0,%1,%2,%3}, [%4];"
                 : "=r"(r0), "=r"(r1), "=r"(r2), "=r"(r3) : "r"(addr));
}

// ---------------- 1) gating ----------------
__global__ void __launch_bounds__(256) gating_kernel(
    const float* __restrict__ x, const float* __restrict__ Wg)
{
    __shared__ float sWgT[NEXP * DMODEL];
    __shared__ float sP[8][NEXP];
    for (int i = threadIdx.x; i < NEXP * DMODEL; i += blockDim.x) {
        int d = i & (DMODEL - 1);
        int e = i >> 10;
        sWgT[i] = Wg[d * NEXP + e];
    }
    __syncthreads();

    int warp = threadIdx.x >> 5;
    int lane = threadIdx.x & 31;
    int tok  = blockIdx.x * 8 + warp;

    const float* xr = x + (size_t)tok * DMODEL;
    float acc[NEXP];
    #pragma unroll
    for (int e = 0; e < NEXP; e++) acc[e] = 0.f;

    #pragma unroll 4
    for (int t = 0; t < 32; t++) {
        int d = t * 32 + lane;
        float xv = xr[d];
        #pragma unroll
        for (int e = 0; e < NEXP; e++)
            acc[e] += xv * sWgT[e * DMODEL + d];
    }
    #pragma unroll
    for (int e = 0; e < NEXP; e++) {
        #pragma unroll
        for (int off = 16; off; off >>= 1)
            acc[e] += __shfl_xor_sync(0xffffffffu, acc[e], off);
    }

    if (lane == 0) {
        float mx = acc[0];
        #pragma unroll
        for (int e = 1; e < NEXP; e++) mx = fmaxf(mx, acc[e]);
        float p[NEXP], sum = 0.f;
        #pragma unroll
        for (int e = 0; e < NEXP; e++) { p[e] = expf(acc[e] - mx); sum += p[e]; }
        float inv = 1.0f / sum;
        #pragma unroll
        for (int e = 0; e < NEXP; e++) p[e] *= inv;

        int i1 = 0; float v1 = p[0];
        #pragma unroll
        for (int e = 1; e < NEXP; e++) if (p[e] > v1) { v1 = p[e]; i1 = e; }
        int i2 = (i1 == 0) ? 1 : 0; float v2 = p[i2];
        #pragma unroll
        for (int e = 0; e < NEXP; e++)
            if (e != i1 && p[e] > v2) { v2 = p[e]; i2 = e; }

        g_idx1[tok] = i1;  g_idx2[tok] = i2;
        g_gate1[tok] = v1; g_gate2[tok] = v2;
        #pragma unroll
        for (int e = 0; e < NEXP; e++) sP[warp][e] = p[e];
    }
    __syncthreads();
    if (threadIdx.x < NEXP) {
        float s = 0.f;
        #pragma unroll
        for (int w = 0; w < 8; w++) s += sP[w][threadIdx.x];
        g_partial[blockIdx.x * NEXP + threadIdx.x] = s;
    }
}

// ---------------- 2) capacity scan + loss (smem-staged, warp-parallel) ----
#define SCAN_SMEM (2 * S_TOK * 4)   // 128 KB

__global__ void __launch_bounds__(256) scan_loss_kernel(float* loss_out)
{
    extern __shared__ int sidx[];
    int* s1 = sidx;
    int* s2 = sidx + S_TOK;

    {
        const int4* p1 = (const int4*)g_idx1;
        const int4* p2 = (const int4*)g_idx2;
        int4* q1 = (int4*)s1;
        int4* q2 = (int4*)s2;
        #pragma unroll
        for (int i = 0; i < S_TOK / 4 / 256; i++) {
            q1[threadIdx.x + i * 256] = p1[threadIdx.x + i * 256];
            q2[threadIdx.x + i * 256] = p2[threadIdx.x + i * 256];
        }
    }
    __syncthreads();

    int warp = threadIdx.x >> 5;
    int lane = threadIdx.x & 31;
    int e = warp;
    unsigned lmask = (1u << lane) - 1u;

    int cnt = 0;
    #pragma unroll 4
    for (int base = 0; base < S_TOK; base += 32) {
        int id = s1[base + lane];
        unsigned m = __ballot_sync(0xffffffffu, id == e);
        if (id == e)
            g_pos1[base + lane] = cnt + __popc(m & lmask);
        cnt += __popc(m);
    }
    if (lane == 0) g_cnt1[e] = cnt;
    int used1 = min(cnt, CAP);

    int cnt2 = 0;
    #pragma unroll 4
    for (int base = 0; base < S_TOK; base += 32) {
        int id = s2[base + lane];
        unsigned m = __ballot_sync(0xffffffffu, id == e);
        if (id == e)
            g_pos2[base + lane] = used1 + cnt2 + __popc(m & lmask);
        cnt2 += __popc(m);
    }

    float s = 0.f;
    #pragma unroll 4
    for (int b = lane; b < GATE_BLOCKS; b += 32)
        s += g_partial[b * NEXP + e];
    #pragma unroll
    for (int off = 16; off; off >>= 1)
        s += __shfl_xor_sync(0xffffffffu, s, off);

    __shared__ float sms[NEXP];
    if (lane == 0) sms[e] = s;
    __syncthreads();
    if (threadIdx.x == 0 && loss_out != nullptr) {
        const float invS = 1.0f / (float)S_TOK;
        float tot = 0.f;
        #pragma unroll
        for (int e2 = 0; e2 < NEXP; e2++)
            tot += (sms[e2] * invS) * ((float)g_cnt1[e2] * invS);
        *loss_out = 0.01f * (tot * 0.125f) * 64.0f;
    }
}

// ---------------- 3) zero dispatch buffers (fp16) ----------------
__global__ void zero_buf_kernel()
{
    size_t i = (size_t)blockIdx.x * blockDim.x + threadIdx.x;
    ((float4*)g_bufh)[i] = make_float4(0.f, 0.f, 0.f, 0.f);
}

// ---------------- 4) dispatch scatter (fp32 -> fp16 RN) ----------------
__global__ void __launch_bounds__(256) dispatch_kernel(const float* __restrict__ x)
{
    int tok = blockIdx.x;
    int i1 = g_idx1[tok], i2 = g_idx2[tok];
    int p1 = g_pos1[tok], p2 = g_pos2[tok];
    bool k1 = p1 < CAP, k2 = p2 < CAP;

    const float4* xr = (const float4*)(x + (size_t)tok * DMODEL);
    uint2* b1p = (uint2*)(g_bufh + ((size_t)i1 * CAP + p1) * DMODEL);
    uint2* b2p = (uint2*)(g_bufh + ((size_t)i2 * CAP + p2) * DMODEL);

    int j = threadIdx.x;
    float4 v = xr[j];
    __half2 h0 = __floats2half2_rn(v.x, v.y);
    __half2 h1 = __floats2half2_rn(v.z, v.w);
    uint2 pk = make_uint2(*(uint32_t*)&h0, *(uint32_t*)&h1);
    if (k1) b1p[j] = pk;
    if (k2) b2p[j] = pk;
}

// ---------------- 5) weight transpose fp32 -> fp16 ----------------
// in [E][R][C] fp32 -> out [E][C][R] fp16
__global__ void __launch_bounds__(256) transpose_h_kernel(
    const float* __restrict__ in, __half* __restrict__ out, int R, int C)
{
    __shared__ float tile[32][33];
    int e = blockIdx.z;
    const float* ine = in + (size_t)e * R * C;
    __half* oute = out + (size_t)e * R * C;
    int c0 = blockIdx.x * 32, r0 = blockIdx.y * 32;
    int tx = threadIdx.x, ty = threadIdx.y;
    #pragma unroll
    for (int i = 0; i < 32; i += 8)
        tile[ty + i][tx] = ine[(size_t)(r0 + ty + i) * C + c0 + tx];
    __syncthreads();
    #pragma unroll
    for (int i = 0; i < 32; i += 8)
        oute[(size_t)(c0 + ty + i) * R + r0 + tx] = __float2half_rn(tile[tx][ty + i]);
}

// ---------------- 6) fp16 mma.sync grouped GEMM ---------------------------
// 128x128 block, BK=64, 4 warps (64x64 warp tile), 128 thr, 2 CTA/SM.
// C[e][m][n] = sum_k A[e][m][k] * Bt[e][n][k]  (+bias, opt gelu)
#define BM 128
#define BN 128
#define BK 64
#define ROWP 72                      // 64 + 8 pad halfs; 144B stride, LDSM conflict-free
#define A_STG (BM * ROWP)            // 9216 halfs
#define B_STG (BN * ROWP)            // 9216 halfs
#define STG_H (A_STG + B_STG)        // 18432 halfs = 36864 B
#define NSTG 3
#define GEMM_SMEM (NSTG * STG_H * 2) // 110592 bytes -> 2 CTAs/SM
#define GT 128                       // GEMM threads per CTA

template<typename OutT, int DO_GELU>
__global__ void __launch_bounds__(GT, 2) moe_mma_gemm(
    const __half* __restrict__ A, const __half* __restrict__ Bt,
    const float* __restrict__ bias, OutT* __restrict__ C,
    int M, int N, int K)
{
    extern __shared__ __half smemh[];
    const uint32_t sb = smem_u32(smemh);

    const int tid = threadIdx.x;
    const int lane = tid & 31;
    const int wid = tid >> 5;        // 0..3
    const int wm = wid & 1;          // warp m half (64)
    const int wn = wid >> 1;         // warp n half (64)
    const int g = lane >> 2;
    const int t4 = lane & 3;

    const int e = blockIdx.z;
    const int mbase = blockIdx.x * BM;
    const int nbase = blockIdx.y * BN;
    const __half* Ae = A + (size_t)e * M * K;
    const __half* Be = Bt + (size_t)e * N * K;

    // cp.async mapping: 128 rows x 8 chunks (16B) per tile; 128 thr
    // lane-group of 8 covers one row's 128B contiguously.
    const int ar = tid >> 3;         // row base (0..15), +16 each pass
    const int ac = tid & 7;          // chunk
    const int KT = K / BK;

    // ldmatrix per-lane smem byte offsets (within a stage)
    const uint32_t a_off =
        (uint32_t)((wm * 64 + (lane & 7) + ((lane >> 3) & 1) * 8) * ROWP
                   + ((lane >> 4) & 1) * 8) * 2;
    const uint32_t b_off = (uint32_t)(A_STG
                   + (wn * 64 + (lane & 7) + ((lane >> 4) & 1) * 8) * ROWP
                   + ((lane >> 3) & 1) * 8) * 2;

    auto load_stage = [&](int s, int kt) {
        uint32_t abase = sb + (uint32_t)(s * STG_H) * 2;
        uint32_t bbase = abase + A_STG * 2;
        const __half* Asrc = Ae + (size_t)mbase * K + (size_t)kt * BK;
        const __half* Bsrc = Be + (size_t)nbase * K + (size_t)kt * BK;
        #pragma unroll
        for (int t = 0; t < 8; t++) {
            int r = ar + t * 16;
            cp_async16(abase + (uint32_t)(r * ROWP + ac * 8) * 2,
                       Asrc + (size_t)r * K + ac * 8);
            cp_async16(bbase + (uint32_t)(r * ROWP + ac * 8) * 2,
                       Bsrc + (size_t)r * K + ac * 8);
        }
    };

    float acc[4][8][4];
    #pragma unroll
    for (int i = 0; i < 4; i++)
        #pragma unroll
        for (int j = 0; j < 8; j++)
            #pragma unroll
            for (int r = 0; r < 4; r++) acc[i][j][r] = 0.f;

    load_stage(0, 0); cp_commit();
    load_stage(1, 1); cp_commit();

    for (int kt = 0; kt < KT; kt++) {
        cp_wait<1>();
        __syncthreads();   // single barrier/kt: data ready + stage-reuse ordering
        if (kt + 2 < KT) load_stage((kt + 2) % NSTG, kt + 2);
        cp_commit();

        uint32_t stg = sb + (uint32_t)((kt % NSTG) * STG_H) * 2;
        uint32_t a_base = stg + a_off;
        uint32_t b_base = stg + b_off;

        #pragma unroll
        for (int kc = 0; kc < 4; kc++) {
            uint32_t a[4][4], b[8][2];
            #pragma unroll
            for (int i = 0; i < 4; i++)
                ldsm_x4(a[i][0], a[i][1], a[i][2], a[i][3],
                        a_base + (uint32_t)(i * 16 * ROWP + kc * 16) * 2);
            #pragma unroll
            for (int jp = 0; jp < 4; jp++)
                ldsm_x4(b[2 * jp][0], b[2 * jp][1], b[2 * jp + 1][0], b[2 * jp + 1][1],
                        b_base + (uint32_t)(jp * 16 * ROWP + kc * 16) * 2);
            #pragma unroll
            for (int i = 0; i < 4; i++)
                #pragma unroll
                for (int j = 0; j < 8; j++)
                    mma_f16(acc[i][j][0], acc[i][j][1], acc[i][j][2], acc[i][j][3],
                            a[i][0], a[i][1], a[i][2], a[i][3],
                            b[j][0], b[j][1]);
        }
        // no trailing barrier: next iteration's post-wait barrier orders reuse
    }

    // ---- epilogue (registers only) ----
    const float* brow = bias + (size_t)e * N + nbase + wn * 64;
    OutT* Cr = C + ((size_t)e * M + mbase + wm * 64) * N + nbase + wn * 64;
    #pragma unroll
    for (int i = 0; i < 4; i++) {
        #pragma unroll
        for (int j = 0; j < 8; j++) {
            int col = j * 8 + 2 * t4;
            float b0 = brow[col], b1 = brow[col + 1];
            float v0 = acc[i][j][0] + b0;
            float v1 = acc[i][j][1] + b1;
            float v2 = acc[i][j][2] + b0;
            float v3 = acc[i][j][3] + b1;
            if (DO_GELU) {
                v0 = gelu_tanh(v0); v1 = gelu_tanh(v1);
                v2 = gelu_tanh(v2); v3 = gelu_tanh(v3);
            }
            OutT* p0 = Cr + (size_t)(i * 16 + g) * N + col;
            OutT* p1 = Cr + (size_t)(i * 16 + g + 8) * N + col;
            if (sizeof(OutT) == 2) {
                __half2 h0 = __floats2half2_rn(v0, v1);
                __half2 h1 = __floats2half2_rn(v2, v3);
                *(__half2*)p0 = h0;
                *(__half2*)p1 = h1;
            } else {
                *(float2*)p0 = make_float2(v0, v1);
                *(float2*)p1 = make_float2(v2, v3);
            }
        }
    }
}

// ---------------- 7) combine ----------------
__global__ void __launch_bounds__(256) combine_kernel(float* __restrict__ out)
{
    int tok = blockIdx.x;
    int i1 = g_idx1[tok], i2 = g_idx2[tok];
    int p1 = g_pos1[tok], p2 = g_pos2[tok];
    float ga = g_gate1[tok], gb = g_gate2[tok];
    bool k1 = p1 < CAP, k2 = p2 < CAP;
    float a1 = k1 ? ga : 0.f;
    float a2 = k2 ? gb : 0.f;
    float denom = a1 + a2 + 1e-9f;
    float w1 = a1 / denom, w2 = a2 / denom;
    int q1 = k1 ? p1 : 0, q2 = k2 ? p2 : 0;

    const float4* e1 = (const float4*)(g_eo + ((size_t)i1 * CAP + q1) * DMODEL);
    const float4* e2 = (const float4*)(g_eo + ((size_t)i2 * CAP + q2) * DMODEL);
    float4* o = (float4*)(out + (size_t)tok * DMODEL);

    int j = threadIdx.x;
    float4 v1 = e1[j], v2 = e2[j];
    float4 r;
    r.x = w1 * v1.x + w2 * v2.x;
    r.y = w1 * v1.y + w2 * v2.y;
    r.z = w1 * v1.z + w2 * v2.z;
    r.w = w1 * v1.w + w2 * v2.w;
    o[j] = r;
}

// ---------------- launch ----------------
extern "C" void kernel_launch(void* const* d_in, const int* in_sizes, int n_in,
                              void* d_out, int out_size)
{
    const float* x  = (const float*)d_in[0];
    const float* Wg = (const float*)d_in[1];
    const float* W1 = (const float*)d_in[2];
    const float* b1 = (const float*)d_in[3];
    const float* W2 = (const float*)d_in[4];
    const float* b2 = (const float*)d_in[5];
    float* out = (float*)d_out;

    void *pbuf, *ph, *peo, *pw1, *pw2;
    cudaGetSymbolAddress(&pbuf, g_bufh);
    cudaGetSymbolAddress(&ph,   g_hh);
    cudaGetSymbolAddress(&peo,  g_eo);
    cudaGetSymbolAddress(&pw1,  g_w1h);
    cudaGetSymbolAddress(&pw2,  g_w2h);

    cudaFuncSetAttribute((const void*)moe_mma_gemm<__half, 1>,
                         cudaFuncAttributeMaxDynamicSharedMemorySize, GEMM_SMEM);
    cudaFuncSetAttribute((const void*)moe_mma_gemm<float, 0>,
                         cudaFuncAttributeMaxDynamicSharedMemorySize, GEMM_SMEM);
    cudaFuncSetAttribute((const void*)scan_loss_kernel,
                         cudaFuncAttributeMaxDynamicSharedMemorySize, SCAN_SMEM);

    float* loss_ptr = (out_size > S_TOK * DMODEL) ? (out + (size_t)S_TOK * DMODEL)
                                                  : nullptr;

    // weight transposes fp32 -> fp16 (W^T layouts for row.col mma)
    transpose_h_kernel<<<dim3(HFFN / 32, DMODEL / 32, NEXP), dim3(32, 8)>>>(
        W1, (__half*)pw1, DMODEL, HFFN);
    transpose_h_kernel<<<dim3(DMODEL / 32, HFFN / 32, NEXP), dim3(32, 8)>>>(
        W2, (__half*)pw2, HFFN, DMODEL);

    gating_kernel<<<GATE_BLOCKS, 256>>>(x, Wg);
    scan_loss_kernel<<<1, 256, SCAN_SMEM>>>(loss_ptr);

    zero_buf_kernel<<<(int)(((size_t)NEXP * CAP * DMODEL * 2 / 16) / 256), 256>>>();
    dispatch_kernel<<<S_TOK, 256>>>(x);

    // GEMM1: h = gelu(buf @ W1 + b1) -> fp16
    moe_mma_gemm<__half, 1><<<dim3(CAP / BM, HFFN / BN, NEXP), GT, GEMM_SMEM>>>(
        (const __half*)pbuf, (const __half*)pw1, b1, (__half*)ph,
        CAP, HFFN, DMODEL);
    // GEMM2: eo = h @ W2 + b2 -> fp32
    moe_mma_gemm<float, 0><<<dim3(CAP / BM, DMODEL / BN, NEXP), GT, GEMM_SMEM>>>(
        (const __half*)ph, (const __half*)pw2, b2, (float*)peo,
        CAP, DMODEL, HFFN);

    combine_kernel<<<S_TOK, 256>>>(out);
}

// round 10
// speedup vs baseline: 6.6197x; 1.0074x over previous
#include <cuda_runtime.h>
#include <cuda_fp16.h>
#include <math.h>
#include <stdint.h>

// ---------------- problem constants ----------------
#define S_TOK   16384          // B*N
#define DMODEL  1024
#define NEXP    8
#define HFFN    4096
#define CAP     2560           // int(S*1.25/E)
#define GATE_BLOCKS (S_TOK/8)

// ---------------- device scratch (allocation-free rule) ----------------
__device__ __half g_bufh[NEXP * CAP * DMODEL];            // 42 MB  dispatch fp16
__device__ __half g_hh  [(size_t)NEXP * CAP * HFFN];      // 168 MB hidden fp16
__device__ __half g_w1h [(size_t)NEXP * HFFN * DMODEL];   // 67 MB  W1^T [E][H][D]
__device__ __half g_w2h [(size_t)NEXP * DMODEL * HFFN];   // 67 MB  W2^T [E][D][H]
__device__ float g_gate1[S_TOK];
__device__ float g_gate2[S_TOK];
__device__ int   g_idx1[S_TOK];
__device__ int   g_idx2[S_TOK];
__device__ int   g_pos1[S_TOK];
__device__ int   g_pos2[S_TOK];
__device__ float g_partial[GATE_BLOCKS * NEXP];
__device__ int   g_cnt1[NEXP];
__device__ int   g_slot_tok[NEXP * CAP];                  // token id or -1
__device__ float g_slot_w  [NEXP * CAP];                  // renormalized gate

// ---------------- helpers ----------------
__device__ __forceinline__ float gelu_tanh(float x) {
    float x3 = x * x * x;
    return 0.5f * x * (1.0f + tanhf(0.7978845608028654f * (x + 0.044715f * x3)));
}
__device__ __forceinline__ uint32_t smem_u32(const void* p) {
    uint32_t a;
    asm("{ .reg .u64 t; cvta.to.shared.u64 t, %1; cvt.u32.u64 %0, t; }" : "=r"(a) : "l"(p));
    return a;
}
__device__ __forceinline__ void cp_async16(uint32_t dst, const void* src) {
    asm volatile("cp.async.cg.shared.global [%0], [%1], 16;" :: "r"(dst), "l"(src));
}
__device__ __forceinline__ void cp_commit() {
    asm volatile("cp.async.commit_group;");
}
template<int N>
__device__ __forceinline__ void cp_wait() {
    asm volatile("cp.async.wait_group %0;" :: "n"(N));
}
__device__ __forceinline__ void mma_f16(float& c0, float& c1, float& c2, float& c3,
                                        uint32_t a0, uint32_t a1, uint32_t a2, uint32_t a3,
                                        uint32_t b0, uint32_t b1) {
    asm volatile(
        "mma.sync.aligned.m16n8k16.row.col.f32.f16.f16.f32 "
        "{%0,%1,%2,%3}, {%4,%5,%6,%7}, {%8,%9}, {%0,%1,%2,%3};"
        : "+f"(c0), "+f"(c1), "+f"(c2), "+f"(c3)
        : "r"(a0), "r"(a1), "r"(a2), "r"(a3), "r"(b0), "r"(b1));
}
__device__ __forceinline__ void ldsm_x4(uint32_t& r0, uint32_t& r1,
                                        uint32_t& r2, uint32_t& r3, uint32_t addr) {
    asm volatile("ldmatrix.sync.aligned.m8n8.x4.shared.b16 {%0,%1,%2,%3}, [%4];"
                 : "=r"(r0), "=r"(r1), "=r"(r2), "=r"(r3) : "r"(addr));
}

// ---------------- 1) gating ----------------
__global__ void __launch_bounds__(256) gating_kernel(
    const float* __restrict__ x, const float* __restrict__ Wg)
{
    __shared__ float sWgT[NEXP * DMODEL];
    __shared__ float sP[8][NEXP];
    for (int i = threadIdx.x; i < NEXP * DMODEL; i += blockDim.x) {
        int d = i & (DMODEL - 1);
        int e = i >> 10;
        sWgT[i] = Wg[d * NEXP + e];
    }
    __syncthreads();

    int warp = threadIdx.x >> 5;
    int lane = threadIdx.x & 31;
    int tok  = blockIdx.x * 8 + warp;

    const float* xr = x + (size_t)tok * DMODEL;
    float acc[NEXP];
    #pragma unroll
    for (int e = 0; e < NEXP; e++) acc[e] = 0.f;

    #pragma unroll 4
    for (int t = 0; t < 32; t++) {
        int d = t * 32 + lane;
        float xv = xr[d];
        #pragma unroll
        for (int e = 0; e < NEXP; e++)
            acc[e] += xv * sWgT[e * DMODEL + d];
    }
    #pragma unroll
    for (int e = 0; e < NEXP; e++) {
        #pragma unroll
        for (int off = 16; off; off >>= 1)
            acc[e] += __shfl_xor_sync(0xffffffffu, acc[e], off);
    }

    if (lane == 0) {
        float mx = acc[0];
        #pragma unroll
        for (int e = 1; e < NEXP; e++) mx = fmaxf(mx, acc[e]);
        float p[NEXP], sum = 0.f;
        #pragma unroll
        for (int e = 0; e < NEXP; e++) { p[e] = expf(acc[e] - mx); sum += p[e]; }
        float inv = 1.0f / sum;
        #pragma unroll
        for (int e = 0; e < NEXP; e++) p[e] *= inv;

        int i1 = 0; float v1 = p[0];
        #pragma unroll
        for (int e = 1; e < NEXP; e++) if (p[e] > v1) { v1 = p[e]; i1 = e; }
        int i2 = (i1 == 0) ? 1 : 0; float v2 = p[i2];
        #pragma unroll
        for (int e = 0; e < NEXP; e++)
            if (e != i1 && p[e] > v2) { v2 = p[e]; i2 = e; }

        g_idx1[tok] = i1;  g_idx2[tok] = i2;
        g_gate1[tok] = v1; g_gate2[tok] = v2;
        #pragma unroll
        for (int e = 0; e < NEXP; e++) sP[warp][e] = p[e];
    }
    __syncthreads();
    if (threadIdx.x < NEXP) {
        float s = 0.f;
        #pragma unroll
        for (int w = 0; w < 8; w++) s += sP[w][threadIdx.x];
        g_partial[blockIdx.x * NEXP + threadIdx.x] = s;
    }
}

// ---------------- 2) capacity scan + loss (smem-staged, warp-parallel) ----
#define SCAN_SMEM (2 * S_TOK * 4)   // 128 KB

__global__ void __launch_bounds__(256) scan_loss_kernel(float* loss_out)
{
    extern __shared__ int sidx[];
    int* s1 = sidx;
    int* s2 = sidx + S_TOK;

    {
        const int4* p1 = (const int4*)g_idx1;
        const int4* p2 = (const int4*)g_idx2;
        int4* q1 = (int4*)s1;
        int4* q2 = (int4*)s2;
        #pragma unroll
        for (int i = 0; i < S_TOK / 4 / 256; i++) {
            q1[threadIdx.x + i * 256] = p1[threadIdx.x + i * 256];
            q2[threadIdx.x + i * 256] = p2[threadIdx.x + i * 256];
        }
    }
    __syncthreads();

    int warp = threadIdx.x >> 5;
    int lane = threadIdx.x & 31;
    int e = warp;
    unsigned lmask = (1u << lane) - 1u;

    int cnt = 0;
    #pragma unroll 4
    for (int base = 0; base < S_TOK; base += 32) {
        int id = s1[base + lane];
        unsigned m = __ballot_sync(0xffffffffu, id == e);
        if (id == e)
            g_pos1[base + lane] = cnt + __popc(m & lmask);
        cnt += __popc(m);
    }
    if (lane == 0) g_cnt1[e] = cnt;
    int used1 = min(cnt, CAP);

    int cnt2 = 0;
    #pragma unroll 4
    for (int base = 0; base < S_TOK; base += 32) {
        int id = s2[base + lane];
        unsigned m = __ballot_sync(0xffffffffu, id == e);
        if (id == e)
            g_pos2[base + lane] = used1 + cnt2 + __popc(m & lmask);
        cnt2 += __popc(m);
    }

    float s = 0.f;
    #pragma unroll 4
    for (int b = lane; b < GATE_BLOCKS; b += 32)
        s += g_partial[b * NEXP + e];
    #pragma unroll
    for (int off = 16; off; off >>= 1)
        s += __shfl_xor_sync(0xffffffffu, s, off);

    __shared__ float sms[NEXP];
    if (lane == 0) sms[e] = s;
    __syncthreads();
    if (threadIdx.x == 0 && loss_out != nullptr) {
        const float invS = 1.0f / (float)S_TOK;
        float tot = 0.f;
        #pragma unroll
        for (int e2 = 0; e2 < NEXP; e2++)
            tot += (sms[e2] * invS) * ((float)g_cnt1[e2] * invS);
        *loss_out = 0.01f * (tot * 0.125f) * 64.0f;
    }
}

// ---------------- 3a) slot map init (-1) ----------------
__global__ void slot_init_kernel()
{
    int i = blockIdx.x * blockDim.x + threadIdx.x;
    g_slot_tok[i] = -1;
}

// ---------------- 3b) zero output (atomic accumulate target) ----------------
__global__ void zero_out_kernel(float4* __restrict__ out)
{
    size_t i = (size_t)blockIdx.x * blockDim.x + threadIdx.x;
    out[i] = make_float4(0.f, 0.f, 0.f, 0.f);
}

// ---------------- 4) dispatch scatter + slot map (fp32 -> fp16 RN) --------
__global__ void __launch_bounds__(256) dispatch_kernel(const float* __restrict__ x)
{
    int tok = blockIdx.x;
    int i1 = g_idx1[tok], i2 = g_idx2[tok];
    int p1 = g_pos1[tok], p2 = g_pos2[tok];
    float ga = g_gate1[tok], gb = g_gate2[tok];
    bool k1 = p1 < CAP, k2 = p2 < CAP;

    if (threadIdx.x == 0) {
        float a1 = k1 ? ga : 0.f;
        float a2 = k2 ? gb : 0.f;
        float denom = a1 + a2 + 1e-9f;
        if (k1) {
            g_slot_tok[i1 * CAP + p1] = tok;
            g_slot_w[i1 * CAP + p1] = a1 / denom;
        }
        if (k2) {
            g_slot_tok[i2 * CAP + p2] = tok;
            g_slot_w[i2 * CAP + p2] = a2 / denom;
        }
    }

    const float4* xr = (const float4*)(x + (size_t)tok * DMODEL);
    uint2* b1p = (uint2*)(g_bufh + ((size_t)i1 * CAP + p1) * DMODEL);
    uint2* b2p = (uint2*)(g_bufh + ((size_t)i2 * CAP + p2) * DMODEL);

    int j = threadIdx.x;
    float4 v = xr[j];
    __half2 h0 = __floats2half2_rn(v.x, v.y);
    __half2 h1 = __floats2half2_rn(v.z, v.w);
    uint2 pk = make_uint2(*(uint32_t*)&h0, *(uint32_t*)&h1);
    if (k1) b1p[j] = pk;
    if (k2) b2p[j] = pk;
}

// ---------------- 5) weight transpose fp32 -> fp16 ----------------
// in [E][R][C] fp32 -> out [E][C][R] fp16
__global__ void __launch_bounds__(256) transpose_h_kernel(
    const float* __restrict__ in, __half* __restrict__ out, int R, int C)
{
    __shared__ float tile[32][33];
    int e = blockIdx.z;
    const float* ine = in + (size_t)e * R * C;
    __half* oute = out + (size_t)e * R * C;
    int c0 = blockIdx.x * 32, r0 = blockIdx.y * 32;
    int tx = threadIdx.x, ty = threadIdx.y;
    #pragma unroll
    for (int i = 0; i < 32; i += 8)
        tile[ty + i][tx] = ine[(size_t)(r0 + ty + i) * C + c0 + tx];
    __syncthreads();
    #pragma unroll
    for (int i = 0; i < 32; i += 8)
        oute[(size_t)(c0 + ty + i) * R + r0 + tx] = __float2half_rn(tile[tx][ty + i]);
}

// ---------------- 6) fp16 mma.sync grouped GEMM ---------------------------
// 128x128 block, BK=64, 4 warps (64x64 warp tile), 128 thr, 2 CTA/SM.
// SCATTER=0: C[e][m][n] = sum_k A.Bt (+bias, opt gelu), plain store
// SCATTER=1: per-row (tok,w) from slot map; atomicAdd w*(acc+bias) into out
#define BM 128
#define BN 128
#define BK 64
#define ROWP 72                      // 64 + 8 pad halfs; 144B stride, LDSM conflict-free
#define A_STG (BM * ROWP)            // 9216 halfs
#define B_STG (BN * ROWP)            // 9216 halfs
#define STG_H (A_STG + B_STG)        // 18432 halfs = 36864 B
#define NSTG 3
#define GEMM_SMEM (NSTG * STG_H * 2) // 110592 bytes -> 2 CTAs/SM
#define GT 128                       // GEMM threads per CTA

template<typename OutT, int DO_GELU, int SCATTER>
__global__ void __launch_bounds__(GT, 2) moe_mma_gemm(
    const __half* __restrict__ A, const __half* __restrict__ Bt,
    const float* __restrict__ bias, OutT* __restrict__ C,
    int M, int N, int K)
{
    extern __shared__ __half smemh[];
    const uint32_t sb = smem_u32(smemh);

    const int tid = threadIdx.x;
    const int lane = tid & 31;
    const int wid = tid >> 5;        // 0..3
    const int wm = wid & 1;          // warp m half (64)
    const int wn = wid >> 1;         // warp n half (64)
    const int g = lane >> 2;
    const int t4 = lane & 3;

    const int e = blockIdx.z;
    const int mbase = blockIdx.x * BM;
    const int nbase = blockIdx.y * BN;
    const __half* Ae = A + (size_t)e * M * K;
    const __half* Be = Bt + (size_t)e * N * K;

    const int ar = tid >> 3;         // row base (0..15), +16 each pass
    const int ac = tid & 7;          // chunk
    const int KT = K / BK;

    const uint32_t a_off =
        (uint32_t)((wm * 64 + (lane & 7) + ((lane >> 3) & 1) * 8) * ROWP
                   + ((lane >> 4) & 1) * 8) * 2;
    const uint32_t b_off = (uint32_t)(A_STG
                   + (wn * 64 + (lane & 7) + ((lane >> 4) & 1) * 8) * ROWP
                   + ((lane >> 3) & 1) * 8) * 2;

    auto load_stage = [&](int s, int kt) {
        uint32_t abase = sb + (uint32_t)(s * STG_H) * 2;
        uint32_t bbase = abase + A_STG * 2;
        const __half* Asrc = Ae + (size_t)mbase * K + (size_t)kt * BK;
        const __half* Bsrc = Be + (size_t)nbase * K + (size_t)kt * BK;
        #pragma unroll
        for (int t = 0; t < 8; t++) {
            int r = ar + t * 16;
            cp_async16(abase + (uint32_t)(r * ROWP + ac * 8) * 2,
                       Asrc + (size_t)r * K + ac * 8);
            cp_async16(bbase + (uint32_t)(r * ROWP + ac * 8) * 2,
                       Bsrc + (size_t)r * K + ac * 8);
        }
    };

    float acc[4][8][4];
    #pragma unroll
    for (int i = 0; i < 4; i++)
        #pragma unroll
        for (int j = 0; j < 8; j++)
            #pragma unroll
            for (int r = 0; r < 4; r++) acc[i][j][r] = 0.f;

    load_stage(0, 0); cp_commit();
    load_stage(1, 1); cp_commit();

    for (int kt = 0; kt < KT; kt++) {
        cp_wait<1>();
        __syncthreads();
        if (kt + 2 < KT) load_stage((kt + 2) % NSTG, kt + 2);
        cp_commit();

        uint32_t stg = sb + (uint32_t)((kt % NSTG) * STG_H) * 2;
        uint32_t a_base = stg + a_off;
        uint32_t b_base = stg + b_off;

        #pragma unroll
        for (int kc = 0; kc < 4; kc++) {
            uint32_t a[4][4], b[8][2];
            #pragma unroll
            for (int i = 0; i < 4; i++)
                ldsm_x4(a[i][0], a[i][1], a[i][2], a[i][3],
                        a_base + (uint32_t)(i * 16 * ROWP + kc * 16) * 2);
            #pragma unroll
            for (int jp = 0; jp < 4; jp++)
                ldsm_x4(b[2 * jp][0], b[2 * jp][1], b[2 * jp + 1][0], b[2 * jp + 1][1],
                        b_base + (uint32_t)(jp * 16 * ROWP + kc * 16) * 2);
            #pragma unroll
            for (int i = 0; i < 4; i++)
                #pragma unroll
                for (int j = 0; j < 8; j++)
                    mma_f16(acc[i][j][0], acc[i][j][1], acc[i][j][2], acc[i][j][3],
                            a[i][0], a[i][1], a[i][2], a[i][3],
                            b[j][0], b[j][1]);
        }
    }

    // ---- epilogue ----
    const float* brow = bias + (size_t)e * N + nbase + wn * 64;
    if (SCATTER) {
        // per-row token scatter-add (deterministic: <=2 commutative adds/elem)
        #pragma unroll
        for (int i = 0; i < 4; i++) {
            int slot0 = e * CAP + mbase + wm * 64 + i * 16 + g;
            int tk0 = g_slot_tok[slot0];
            int tk1 = g_slot_tok[slot0 + 8];
            float w0 = g_slot_w[slot0];
            float w1 = g_slot_w[slot0 + 8];
            float* o0 = (float*)C + (size_t)tk0 * DMODEL + nbase + wn * 64;
            float* o1 = (float*)C + (size_t)tk1 * DMODEL + nbase + wn * 64;
            #pragma unroll
            for (int j = 0; j < 8; j++) {
                int col = j * 8 + 2 * t4;
                float b0 = brow[col], b1 = brow[col + 1];
                if (tk0 >= 0) {
                    atomicAdd(o0 + col,     w0 * (acc[i][j][0] + b0));
                    atomicAdd(o0 + col + 1, w0 * (acc[i][j][1] + b1));
                }
                if (tk1 >= 0) {
                    atomicAdd(o1 + col,     w1 * (acc[i][j][2] + b0));
                    atomicAdd(o1 + col + 1, w1 * (acc[i][j][3] + b1));
                }
            }
        }
    } else {
        OutT* Cr = C + ((size_t)e * M + mbase + wm * 64) * N + nbase + wn * 64;
        #pragma unroll
        for (int i = 0; i < 4; i++) {
            #pragma unroll
            for (int j = 0; j < 8; j++) {
                int col = j * 8 + 2 * t4;
                float b0 = brow[col], b1 = brow[col + 1];
                float v0 = acc[i][j][0] + b0;
                float v1 = acc[i][j][1] + b1;
                float v2 = acc[i][j][2] + b0;
                float v3 = acc[i][j][3] + b1;
                if (DO_GELU) {
                    v0 = gelu_tanh(v0); v1 = gelu_tanh(v1);
                    v2 = gelu_tanh(v2); v3 = gelu_tanh(v3);
                }
                OutT* p0 = Cr + (size_t)(i * 16 + g) * N + col;
                OutT* p1 = Cr + (size_t)(i * 16 + g + 8) * N + col;
                if (sizeof(OutT) == 2) {
                    __half2 h0 = __floats2half2_rn(v0, v1);
                    __half2 h1 = __floats2half2_rn(v2, v3);
                    *(__half2*)p0 = h0;
                    *(__half2*)p1 = h1;
                } else {
                    *(float2*)p0 = make_float2(v0, v1);
                    *(float2*)p1 = make_float2(v2, v3);
                }
            }
        }
    }
}

// ---------------- launch ----------------
extern "C" void kernel_launch(void* const* d_in, const int* in_sizes, int n_in,
                              void* d_out, int out_size)
{
    const float* x  = (const float*)d_in[0];
    const float* Wg = (const float*)d_in[1];
    const float* W1 = (const float*)d_in[2];
    const float* b1 = (const float*)d_in[3];
    const float* W2 = (const float*)d_in[4];
    const float* b2 = (const float*)d_in[5];
    float* out = (float*)d_out;

    void *pbuf, *ph, *pw1, *pw2;
    cudaGetSymbolAddress(&pbuf, g_bufh);
    cudaGetSymbolAddress(&ph,   g_hh);
    cudaGetSymbolAddress(&pw1,  g_w1h);
    cudaGetSymbolAddress(&pw2,  g_w2h);

    cudaFuncSetAttribute((const void*)moe_mma_gemm<__half, 1, 0>,
                         cudaFuncAttributeMaxDynamicSharedMemorySize, GEMM_SMEM);
    cudaFuncSetAttribute((const void*)moe_mma_gemm<float, 0, 1>,
                         cudaFuncAttributeMaxDynamicSharedMemorySize, GEMM_SMEM);
    cudaFuncSetAttribute((const void*)scan_loss_kernel,
                         cudaFuncAttributeMaxDynamicSharedMemorySize, SCAN_SMEM);

    float* loss_ptr = (out_size > S_TOK * DMODEL) ? (out + (size_t)S_TOK * DMODEL)
                                                  : nullptr;

    // weight transposes fp32 -> fp16 (W^T layouts for row.col mma)
    transpose_h_kernel<<<dim3(HFFN / 32, DMODEL / 32, NEXP), dim3(32, 8)>>>(
        W1, (__half*)pw1, DMODEL, HFFN);
    transpose_h_kernel<<<dim3(DMODEL / 32, HFFN / 32, NEXP), dim3(32, 8)>>>(
        W2, (__half*)pw2, HFFN, DMODEL);

    gating_kernel<<<GATE_BLOCKS, 256>>>(x, Wg);
    scan_loss_kernel<<<1, 256, SCAN_SMEM>>>(loss_ptr);

    slot_init_kernel<<<(NEXP * CAP) / 256, 256>>>();
    zero_out_kernel<<<(S_TOK * DMODEL / 4) / 256, 256>>>((float4*)out);
    dispatch_kernel<<<S_TOK, 256>>>(x);

    // GEMM1: h = gelu(buf @ W1 + b1) -> fp16
    moe_mma_gemm<__half, 1, 0><<<dim3(CAP / BM, HFFN / BN, NEXP), GT, GEMM_SMEM>>>(
        (const __half*)pbuf, (const __half*)pw1, b1, (__half*)ph,
        CAP, HFFN, DMODEL);
    // GEMM2 fused combine: atomic scatter-add w*(h @ W2 + b2) into out
    moe_mma_gemm<float, 0, 1><<<dim3(CAP / BM, DMODEL / BN, NEXP), GT, GEMM_SMEM>>>(
        (const __half*)ph, (const __half*)pw2, b2, out,
        CAP, DMODEL, HFFN);
}

// round 11
// speedup vs baseline: 6.6386x; 1.0029x over previous
#include <cuda_runtime.h>
#include <cuda_fp16.h>
#include <math.h>
#include <stdint.h>

// ---------------- problem constants ----------------
#define S_TOK   16384          // B*N
#define DMODEL  1024
#define NEXP    8
#define HFFN    4096
#define CAP     2560           // int(S*1.25/E)
#define GATE_BLOCKS (S_TOK/8)

// ---------------- device scratch (allocation-free rule) ----------------
__device__ __half g_bufh[NEXP * CAP * DMODEL];            // 42 MB  dispatch fp16
__device__ __half g_hh  [(size_t)NEXP * CAP * HFFN];      // 168 MB hidden fp16
__device__ __half g_w1h [(size_t)NEXP * HFFN * DMODEL];   // 67 MB  W1^T [E][H][D]
__device__ __half g_w2h [(size_t)NEXP * DMODEL * HFFN];   // 67 MB  W2^T [E][D][H]
__device__ float g_gate1[S_TOK];
__device__ float g_gate2[S_TOK];
__device__ int   g_idx1[S_TOK];
__device__ int   g_idx2[S_TOK];
__device__ int   g_pos1[S_TOK];
__device__ int   g_pos2[S_TOK];
__device__ float g_partial[GATE_BLOCKS * NEXP];
__device__ int   g_cnt1[NEXP];
__device__ int   g_slot_tok[NEXP * CAP];                  // token id or -1
__device__ float g_slot_w  [NEXP * CAP];                  // renormalized gate

// ---------------- helpers ----------------
__device__ __forceinline__ float gelu_tanh(float x) {
    float x3 = x * x * x;
    return 0.5f * x * (1.0f + tanhf(0.7978845608028654f * (x + 0.044715f * x3)));
}
__device__ __forceinline__ uint32_t smem_u32(const void* p) {
    uint32_t a;
    asm("{ .reg .u64 t; cvta.to.shared.u64 t, %1; cvt.u32.u64 %0, t; }" : "=r"(a) : "l"(p));
    return a;
}
__device__ __forceinline__ void cp_async16(uint32_t dst, const void* src) {
    asm volatile("cp.async.cg.shared.global [%0], [%1], 16;" :: "r"(dst), "l"(src));
}
__device__ __forceinline__ void cp_commit() {
    asm volatile("cp.async.commit_group;");
}
template<int N>
__device__ __forceinline__ void cp_wait() {
    asm volatile("cp.async.wait_group %0;" :: "n"(N));
}
__device__ __forceinline__ void mma_f16(float& c0, float& c1, float& c2, float& c3,
                                        uint32_t a0, uint32_t a1, uint32_t a2, uint32_t a3,
                                        uint32_t b0, uint32_t b1) {
    asm volatile(
        "mma.sync.aligned.m16n8k16.row.col.f32.f16.f16.f32 "
        "{%0,%1,%2,%3}, {%4,%5,%6,%7}, {%8,%9}, {%0,%1,%2,%3};"
        : "+f"(c0), "+f"(c1), "+f"(c2), "+f"(c3)
        : "r"(a0), "r"(a1), "r"(a2), "r"(a3), "r"(b0), "r"(b1));
}
__device__ __forceinline__ void ldsm_x4(uint32_t& r0, uint32_t& r1,
                                        uint32_t& r2, uint32_t& r3, uint32_t addr) {
    asm volatile("ldmatrix.sync.aligned.m8n8.x4.shared.b16 {%0,%1,%2,%3}, [%4];"
                 : "=r"(r0), "=r"(r1), "=r"(r2), "=r"(r3) : "r"(addr));
}

// ---------------- 1) gating ----------------
__global__ void __launch_bounds__(256) gating_kernel(
    const float* __restrict__ x, const float* __restrict__ Wg)
{
    __shared__ float sWgT[NEXP * DMODEL];
    __shared__ float sP[8][NEXP];
    for (int i = threadIdx.x; i < NEXP * DMODEL; i += blockDim.x) {
        int d = i & (DMODEL - 1);
        int e = i >> 10;
        sWgT[i] = Wg[d * NEXP + e];
    }
    __syncthreads();

    int warp = threadIdx.x >> 5;
    int lane = threadIdx.x & 31;
    int tok  = blockIdx.x * 8 + warp;

    const float* xr = x + (size_t)tok * DMODEL;
    float acc[NEXP];
    #pragma unroll
    for (int e = 0; e < NEXP; e++) acc[e] = 0.f;

    #pragma unroll 4
    for (int t = 0; t < 32; t++) {
        int d = t * 32 + lane;
        float xv = xr[d];
        #pragma unroll
        for (int e = 0; e < NEXP; e++)
            acc[e] += xv * sWgT[e * DMODEL + d];
    }
    #pragma unroll
    for (int e = 0; e < NEXP; e++) {
        #pragma unroll
        for (int off = 16; off; off >>= 1)
            acc[e] += __shfl_xor_sync(0xffffffffu, acc[e], off);
    }

    if (lane == 0) {
        float mx = acc[0];
        #pragma unroll
        for (int e = 1; e < NEXP; e++) mx = fmaxf(mx, acc[e]);
        float p[NEXP], sum = 0.f;
        #pragma unroll
        for (int e = 0; e < NEXP; e++) { p[e] = expf(acc[e] - mx); sum += p[e]; }
        float inv = 1.0f / sum;
        #pragma unroll
        for (int e = 0; e < NEXP; e++) p[e] *= inv;

        int i1 = 0; float v1 = p[0];
        #pragma unroll
        for (int e = 1; e < NEXP; e++) if (p[e] > v1) { v1 = p[e]; i1 = e; }
        int i2 = (i1 == 0) ? 1 : 0; float v2 = p[i2];
        #pragma unroll
        for (int e = 0; e < NEXP; e++)
            if (e != i1 && p[e] > v2) { v2 = p[e]; i2 = e; }

        g_idx1[tok] = i1;  g_idx2[tok] = i2;
        g_gate1[tok] = v1; g_gate2[tok] = v2;
        #pragma unroll
        for (int e = 0; e < NEXP; e++) sP[warp][e] = p[e];
    }
    __syncthreads();
    if (threadIdx.x < NEXP) {
        float s = 0.f;
        #pragma unroll
        for (int w = 0; w < 8; w++) s += sP[w][threadIdx.x];
        g_partial[blockIdx.x * NEXP + threadIdx.x] = s;
    }
}

// ---------------- 2) capacity scan + loss (smem-staged, warp-parallel) ----
#define SCAN_SMEM (2 * S_TOK * 4)   // 128 KB

__global__ void __launch_bounds__(256) scan_loss_kernel(float* loss_out)
{
    extern __shared__ int sidx[];
    int* s1 = sidx;
    int* s2 = sidx + S_TOK;

    {
        const int4* p1 = (const int4*)g_idx1;
        const int4* p2 = (const int4*)g_idx2;
        int4* q1 = (int4*)s1;
        int4* q2 = (int4*)s2;
        #pragma unroll
        for (int i = 0; i < S_TOK / 4 / 256; i++) {
            q1[threadIdx.x + i * 256] = p1[threadIdx.x + i * 256];
            q2[threadIdx.x + i * 256] = p2[threadIdx.x + i * 256];
        }
    }
    __syncthreads();

    int warp = threadIdx.x >> 5;
    int lane = threadIdx.x & 31;
    int e = warp;
    unsigned lmask = (1u << lane) - 1u;

    int cnt = 0;
    #pragma unroll 4
    for (int base = 0; base < S_TOK; base += 32) {
        int id = s1[base + lane];
        unsigned m = __ballot_sync(0xffffffffu, id == e);
        if (id == e)
            g_pos1[base + lane] = cnt + __popc(m & lmask);
        cnt += __popc(m);
    }
    if (lane == 0) g_cnt1[e] = cnt;
    int used1 = min(cnt, CAP);

    int cnt2 = 0;
    #pragma unroll 4
    for (int base = 0; base < S_TOK; base += 32) {
        int id = s2[base + lane];
        unsigned m = __ballot_sync(0xffffffffu, id == e);
        if (id == e)
            g_pos2[base + lane] = used1 + cnt2 + __popc(m & lmask);
        cnt2 += __popc(m);
    }

    float s = 0.f;
    #pragma unroll 4
    for (int b = lane; b < GATE_BLOCKS; b += 32)
        s += g_partial[b * NEXP + e];
    #pragma unroll
    for (int off = 16; off; off >>= 1)
        s += __shfl_xor_sync(0xffffffffu, s, off);

    __shared__ float sms[NEXP];
    if (lane == 0) sms[e] = s;
    __syncthreads();
    if (threadIdx.x == 0 && loss_out != nullptr) {
        const float invS = 1.0f / (float)S_TOK;
        float tot = 0.f;
        #pragma unroll
        for (int e2 = 0; e2 < NEXP; e2++)
            tot += (sms[e2] * invS) * ((float)g_cnt1[e2] * invS);
        *loss_out = 0.01f * (tot * 0.125f) * 64.0f;
    }
}

// ---------------- 3a) slot map init (-1) ----------------
__global__ void slot_init_kernel()
{
    int i = blockIdx.x * blockDim.x + threadIdx.x;
    g_slot_tok[i] = -1;
}

// ---------------- 3b) zero output (atomic accumulate target) ----------------
__global__ void zero_out_kernel(float4* __restrict__ out)
{
    size_t i = (size_t)blockIdx.x * blockDim.x + threadIdx.x;
    out[i] = make_float4(0.f, 0.f, 0.f, 0.f);
}

// ---------------- 4) dispatch scatter + slot map (fp32 -> fp16 RN) --------
__global__ void __launch_bounds__(256) dispatch_kernel(const float* __restrict__ x)
{
    int tok = blockIdx.x;
    int i1 = g_idx1[tok], i2 = g_idx2[tok];
    int p1 = g_pos1[tok], p2 = g_pos2[tok];
    float ga = g_gate1[tok], gb = g_gate2[tok];
    bool k1 = p1 < CAP, k2 = p2 < CAP;

    if (threadIdx.x == 0) {
        float a1 = k1 ? ga : 0.f;
        float a2 = k2 ? gb : 0.f;
        float denom = a1 + a2 + 1e-9f;
        if (k1) {
            g_slot_tok[i1 * CAP + p1] = tok;
            g_slot_w[i1 * CAP + p1] = a1 / denom;
        }
        if (k2) {
            g_slot_tok[i2 * CAP + p2] = tok;
            g_slot_w[i2 * CAP + p2] = a2 / denom;
        }
    }

    const float4* xr = (const float4*)(x + (size_t)tok * DMODEL);
    uint2* b1p = (uint2*)(g_bufh + ((size_t)i1 * CAP + p1) * DMODEL);
    uint2* b2p = (uint2*)(g_bufh + ((size_t)i2 * CAP + p2) * DMODEL);

    int j = threadIdx.x;
    float4 v = xr[j];
    __half2 h0 = __floats2half2_rn(v.x, v.y);
    __half2 h1 = __floats2half2_rn(v.z, v.w);
    uint2 pk = make_uint2(*(uint32_t*)&h0, *(uint32_t*)&h1);
    if (k1) b1p[j] = pk;
    if (k2) b2p[j] = pk;
}

// ---------------- 5) weight transpose fp32 -> fp16 ----------------
// in [E][R][C] fp32 -> out [E][C][R] fp16
__global__ void __launch_bounds__(256) transpose_h_kernel(
    const float* __restrict__ in, __half* __restrict__ out, int R, int C)
{
    __shared__ float tile[32][33];
    int e = blockIdx.z;
    const float* ine = in + (size_t)e * R * C;
    __half* oute = out + (size_t)e * R * C;
    int c0 = blockIdx.x * 32, r0 = blockIdx.y * 32;
    int tx = threadIdx.x, ty = threadIdx.y;
    #pragma unroll
    for (int i = 0; i < 32; i += 8)
        tile[ty + i][tx] = ine[(size_t)(r0 + ty + i) * C + c0 + tx];
    __syncthreads();
    #pragma unroll
    for (int i = 0; i < 32; i += 8)
        oute[(size_t)(c0 + ty + i) * R + r0 + tx] = __float2half_rn(tile[tx][ty + i]);
}

// ---------------- 6) fp16 mma.sync grouped GEMM ---------------------------
// 128x128 block, BK=64, 4 warps (64x64 warp tile), 128 thr, 2 CTA/SM.
// Fragment double-buffering across kc chunks (LDSM latency hidden under MMA).
// SCATTER=0: plain store (+bias, opt gelu); SCATTER=1: slot-map atomic scatter.
#define BM 128
#define BN 128
#define BK 64
#define ROWP 72                      // 64 + 8 pad halfs; 144B stride, LDSM conflict-free
#define A_STG (BM * ROWP)            // 9216 halfs
#define B_STG (BN * ROWP)            // 9216 halfs
#define STG_H (A_STG + B_STG)        // 18432 halfs = 36864 B
#define NSTG 3
#define GEMM_SMEM (NSTG * STG_H * 2) // 110592 bytes -> 2 CTAs/SM
#define GT 128                       // GEMM threads per CTA

template<typename OutT, int DO_GELU, int SCATTER>
__global__ void __launch_bounds__(GT, 2) moe_mma_gemm(
    const __half* __restrict__ A, const __half* __restrict__ Bt,
    const float* __restrict__ bias, OutT* __restrict__ C,
    int M, int N, int K)
{
    extern __shared__ __half smemh[];
    const uint32_t sb = smem_u32(smemh);

    const int tid = threadIdx.x;
    const int lane = tid & 31;
    const int wid = tid >> 5;        // 0..3
    const int wm = wid & 1;          // warp m half (64)
    const int wn = wid >> 1;         // warp n half (64)
    const int g = lane >> 2;
    const int t4 = lane & 3;

    const int e = blockIdx.z;
    const int mbase = blockIdx.x * BM;
    const int nbase = blockIdx.y * BN;
    const __half* Ae = A + (size_t)e * M * K;
    const __half* Be = Bt + (size_t)e * N * K;

    const int ar = tid >> 3;         // row base (0..15), +16 each pass
    const int ac = tid & 7;          // chunk
    const int KT = K / BK;

    const uint32_t a_off =
        (uint32_t)((wm * 64 + (lane & 7) + ((lane >> 3) & 1) * 8) * ROWP
                   + ((lane >> 4) & 1) * 8) * 2;
    const uint32_t b_off = (uint32_t)(A_STG
                   + (wn * 64 + (lane & 7) + ((lane >> 4) & 1) * 8) * ROWP
                   + ((lane >> 3) & 1) * 8) * 2;

    auto load_stage = [&](int s, int kt) {
        uint32_t abase = sb + (uint32_t)(s * STG_H) * 2;
        uint32_t bbase = abase + A_STG * 2;
        const __half* Asrc = Ae + (size_t)mbase * K + (size_t)kt * BK;
        const __half* Bsrc = Be + (size_t)nbase * K + (size_t)kt * BK;
        #pragma unroll
        for (int t = 0; t < 8; t++) {
            int r = ar + t * 16;
            cp_async16(abase + (uint32_t)(r * ROWP + ac * 8) * 2,
                       Asrc + (size_t)r * K + ac * 8);
            cp_async16(bbase + (uint32_t)(r * ROWP + ac * 8) * 2,
                       Bsrc + (size_t)r * K + ac * 8);
        }
    };

    float acc[4][8][4];
    #pragma unroll
    for (int i = 0; i < 4; i++)
        #pragma unroll
        for (int j = 0; j < 8; j++)
            #pragma unroll
            for (int r = 0; r < 4; r++) acc[i][j][r] = 0.f;

    // double-buffered fragments
    uint32_t afr[2][4][4], bfr[2][8][2];

    load_stage(0, 0); cp_commit();
    load_stage(1, 1); cp_commit();

    for (int kt = 0; kt < KT; kt++) {
        cp_wait<1>();
        __syncthreads();
        if (kt + 2 < KT) load_stage((kt + 2) % NSTG, kt + 2);
        cp_commit();

        uint32_t stg = sb + (uint32_t)((kt % NSTG) * STG_H) * 2;
        uint32_t a_base = stg + a_off;
        uint32_t b_base = stg + b_off;

        // prologue: fragments for kc=0
        #pragma unroll
        for (int i = 0; i < 4; i++)
            ldsm_x4(afr[0][i][0], afr[0][i][1], afr[0][i][2], afr[0][i][3],
                    a_base + (uint32_t)(i * 16 * ROWP) * 2);
        #pragma unroll
        for (int jp = 0; jp < 4; jp++)
            ldsm_x4(bfr[0][2 * jp][0], bfr[0][2 * jp][1],
                    bfr[0][2 * jp + 1][0], bfr[0][2 * jp + 1][1],
                    b_base + (uint32_t)(jp * 16 * ROWP) * 2);

        #pragma unroll
        for (int kc = 0; kc < 4; kc++) {
            int cur = kc & 1, nxt = cur ^ 1;
            if (kc < 3) {
                // prefetch kc+1 fragments ahead of this kc's MMAs
                #pragma unroll
                for (int i = 0; i < 4; i++)
                    ldsm_x4(afr[nxt][i][0], afr[nxt][i][1],
                            afr[nxt][i][2], afr[nxt][i][3],
                            a_base + (uint32_t)(i * 16 * ROWP + (kc + 1) * 16) * 2);
                #pragma unroll
                for (int jp = 0; jp < 4; jp++)
                    ldsm_x4(bfr[nxt][2 * jp][0], bfr[nxt][2 * jp][1],
                            bfr[nxt][2 * jp + 1][0], bfr[nxt][2 * jp + 1][1],
                            b_base + (uint32_t)(jp * 16 * ROWP + (kc + 1) * 16) * 2);
            }
            #pragma unroll
            for (int i = 0; i < 4; i++)
                #pragma unroll
                for (int j = 0; j < 8; j++)
                    mma_f16(acc[i][j][0], acc[i][j][1], acc[i][j][2], acc[i][j][3],
                            afr[cur][i][0], afr[cur][i][1],
                            afr[cur][i][2], afr[cur][i][3],
                            bfr[cur][j][0], bfr[cur][j][1]);
        }
    }

    // ---- epilogue ----
    const float* brow = bias + (size_t)e * N + nbase + wn * 64;
    if (SCATTER) {
        // per-row token scatter-add (deterministic: <=2 commutative adds/elem)
        #pragma unroll
        for (int i = 0; i < 4; i++) {
            int slot0 = e * CAP + mbase + wm * 64 + i * 16 + g;
            int tk0 = g_slot_tok[slot0];
            int tk1 = g_slot_tok[slot0 + 8];
            float w0 = g_slot_w[slot0];
            float w1 = g_slot_w[slot0 + 8];
            float* o0 = (float*)C + (size_t)tk0 * DMODEL + nbase + wn * 64;
            float* o1 = (float*)C + (size_t)tk1 * DMODEL + nbase + wn * 64;
            #pragma unroll
            for (int j = 0; j < 8; j++) {
                int col = j * 8 + 2 * t4;
                float b0 = brow[col], b1 = brow[col + 1];
                if (tk0 >= 0) {
                    atomicAdd(o0 + col,     w0 * (acc[i][j][0] + b0));
                    atomicAdd(o0 + col + 1, w0 * (acc[i][j][1] + b1));
                }
                if (tk1 >= 0) {
                    atomicAdd(o1 + col,     w1 * (acc[i][j][2] + b0));
                    atomicAdd(o1 + col + 1, w1 * (acc[i][j][3] + b1));
                }
            }
        }
    } else {
        OutT* Cr = C + ((size_t)e * M + mbase + wm * 64) * N + nbase + wn * 64;
        #pragma unroll
        for (int i = 0; i < 4; i++) {
            #pragma unroll
            for (int j = 0; j < 8; j++) {
                int col = j * 8 + 2 * t4;
                float b0 = brow[col], b1 = brow[col + 1];
                float v0 = acc[i][j][0] + b0;
                float v1 = acc[i][j][1] + b1;
                float v2 = acc[i][j][2] + b0;
                float v3 = acc[i][j][3] + b1;
                if (DO_GELU) {
                    v0 = gelu_tanh(v0); v1 = gelu_tanh(v1);
                    v2 = gelu_tanh(v2); v3 = gelu_tanh(v3);
                }
                OutT* p0 = Cr + (size_t)(i * 16 + g) * N + col;
                OutT* p1 = Cr + (size_t)(i * 16 + g + 8) * N + col;
                if (sizeof(OutT) == 2) {
                    __half2 h0 = __floats2half2_rn(v0, v1);
                    __half2 h1 = __floats2half2_rn(v2, v3);
                    *(__half2*)p0 = h0;
                    *(__half2*)p1 = h1;
                } else {
                    *(float2*)p0 = make_float2(v0, v1);
                    *(float2*)p1 = make_float2(v2, v3);
                }
            }
        }
    }
}

// ---------------- launch ----------------
extern "C" void kernel_launch(void* const* d_in, const int* in_sizes, int n_in,
                              void* d_out, int out_size)
{
    const float* x  = (const float*)d_in[0];
    const float* Wg = (const float*)d_in[1];
    const float* W1 = (const float*)d_in[2];
    const float* b1 = (const float*)d_in[3];
    const float* W2 = (const float*)d_in[4];
    const float* b2 = (const float*)d_in[5];
    float* out = (float*)d_out;

    void *pbuf, *ph, *pw1, *pw2;
    cudaGetSymbolAddress(&pbuf, g_bufh);
    cudaGetSymbolAddress(&ph,   g_hh);
    cudaGetSymbolAddress(&pw1,  g_w1h);
    cudaGetSymbolAddress(&pw2,  g_w2h);

    cudaFuncSetAttribute((const void*)moe_mma_gemm<__half, 1, 0>,
                         cudaFuncAttributeMaxDynamicSharedMemorySize, GEMM_SMEM);
    cudaFuncSetAttribute((const void*)moe_mma_gemm<float, 0, 1>,
                         cudaFuncAttributeMaxDynamicSharedMemorySize, GEMM_SMEM);
    cudaFuncSetAttribute((const void*)scan_loss_kernel,
                         cudaFuncAttributeMaxDynamicSharedMemorySize, SCAN_SMEM);

    float* loss_ptr = (out_size > S_TOK * DMODEL) ? (out + (size_t)S_TOK * DMODEL)
                                                  : nullptr;

    // weight transposes fp32 -> fp16 (W^T layouts for row.col mma)
    transpose_h_kernel<<<dim3(HFFN / 32, DMODEL / 32, NEXP), dim3(32, 8)>>>(
        W1, (__half*)pw1, DMODEL, HFFN);
    transpose_h_kernel<<<dim3(DMODEL / 32, HFFN / 32, NEXP), dim3(32, 8)>>>(
        W2, (__half*)pw2, HFFN, DMODEL);

    gating_kernel<<<GATE_BLOCKS, 256>>>(x, Wg);
    scan_loss_kernel<<<1, 256, SCAN_SMEM>>>(loss_ptr);

    slot_init_kernel<<<(NEXP * CAP) / 256, 256>>>();
    zero_out_kernel<<<(S_TOK * DMODEL / 4) / 256, 256>>>((float4*)out);
    dispatch_kernel<<<S_TOK, 256>>>(x);

    // GEMM1: h = gelu(buf @ W1 + b1) -> fp16
    moe_mma_gemm<__half, 1, 0><<<dim3(CAP / BM, HFFN / BN, NEXP), GT, GEMM_SMEM>>>(
        (const __half*)pbuf, (const __half*)pw1, b1, (__half*)ph,
        CAP, HFFN, DMODEL);
    // GEMM2 fused combine: atomic scatter-add w*(h @ W2 + b2) into out
    moe_mma_gemm<float, 0, 1><<<dim3(CAP / BM, DMODEL / BN, NEXP), GT, GEMM_SMEM>>>(
        (const __half*)ph, (const __half*)pw2, b2, out,
        CAP, DMODEL, HFFN);
}